// round 1
// baseline (speedup 1.0000x reference)
#include <cuda_runtime.h>

typedef unsigned long long u64;

// Problem constants
constexpr int B_ = 8;
constexpr int D_ = 128;
constexpr int S_ = 1024;
constexpr int C_ = 512;
constexpr int K_ = 16384;
constexpr float INV_TAU = 5.0f;

// Output layout (flattened concatenation, float32):
// output_g [B, 1+K], target_g [B], output_d [B, 1+K, S], target_d [B, S]
constexpr size_t OG = 0;
constexpr size_t TG = (size_t)B_ * (K_ + 1);              // 131080
constexpr size_t OD = TG + B_;                            // 131088
constexpr size_t TD = OD + (size_t)B_ * (K_ + 1) * S_;    // 134357008

// Scratch (device globals; no allocation allowed)
__device__ float g_fkn[B_ * C_ * S_];   // normalized feat_k
__device__ float g_dqn[B_ * D_ * S_];   // normalized d_q
__device__ float g_dkn[B_ * D_ * S_];   // normalized d_k
__device__ float g_dqg[B_ * D_ * S_];   // gathered d_qn at match indices
__device__ float g_gqn[B_ * D_];
__device__ float g_gkn[B_ * D_];
__device__ u64   g_best[B_ * S_];       // packed (ordered max value, ~idx)

// ---------- packed f32x2 helpers (Blackwell FFMA2) ----------
__device__ __forceinline__ u64 dup2(float x) {
    u64 r; asm("mov.b64 %0, {%1, %1};" : "=l"(r) : "f"(x)); return r;
}
__device__ __forceinline__ void unpack2(u64 v, float& lo, float& hi) {
    asm("mov.b64 {%0, %1}, %2;" : "=f"(lo), "=f"(hi) : "l"(v));
}
__device__ __forceinline__ void ffma2(u64& d, u64 a, u64 b) {
    asm("fma.rn.f32x2 %0, %1, %2, %0;" : "+l"(d) : "l"(a), "l"(b));
}

// order-preserving float->uint (monotonic), for packed atomicMax argmax
__device__ __forceinline__ unsigned ford(float f) {
    unsigned u = __float_as_uint(f);
    return (u & 0x80000000u) ? ~u : (u | 0x80000000u);
}

// ---------------------------------------------------------------------------
__global__ void zero_best_kernel() {
    int i = blockIdx.x * blockDim.x + threadIdx.x;
    if (i < B_ * S_) g_best[i] = 0ull;
}

// Normalize g_q / g_k rows (len 128). grid (2, B), block 128.
__global__ void norm_g_kernel(const float* __restrict__ gq,
                              const float* __restrict__ gk) {
    int b = blockIdx.y;
    const float* src = blockIdx.x ? gk : gq;
    float* dst = blockIdx.x ? g_gkn : g_gqn;
    int t = threadIdx.x;
    float v = src[b * D_ + t];
    __shared__ float sm[128];
    sm[t] = v * v;
    __syncthreads();
    for (int off = 64; off; off >>= 1) {
        if (t < off) sm[t] += sm[t + off];
        __syncthreads();
    }
    float sc = rsqrtf(fmaxf(sm[0], 1e-24f));
    dst[b * D_ + t] = v * sc;
}

// Normalize columns along C for [B, C, S] tensors. grid (S/256, B), block 256.
template <int C>
__device__ __forceinline__ void norm_cols_body(const float* __restrict__ src,
                                               float* __restrict__ dst) {
    int b = blockIdx.y;
    int s = blockIdx.x * blockDim.x + threadIdx.x;
    const float* p = src + (size_t)b * C * S_ + s;
    float ss = 0.0f;
#pragma unroll 8
    for (int c = 0; c < C; c++) {
        float v = p[(size_t)c * S_];
        ss += v * v;
    }
    float sc = rsqrtf(fmaxf(ss, 1e-24f));
    float* q = dst + (size_t)b * C * S_ + s;
#pragma unroll 8
    for (int c = 0; c < C; c++) q[(size_t)c * S_] = p[(size_t)c * S_] * sc;
}
__global__ void norm_dq_kernel(const float* __restrict__ src) { norm_cols_body<128>(src, g_dqn); }
__global__ void norm_dk_kernel(const float* __restrict__ src) { norm_cols_body<128>(src, g_dkn); }
__global__ void norm_fk_kernel(const float* __restrict__ src) { norm_cols_body<512>(src, g_fkn); }

// ---------------------------------------------------------------------------
// cosine[b,i,j] = sum_c fkn[b,c,i] * feat_q[b,c,j]; argmax over i per (b,j).
// feat_q left unnormalized: positive per-column scale doesn't change argmax.
// grid (S/128 i-tiles, S/128 j-tiles, B), block 256 (16x16), micro 8x8, fp32
// accumulation via packed fma.rn.f32x2 (pairs along i).
__global__ __launch_bounds__(256) void cos_argmax_kernel(const float* __restrict__ featq) {
    __shared__ float As[16][132];   // [c][i]
    __shared__ float Bs[16][132];   // [c][j]
    __shared__ u64 red[16][128];

    int b = blockIdx.z;
    int i0 = blockIdx.x * 128;
    int j0 = blockIdx.y * 128;
    int tid = threadIdx.x;
    int tx = tid & 15;
    int ty = tid >> 4;

    const float* fk = g_fkn + (size_t)b * C_ * S_;
    const float* fq = featq + (size_t)b * C_ * S_;

    u64 acc[4][8];
#pragma unroll
    for (int p = 0; p < 4; p++)
#pragma unroll
        for (int j = 0; j < 8; j++) acc[p][j] = 0ull;

    for (int c0 = 0; c0 < C_; c0 += 16) {
#pragma unroll
        for (int l = tid; l < 2048; l += 256) {
            int cc = l >> 7, col = l & 127;
            As[cc][col] = fk[(size_t)(c0 + cc) * S_ + i0 + col];
            Bs[cc][col] = fq[(size_t)(c0 + cc) * S_ + j0 + col];
        }
        __syncthreads();
#pragma unroll
        for (int cc = 0; cc < 16; cc++) {
            const u64* arow = reinterpret_cast<const u64*>(&As[cc][ty * 8]);
            u64 av[4] = {arow[0], arow[1], arow[2], arow[3]};
            const float4* brow = reinterpret_cast<const float4*>(&Bs[cc][tx * 8]);
            float4 b0 = brow[0], b1 = brow[1];
            u64 bb[8] = {dup2(b0.x), dup2(b0.y), dup2(b0.z), dup2(b0.w),
                         dup2(b1.x), dup2(b1.y), dup2(b1.z), dup2(b1.w)};
#pragma unroll
            for (int p = 0; p < 4; p++)
#pragma unroll
                for (int j = 0; j < 8; j++) ffma2(acc[p][j], av[p], bb[j]);
        }
        __syncthreads();
    }

    // per-thread argmax over its 8 i-rows (ascending i; strict > => lowest idx on tie)
    float bestv[8];
    unsigned besti[8];
#pragma unroll
    for (int j = 0; j < 8; j++) { bestv[j] = -2.0f; besti[j] = 0; }
#pragma unroll
    for (int p = 0; p < 4; p++) {
#pragma unroll
        for (int j = 0; j < 8; j++) {
            float lo, hi;
            unpack2(acc[p][j], lo, hi);
            unsigned ib = (unsigned)(i0 + ty * 8 + 2 * p);
            if (lo > bestv[j]) { bestv[j] = lo; besti[j] = ib; }
            if (hi > bestv[j]) { bestv[j] = hi; besti[j] = ib + 1; }
        }
    }
#pragma unroll
    for (int j = 0; j < 8; j++) {
        u64 key = ((u64)ford(bestv[j]) << 32) | (u64)(0xFFFFFFFFu - besti[j]);
        red[ty][tx * 8 + j] = key;
    }
    __syncthreads();
    if (tid < 128) {
        u64 m = red[0][tid];
#pragma unroll
        for (int t = 1; t < 16; t++) m = max(m, red[t][tid]);
        atomicMax(&g_best[b * S_ + j0 + tid], m);
    }
}

// ---------------------------------------------------------------------------
// Decode match idx, gather d_qg, compute pos_d, write output_d row 0 + target_d.
__global__ void gather_kernel(float* __restrict__ out) {
    int b = blockIdx.y;
    int z = blockIdx.x * blockDim.x + threadIdx.x;
    u64 key = g_best[b * S_ + z];
    int m = (int)(0xFFFFFFFFu - (unsigned)(key & 0xFFFFFFFFull));
    float pos = 0.0f;
#pragma unroll 4
    for (int d = 0; d < D_; d++) {
        float v = g_dqn[((size_t)b * D_ + d) * S_ + m];
        g_dqg[((size_t)b * D_ + d) * S_ + z] = v;
        pos += g_dkn[((size_t)b * D_ + d) * S_ + z] * v;
    }
    out[OD + (size_t)b * (K_ + 1) * S_ + z] = pos * INV_TAU;
    out[TD + (size_t)b * S_ + z] = 0.0f;
}

// output_g: pos_g + g_qn @ queue_g, /TAU; also target_g. grid (K/128, B), block 128.
__global__ void outg_kernel(const float* __restrict__ queue_g, float* __restrict__ out) {
    int b = blockIdx.y;
    int t = threadIdx.x;
    int k = blockIdx.x * 128 + t;
    __shared__ float q[128];
    q[t] = g_gqn[b * D_ + t];
    __syncthreads();
    float acc = 0.0f;
#pragma unroll 16
    for (int d = 0; d < D_; d++) acc += q[d] * queue_g[(size_t)d * K_ + k];
    out[OG + (size_t)b * (K_ + 1) + 1 + k] = acc * INV_TAU;
    if (blockIdx.x == 0 && t == 0) {
        float p = 0.0f;
        for (int d = 0; d < D_; d++) p += g_gqn[b * D_ + d] * g_gkn[b * D_ + d];
        out[OG + (size_t)b * (K_ + 1)] = p * INV_TAU;
        out[TG + b] = 0.0f;
    }
}

// ---------------------------------------------------------------------------
// neg_d: out[b, 1+q, z] = (1/TAU) * sum_d queue_d[d,q] * d_qg[b,d,z]
// grid (K/128 q-tiles, S/128 z-tiles, B), block 256, 128x128 tile, K=128.
__global__ __launch_bounds__(256) void negd_kernel(const float* __restrict__ queue_d,
                                                   float* __restrict__ out) {
    __shared__ float As[16][132];   // [k][q]
    __shared__ float Bs[16][132];   // [k][z]

    int b = blockIdx.z;
    int q0 = blockIdx.x * 128;
    int z0 = blockIdx.y * 128;
    int tid = threadIdx.x;
    int tx = tid & 15;
    int ty = tid >> 4;

    u64 acc[4][8];
#pragma unroll
    for (int p = 0; p < 4; p++)
#pragma unroll
        for (int j = 0; j < 8; j++) acc[p][j] = 0ull;

    for (int c0 = 0; c0 < D_; c0 += 16) {
#pragma unroll
        for (int l = tid; l < 2048; l += 256) {
            int cc = l >> 7, col = l & 127;
            As[cc][col] = queue_d[(size_t)(c0 + cc) * K_ + q0 + col];
            Bs[cc][col] = g_dqg[((size_t)b * D_ + c0 + cc) * S_ + z0 + col];
        }
        __syncthreads();
#pragma unroll
        for (int cc = 0; cc < 16; cc++) {
            const u64* arow = reinterpret_cast<const u64*>(&As[cc][ty * 8]);
            u64 av[4] = {arow[0], arow[1], arow[2], arow[3]};
            const float4* brow = reinterpret_cast<const float4*>(&Bs[cc][tx * 8]);
            float4 b0 = brow[0], b1 = brow[1];
            u64 bb[8] = {dup2(b0.x), dup2(b0.y), dup2(b0.z), dup2(b0.w),
                         dup2(b1.x), dup2(b1.y), dup2(b1.z), dup2(b1.w)};
#pragma unroll
            for (int p = 0; p < 4; p++)
#pragma unroll
                for (int j = 0; j < 8; j++) ffma2(acc[p][j], av[p], bb[j]);
        }
        __syncthreads();
    }

    // epilogue: rows q = q0 + ty*8 + (2p, 2p+1), cols z = z0 + tx*8 + j
#pragma unroll
    for (int p = 0; p < 4; p++) {
        float lo[8], hi[8];
#pragma unroll
        for (int j = 0; j < 8; j++) unpack2(acc[p][j], lo[j], hi[j]);
        size_t row_lo = (size_t)(b * (K_ + 1) + 1 + q0 + ty * 8 + 2 * p);
        float* plo = out + OD + row_lo * S_ + z0 + tx * 8;
        float* phi = plo + S_;
        float4 w;
        w.x = lo[0] * INV_TAU; w.y = lo[1] * INV_TAU; w.z = lo[2] * INV_TAU; w.w = lo[3] * INV_TAU;
        *reinterpret_cast<float4*>(plo) = w;
        w.x = lo[4] * INV_TAU; w.y = lo[5] * INV_TAU; w.z = lo[6] * INV_TAU; w.w = lo[7] * INV_TAU;
        *reinterpret_cast<float4*>(plo + 4) = w;
        w.x = hi[0] * INV_TAU; w.y = hi[1] * INV_TAU; w.z = hi[2] * INV_TAU; w.w = hi[3] * INV_TAU;
        *reinterpret_cast<float4*>(phi) = w;
        w.x = hi[4] * INV_TAU; w.y = hi[5] * INV_TAU; w.z = hi[6] * INV_TAU; w.w = hi[7] * INV_TAU;
        *reinterpret_cast<float4*>(phi + 4) = w;
    }
}

// ---------------------------------------------------------------------------
extern "C" void kernel_launch(void* const* d_in, const int* in_sizes, int n_in,
                              void* d_out, int out_size) {
    const float* g_q    = (const float*)d_in[0];
    const float* g_k    = (const float*)d_in[1];
    const float* d_q    = (const float*)d_in[2];
    const float* d_k    = (const float*)d_in[3];
    const float* feat_q = (const float*)d_in[4];
    const float* feat_k = (const float*)d_in[5];
    const float* queue_g = (const float*)d_in[6];
    const float* queue_d = (const float*)d_in[7];
    float* out = (float*)d_out;

    zero_best_kernel<<<8, 1024>>>();
    norm_g_kernel<<<dim3(2, B_), 128>>>(g_q, g_k);
    norm_dq_kernel<<<dim3(S_ / 256, B_), 256>>>(d_q);
    norm_dk_kernel<<<dim3(S_ / 256, B_), 256>>>(d_k);
    norm_fk_kernel<<<dim3(S_ / 256, B_), 256>>>(feat_k);
    cos_argmax_kernel<<<dim3(S_ / 128, S_ / 128, B_), 256>>>(feat_q);
    gather_kernel<<<dim3(S_ / 256, B_), 256>>>(out);
    outg_kernel<<<dim3(K_ / 128, B_), 128>>>(queue_g, out);
    negd_kernel<<<dim3(K_ / 128, S_ / 128, B_), 256>>>(queue_d, out);
}

// round 3
// speedup vs baseline: 1.2265x; 1.2265x over previous
#include <cuda_runtime.h>
#include <cuda_bf16.h>
#include <cstdint>

typedef unsigned long long u64;

// Problem constants
constexpr int B_ = 8;
constexpr int D_ = 128;
constexpr int S_ = 1024;
constexpr int C_ = 512;
constexpr int K_ = 16384;
constexpr float INV_TAU = 5.0f;

// Output layout (flattened concatenation, float32):
// output_g [B, 1+K], target_g [B], output_d [B, 1+K, S], target_d [B, S]
constexpr size_t OG = 0;
constexpr size_t TG = (size_t)B_ * (K_ + 1);
constexpr size_t OD = TG + B_;
constexpr size_t TD = OD + (size_t)B_ * (K_ + 1) * S_;

// Scratch (device globals; no allocation allowed)
__device__ float g_fkn[B_ * C_ * S_];   // normalized feat_k
__device__ float g_dqn[B_ * D_ * S_];   // normalized d_q
__device__ float g_dkn[B_ * D_ * S_];   // normalized d_k
__device__ float g_gqn[B_ * D_];
__device__ float g_gkn[B_ * D_];
__device__ u64   g_best[B_ * S_];       // packed (ordered max value, ~idx)

// bf16 hi/lo tiles, plain row-major [tile][row(128)][d(128 bf16 = 16 uint4)]
__device__ uint4 g_qth4[128 * 2048];    // queue_d hi: 128 q-tiles
__device__ uint4 g_qtl4[128 * 2048];    // queue_d lo
__device__ uint4 g_bth4[64 * 2048];     // gathered d_q hi: 8b x 8 z-tiles
__device__ uint4 g_btl4[64 * 2048];     // gathered d_q lo

// ---------- packed f32x2 helpers (Blackwell FFMA2) ----------
__device__ __forceinline__ u64 dup2(float x) {
    u64 r; asm("mov.b64 %0, {%1, %1};" : "=l"(r) : "f"(x)); return r;
}
__device__ __forceinline__ void unpack2(u64 v, float& lo, float& hi) {
    asm("mov.b64 {%0, %1}, %2;" : "=f"(lo), "=f"(hi) : "l"(v));
}
__device__ __forceinline__ void ffma2(u64& d, u64 a, u64 b) {
    asm("fma.rn.f32x2 %0, %1, %2, %0;" : "+l"(d) : "l"(a), "l"(b));
}

__device__ __forceinline__ unsigned ford(float f) {
    unsigned u = __float_as_uint(f);
    return (u & 0x80000000u) ? ~u : (u | 0x80000000u);
}

// ---------- sm_80-class tensor ISA (valid at compute_103) ----------
__device__ __forceinline__ uint32_t smem_to_u32(const void* p) {
    uint32_t a;
    asm("{ .reg .u64 t; cvta.to.shared.u64 t, %1; cvt.u32.u64 %0, t; }"
        : "=r"(a) : "l"(p));
    return a;
}
#define LDSM_X4(r0, r1, r2, r3, a) \
    asm volatile("ldmatrix.sync.aligned.m8n8.x4.shared.b16 {%0,%1,%2,%3}, [%4];" \
                 : "=r"(r0), "=r"(r1), "=r"(r2), "=r"(r3) : "r"(a))
#define LDSM_X2(r0, r1, a) \
    asm volatile("ldmatrix.sync.aligned.m8n8.x2.shared.b16 {%0,%1}, [%2];" \
                 : "=r"(r0), "=r"(r1) : "r"(a))
#define MMA_BF16(c, a, b) \
    asm volatile("mma.sync.aligned.m16n8k16.row.col.f32.bf16.bf16.f32 " \
                 "{%0,%1,%2,%3}, {%4,%5,%6,%7}, {%8,%9}, {%0,%1,%2,%3};" \
                 : "+f"((c)[0]), "+f"((c)[1]), "+f"((c)[2]), "+f"((c)[3]) \
                 : "r"((a)[0]), "r"((a)[1]), "r"((a)[2]), "r"((a)[3]), \
                   "r"((b)[0]), "r"((b)[1]))
#define CP16(dst, src) \
    asm volatile("cp.async.cg.shared.global [%0], [%1], 16;" \
                 :: "r"(dst), "l"(src))
#define CP_COMMIT() asm volatile("cp.async.commit_group;")
#define CP_WAIT0()  asm volatile("cp.async.wait_group 0;" ::: "memory")

// ---------------------------------------------------------------------------
__global__ void zero_best_kernel() {
    int i = blockIdx.x * blockDim.x + threadIdx.x;
    if (i < B_ * S_) g_best[i] = 0ull;
}

__global__ void norm_g_kernel(const float* __restrict__ gq,
                              const float* __restrict__ gk) {
    int b = blockIdx.y;
    const float* src = blockIdx.x ? gk : gq;
    float* dst = blockIdx.x ? g_gkn : g_gqn;
    int t = threadIdx.x;
    float v = src[b * D_ + t];
    __shared__ float sm[128];
    sm[t] = v * v;
    __syncthreads();
    for (int off = 64; off; off >>= 1) {
        if (t < off) sm[t] += sm[t + off];
        __syncthreads();
    }
    float sc = rsqrtf(fmaxf(sm[0], 1e-24f));
    dst[b * D_ + t] = v * sc;
}

// Column-normalize [B, C, S] along C. block 256 = 64 cols x 4 c-groups.
// grid (S/64, B). 4x the CTA count / quarter the per-thread loop vs R1.
template <int C>
__device__ __forceinline__ void norm_cols_body(const float* __restrict__ src,
                                               float* __restrict__ dst) {
    __shared__ float red[4][64];
    int b = blockIdx.y;
    int sl = threadIdx.x & 63;
    int g = threadIdx.x >> 6;
    int s = blockIdx.x * 64 + sl;
    const float* p = src + (size_t)b * C * S_ + s;
    float ss = 0.0f;
#pragma unroll 8
    for (int c = g * (C / 4); c < (g + 1) * (C / 4); c++) {
        float v = p[(size_t)c * S_];
        ss += v * v;
    }
    red[g][sl] = ss;
    __syncthreads();
    float tot = red[0][sl] + red[1][sl] + red[2][sl] + red[3][sl];
    float sc = rsqrtf(fmaxf(tot, 1e-24f));
    float* q = dst + (size_t)b * C * S_ + s;
#pragma unroll 8
    for (int c = g * (C / 4); c < (g + 1) * (C / 4); c++)
        q[(size_t)c * S_] = p[(size_t)c * S_] * sc;
}
__global__ void norm_dq_kernel(const float* __restrict__ src) { norm_cols_body<128>(src, g_dqn); }
__global__ void norm_dk_kernel(const float* __restrict__ src) { norm_cols_body<128>(src, g_dkn); }
__global__ void norm_fk_kernel(const float* __restrict__ src) { norm_cols_body<512>(src, g_fkn); }

// ---------------------------------------------------------------------------
// cosine + argmax (fp32 FFMA2, unchanged — known correct)
__global__ __launch_bounds__(256) void cos_argmax_kernel(const float* __restrict__ featq) {
    __shared__ float As[16][132];
    __shared__ float Bs[16][132];
    __shared__ u64 red[16][128];

    int b = blockIdx.z;
    int i0 = blockIdx.x * 128;
    int j0 = blockIdx.y * 128;
    int tid = threadIdx.x;
    int tx = tid & 15;
    int ty = tid >> 4;

    const float* fk = g_fkn + (size_t)b * C_ * S_;
    const float* fq = featq + (size_t)b * C_ * S_;

    u64 acc[4][8];
#pragma unroll
    for (int p = 0; p < 4; p++)
#pragma unroll
        for (int j = 0; j < 8; j++) acc[p][j] = 0ull;

    for (int c0 = 0; c0 < C_; c0 += 16) {
#pragma unroll
        for (int l = tid; l < 2048; l += 256) {
            int cc = l >> 7, col = l & 127;
            As[cc][col] = fk[(size_t)(c0 + cc) * S_ + i0 + col];
            Bs[cc][col] = fq[(size_t)(c0 + cc) * S_ + j0 + col];
        }
        __syncthreads();
#pragma unroll
        for (int cc = 0; cc < 16; cc++) {
            const u64* arow = reinterpret_cast<const u64*>(&As[cc][ty * 8]);
            u64 av[4] = {arow[0], arow[1], arow[2], arow[3]};
            const float4* brow = reinterpret_cast<const float4*>(&Bs[cc][tx * 8]);
            float4 b0 = brow[0], b1 = brow[1];
            u64 bb[8] = {dup2(b0.x), dup2(b0.y), dup2(b0.z), dup2(b0.w),
                         dup2(b1.x), dup2(b1.y), dup2(b1.z), dup2(b1.w)};
#pragma unroll
            for (int p = 0; p < 4; p++)
#pragma unroll
                for (int j = 0; j < 8; j++) ffma2(acc[p][j], av[p], bb[j]);
        }
        __syncthreads();
    }

    float bestv[8];
    unsigned besti[8];
#pragma unroll
    for (int j = 0; j < 8; j++) { bestv[j] = -2.0f; besti[j] = 0; }
#pragma unroll
    for (int p = 0; p < 4; p++) {
#pragma unroll
        for (int j = 0; j < 8; j++) {
            float lo, hi;
            unpack2(acc[p][j], lo, hi);
            unsigned ib = (unsigned)(i0 + ty * 8 + 2 * p);
            if (lo > bestv[j]) { bestv[j] = lo; besti[j] = ib; }
            if (hi > bestv[j]) { bestv[j] = hi; besti[j] = ib + 1; }
        }
    }
#pragma unroll
    for (int j = 0; j < 8; j++) {
        u64 key = ((u64)ford(bestv[j]) << 32) | (u64)(0xFFFFFFFFu - besti[j]);
        red[ty][tx * 8 + j] = key;
    }
    __syncthreads();
    if (tid < 128) {
        u64 m = red[0][tid];
#pragma unroll
        for (int t = 1; t < 16; t++) m = max(m, red[t][tid]);
        atomicMax(&g_best[b * S_ + j0 + tid], m);
    }
}

// ---------------------------------------------------------------------------
// pos_d + output_d row 0 + target_d (fp32 exact)
__global__ void gather_kernel(float* __restrict__ out) {
    int b = blockIdx.y;
    int z = blockIdx.x * blockDim.x + threadIdx.x;
    u64 key = g_best[b * S_ + z];
    int m = (int)(0xFFFFFFFFu - (unsigned)(key & 0xFFFFFFFFull));
    float pos = 0.0f;
#pragma unroll 4
    for (int d = 0; d < D_; d++) {
        float v = g_dqn[((size_t)b * D_ + d) * S_ + m];
        pos += g_dkn[((size_t)b * D_ + d) * S_ + z] * v;
    }
    out[OD + (size_t)b * (K_ + 1) * S_ + z] = pos * INV_TAU;
    out[TD + (size_t)b * S_ + z] = 0.0f;
}

// Build row-major bf16 hi/lo B tiles from gathered d_qn.
// 65536 threads: b(3b) | dgp(3b) | z(10b); each handles 16 d's (2 uint4 = 32B).
__global__ void btile_kernel() {
    int t = blockIdx.x * blockDim.x + threadIdx.x;
    int b = t >> 13;
    int dgp = (t >> 10) & 7;
    int z = t & 1023;
    int d0 = dgp << 4;
    u64 key = g_best[b * S_ + z];
    int m = (int)(0xFFFFFFFFu - (unsigned)(key & 0xFFFFFFFFull));
    __nv_bfloat16 h[16], l[16];
#pragma unroll
    for (int j = 0; j < 16; j++) {
        float v = g_dqn[((size_t)b * D_ + d0 + j) * S_ + m];
        __nv_bfloat16 hh = __float2bfloat16(v);
        h[j] = hh;
        l[j] = __float2bfloat16(v - __bfloat162float(hh));
    }
    size_t idx = ((size_t)((b * 8 + (z >> 7)) * 128 + (z & 127))) * 16 + dgp * 2;
    const uint4* h4 = reinterpret_cast<const uint4*>(h);
    const uint4* l4 = reinterpret_cast<const uint4*>(l);
    g_bth4[idx] = h4[0]; g_bth4[idx + 1] = h4[1];
    g_btl4[idx] = l4[0]; g_btl4[idx + 1] = l4[1];
}

// Build row-major bf16 hi/lo A tiles from queue_d.
// 131072 threads: dgp(3b) | q(14b); each handles 16 d's.
__global__ void qconv_kernel(const float* __restrict__ queue_d) {
    int t = blockIdx.x * blockDim.x + threadIdx.x;
    int dgp = t >> 14;
    int q = t & 16383;
    int d0 = dgp << 4;
    __nv_bfloat16 h[16], l[16];
#pragma unroll
    for (int j = 0; j < 16; j++) {
        float v = queue_d[(size_t)(d0 + j) * K_ + q];
        __nv_bfloat16 hh = __float2bfloat16(v);
        h[j] = hh;
        l[j] = __float2bfloat16(v - __bfloat162float(hh));
    }
    size_t idx = ((size_t)((q >> 7) * 128 + (q & 127))) * 16 + dgp * 2;
    const uint4* h4 = reinterpret_cast<const uint4*>(h);
    const uint4* l4 = reinterpret_cast<const uint4*>(l);
    g_qth4[idx] = h4[0]; g_qth4[idx + 1] = h4[1];
    g_qtl4[idx] = l4[0]; g_qtl4[idx + 1] = l4[1];
}

// ---------------------------------------------------------------------------
// output_g (fp32, unchanged)
__global__ void outg_kernel(const float* __restrict__ queue_g, float* __restrict__ out) {
    int b = blockIdx.y;
    int t = threadIdx.x;
    int k = blockIdx.x * 128 + t;
    __shared__ float q[128];
    q[t] = g_gqn[b * D_ + t];
    __syncthreads();
    float acc = 0.0f;
#pragma unroll 16
    for (int d = 0; d < D_; d++) acc += q[d] * queue_g[(size_t)d * K_ + k];
    out[OG + (size_t)b * (K_ + 1) + 1 + k] = acc * INV_TAU;
    if (blockIdx.x == 0 && t == 0) {
        float p = 0.0f;
        for (int d = 0; d < D_; d++) p += g_gqn[b * D_ + d] * g_gkn[b * D_ + d];
        out[OG + (size_t)b * (K_ + 1)] = p * INV_TAU;
        out[TG + b] = 0.0f;
    }
}

// ---------------------------------------------------------------------------
// negd via mma.sync bf16 (3-term hi/lo split). CTA = (q-tile 128, b), loops
// 8 z-tiles of 128. 8 warps in 2(m) x 4(n); warp tile 64x32; m16n8k16.
// SMEM rows padded to 272B: bank(r,c) = (4r + c) % 32 -> conflict-free ldmatrix.
constexpr int TSTRIDE = 272;              // 128 bf16 + 8 pad
constexpr int TILE_BYTES_SM = 128 * TSTRIDE;  // 34816
constexpr int SM_AH = 0;
constexpr int SM_AL = TILE_BYTES_SM;
constexpr int SM_BB = 2 * TILE_BYTES_SM;  // 2 stages x (hi+lo) follow
constexpr int STAGE_BYTES = 2 * TILE_BYTES_SM;
constexpr int SMEM_NEGD = SM_BB + 2 * STAGE_BYTES;  // 208896

__device__ __forceinline__ void cp_tile(uint32_t smDst, const uint4* src, int tid) {
#pragma unroll
    for (int k = 0; k < 8; k++) {
        int idx = tid + k * 256;
        int row = idx >> 4, w = idx & 15;
        CP16(smDst + row * TSTRIDE + w * 16, src + idx);
    }
}

__global__ __launch_bounds__(256) void negd_mma_kernel(float* __restrict__ out) {
    extern __shared__ char smem[];
    const uint32_t sb = smem_to_u32(smem);
    const int tid = threadIdx.x;
    const int lane = tid & 31;
    const int wid = tid >> 5;
    const int wm = wid & 1;        // m-group (64 q-rows)
    const int wn = wid >> 1;       // n-group (32 z-cols)
    const int qt = blockIdx.x;
    const int b = blockIdx.y;
    const int q0 = qt << 7;

    // ldmatrix lane offsets
    uint32_t aoff[4], boff[4];
    {
        int arow = wm * 64 + ((lane >> 3) & 1) * 8 + (lane & 7);
        int acol = ((lane >> 4) & 1) * 16;
#pragma unroll
        for (int i = 0; i < 4; i++) aoff[i] = (arow + i * 16) * TSTRIDE + acol;
        int brow = lane & 7;
        int bcol = ((lane >> 3) & 1) * 16;
#pragma unroll
        for (int j = 0; j < 4; j++) boff[j] = (wn * 32 + j * 8 + brow) * TSTRIDE + bcol;
    }

    // A (persistent) + B stage 0
    cp_tile(sb + SM_AH, g_qth4 + (size_t)qt * 2048, tid);
    cp_tile(sb + SM_AL, g_qtl4 + (size_t)qt * 2048, tid);
    cp_tile(sb + SM_BB, g_bth4 + (size_t)(b * 8) * 2048, tid);
    cp_tile(sb + SM_BB + TILE_BYTES_SM, g_btl4 + (size_t)(b * 8) * 2048, tid);
    CP_COMMIT();
    CP_WAIT0();
    __syncthreads();

    for (int it = 0; it < 8; it++) {
        const int stage = it & 1;
        if (it < 7) {
            uint32_t d = sb + SM_BB + (stage ^ 1) * STAGE_BYTES;
            cp_tile(d, g_bth4 + (size_t)(b * 8 + it + 1) * 2048, tid);
            cp_tile(d + TILE_BYTES_SM, g_btl4 + (size_t)(b * 8 + it + 1) * 2048, tid);
            CP_COMMIT();
        }

        float acc[4][4][4];
#pragma unroll
        for (int i = 0; i < 4; i++)
#pragma unroll
            for (int j = 0; j < 4; j++)
#pragma unroll
                for (int r = 0; r < 4; r++) acc[i][j][r] = 0.0f;

        const uint32_t aH = sb + SM_AH;
        const uint32_t aL = sb + SM_AL;
        const uint32_t bH = sb + SM_BB + stage * STAGE_BYTES;
        const uint32_t bL = bH + TILE_BYTES_SM;

#pragma unroll
        for (int ks = 0; ks < 8; ks++) {
            uint32_t Ah[4][4], Al[4][4], Bh[4][2], Bl[4][2];
#pragma unroll
            for (int i = 0; i < 4; i++) {
                LDSM_X4(Ah[i][0], Ah[i][1], Ah[i][2], Ah[i][3], aH + aoff[i] + ks * 32);
                LDSM_X4(Al[i][0], Al[i][1], Al[i][2], Al[i][3], aL + aoff[i] + ks * 32);
            }
#pragma unroll
            for (int j = 0; j < 4; j++) {
                LDSM_X2(Bh[j][0], Bh[j][1], bH + boff[j] + ks * 32);
                LDSM_X2(Bl[j][0], Bl[j][1], bL + boff[j] + ks * 32);
            }
#pragma unroll
            for (int i = 0; i < 4; i++)
#pragma unroll
                for (int j = 0; j < 4; j++) {
                    MMA_BF16(acc[i][j], Ah[i], Bh[j]);
                    MMA_BF16(acc[i][j], Ah[i], Bl[j]);
                    MMA_BF16(acc[i][j], Al[i], Bh[j]);
                }
        }

        // epilogue: c0,c1 -> (q, z..z+1); c2,c3 -> (q+8, z..z+1)
#pragma unroll
        for (int i = 0; i < 4; i++) {
            int q = q0 + wm * 64 + i * 16 + (lane >> 2);
            float* rowp = out + OD + (size_t)(b * (K_ + 1) + 1 + q) * S_;
#pragma unroll
            for (int j = 0; j < 4; j++) {
                int z = it * 128 + wn * 32 + j * 8 + 2 * (lane & 3);
                float2 w0 = {acc[i][j][0] * INV_TAU, acc[i][j][1] * INV_TAU};
                float2 w1 = {acc[i][j][2] * INV_TAU, acc[i][j][3] * INV_TAU};
                *reinterpret_cast<float2*>(rowp + z) = w0;
                *reinterpret_cast<float2*>(rowp + 8 * S_ + z) = w1;
            }
        }

        if (it < 7) CP_WAIT0();
        __syncthreads();
    }
}

// ---------------------------------------------------------------------------
extern "C" void kernel_launch(void* const* d_in, const int* in_sizes, int n_in,
                              void* d_out, int out_size) {
    const float* g_q     = (const float*)d_in[0];
    const float* g_k     = (const float*)d_in[1];
    const float* d_q     = (const float*)d_in[2];
    const float* d_k     = (const float*)d_in[3];
    const float* feat_q  = (const float*)d_in[4];
    const float* feat_k  = (const float*)d_in[5];
    const float* queue_g = (const float*)d_in[6];
    const float* queue_d = (const float*)d_in[7];
    float* out = (float*)d_out;

    cudaFuncSetAttribute(negd_mma_kernel,
                         cudaFuncAttributeMaxDynamicSharedMemorySize, SMEM_NEGD);

    zero_best_kernel<<<8, 1024>>>();
    norm_g_kernel<<<dim3(2, B_), 128>>>(g_q, g_k);
    norm_dq_kernel<<<dim3(S_ / 64, B_), 256>>>(d_q);
    norm_dk_kernel<<<dim3(S_ / 64, B_), 256>>>(d_k);
    norm_fk_kernel<<<dim3(S_ / 64, B_), 256>>>(feat_k);
    qconv_kernel<<<131072 / 256, 256>>>(queue_d);
    cos_argmax_kernel<<<dim3(S_ / 128, S_ / 128, B_), 256>>>(feat_q);
    gather_kernel<<<dim3(S_ / 256, B_), 256>>>(out);
    btile_kernel<<<65536 / 256, 256>>>();
    outg_kernel<<<dim3(K_ / 128, B_), 128>>>(queue_g, out);
    negd_mma_kernel<<<dim3(128, B_), 256, SMEM_NEGD>>>(out);
}

// round 4
// speedup vs baseline: 2.1167x; 1.7258x over previous
#include <cuda_runtime.h>
#include <cuda_fp16.h>
#include <cstdint>

typedef unsigned long long u64;

// Problem constants
constexpr int B_ = 8;
constexpr int D_ = 128;
constexpr int S_ = 1024;
constexpr int C_ = 512;
constexpr int K_ = 16384;
constexpr float INV_TAU = 5.0f;

// Output layout (flattened concatenation, float32)
constexpr size_t OG = 0;
constexpr size_t TG = (size_t)B_ * (K_ + 1);
constexpr size_t OD = TG + B_;
constexpr size_t TD = OD + (size_t)B_ * (K_ + 1) * S_;

// Scratch (device globals; no allocation allowed)
__device__ float g_fkn[B_ * C_ * S_];   // normalized feat_k (fp32, for exact rescore)
__device__ float g_dqn[B_ * D_ * S_];   // normalized d_q
__device__ float g_dkn[B_ * D_ * S_];   // normalized d_k
__device__ float g_gqn[B_ * D_];
__device__ float g_gkn[B_ * D_];
__device__ u64   g_best[B_ * S_];       // final packed (ordered val, ~idx)
__device__ u64   g_top2[B_ * S_ * 16];  // per (col, itile): top-2 approx keys

// fp16 hi/lo transposed features: [b][s][c]
__device__ __half g_fkh[B_ * S_ * C_];
__device__ __half g_fkl[B_ * S_ * C_];
__device__ __half g_fqh[B_ * S_ * C_];
__device__ __half g_fql[B_ * S_ * C_];

// fp16 row-major tiles for negd: [tile][row(128)][d(128)] -> 2048 uint4/tile
__device__ uint4 g_qt4[128 * 2048];     // queue_d
__device__ uint4 g_bt4[64 * 2048];      // gathered d_q (8b x 8 z-tiles)

// ---------- helpers ----------
__device__ __forceinline__ unsigned ford(float f) {
    unsigned u = __float_as_uint(f);
    return (u & 0x80000000u) ? ~u : (u | 0x80000000u);
}
__device__ __forceinline__ float unford(unsigned x) {
    unsigned u = (x & 0x80000000u) ? (x & 0x7FFFFFFFu) : ~x;
    return __uint_as_float(u);
}
__device__ __forceinline__ u64 umax64(u64 a, u64 b) { return a > b ? a : b; }
__device__ __forceinline__ u64 umin64(u64 a, u64 b) { return a < b ? a : b; }

__device__ __forceinline__ uint32_t smem_to_u32(const void* p) {
    uint32_t a;
    asm("{ .reg .u64 t; cvta.to.shared.u64 t, %1; cvt.u32.u64 %0, t; }"
        : "=r"(a) : "l"(p));
    return a;
}
#define LDSM_X4(r0, r1, r2, r3, a) \
    asm volatile("ldmatrix.sync.aligned.m8n8.x4.shared.b16 {%0,%1,%2,%3}, [%4];" \
                 : "=r"(r0), "=r"(r1), "=r"(r2), "=r"(r3) : "r"(a))
#define LDSM_X2(r0, r1, a) \
    asm volatile("ldmatrix.sync.aligned.m8n8.x2.shared.b16 {%0,%1}, [%2];" \
                 : "=r"(r0), "=r"(r1) : "r"(a))
#define MMA_FP16(c, a, b) \
    asm volatile("mma.sync.aligned.m16n8k16.row.col.f32.f16.f16.f32 " \
                 "{%0,%1,%2,%3}, {%4,%5,%6,%7}, {%8,%9}, {%0,%1,%2,%3};" \
                 : "+f"((c)[0]), "+f"((c)[1]), "+f"((c)[2]), "+f"((c)[3]) \
                 : "r"((a)[0]), "r"((a)[1]), "r"((a)[2]), "r"((a)[3]), \
                   "r"((b)[0]), "r"((b)[1]))
#define CP16(dst, src) \
    asm volatile("cp.async.cg.shared.global [%0], [%1], 16;" \
                 :: "r"(dst), "l"(src))
#define CP_COMMIT() asm volatile("cp.async.commit_group;")
#define CP_WAIT0()  asm volatile("cp.async.wait_group 0;" ::: "memory")

// ---------------------------------------------------------------------------
__global__ void norm_g_kernel(const float* __restrict__ gq,
                              const float* __restrict__ gk) {
    int b = blockIdx.y;
    const float* src = blockIdx.x ? gk : gq;
    float* dst = blockIdx.x ? g_gkn : g_gqn;
    int t = threadIdx.x;
    float v = src[b * D_ + t];
    __shared__ float sm[128];
    sm[t] = v * v;
    __syncthreads();
    for (int off = 64; off; off >>= 1) {
        if (t < off) sm[t] += sm[t + off];
        __syncthreads();
    }
    float sc = rsqrtf(fmaxf(sm[0], 1e-24f));
    dst[b * D_ + t] = v * sc;
}

// Column-normalize [B, C, S] along C. block 256 = 64 cols x 4 c-groups.
template <int C>
__device__ __forceinline__ void norm_cols_body(const float* __restrict__ src,
                                               float* __restrict__ dst) {
    __shared__ float red[4][64];
    int b = blockIdx.y;
    int sl = threadIdx.x & 63;
    int g = threadIdx.x >> 6;
    int s = blockIdx.x * 64 + sl;
    const float* p = src + (size_t)b * C * S_ + s;
    float ss = 0.0f;
#pragma unroll 8
    for (int c = g * (C / 4); c < (g + 1) * (C / 4); c++) {
        float v = p[(size_t)c * S_];
        ss += v * v;
    }
    red[g][sl] = ss;
    __syncthreads();
    float tot = red[0][sl] + red[1][sl] + red[2][sl] + red[3][sl];
    float sc = rsqrtf(fmaxf(tot, 1e-24f));
    float* q = dst + (size_t)b * C * S_ + s;
#pragma unroll 8
    for (int c = g * (C / 4); c < (g + 1) * (C / 4); c++)
        q[(size_t)c * S_] = p[(size_t)c * S_] * sc;
}
__global__ void norm_dq_kernel(const float* __restrict__ src) { norm_cols_body<128>(src, g_dqn); }
__global__ void norm_dk_kernel(const float* __restrict__ src) { norm_cols_body<128>(src, g_dkn); }
__global__ void norm_fk_kernel(const float* __restrict__ src) { norm_cols_body<512>(src, g_fkn); }

// ---------------------------------------------------------------------------
// Transpose [b][c][s] -> [b][s][c] with fp16 hi/lo split. z<8: fk (from g_fkn);
// z>=8: feat_q raw. grid (S/32, C/32, 16), block (32, 8).
__global__ void fsplit_kernel(const float* __restrict__ featq) {
    __shared__ float tile[32][33];
    int z = blockIdx.z;
    bool isk = z < 8;
    int b = isk ? z : z - 8;
    const float* src = isk ? (const float*)g_fkn : featq;
    __half* dh = isk ? g_fkh : g_fqh;
    __half* dl = isk ? g_fkl : g_fql;
    int s0 = blockIdx.x * 32, c0 = blockIdx.y * 32;
#pragma unroll
    for (int r = 0; r < 4; r++) {
        int c = c0 + threadIdx.y * 4 + r;
        tile[threadIdx.y * 4 + r][threadIdx.x] =
            src[((size_t)b * C_ + c) * S_ + s0 + threadIdx.x];
    }
    __syncthreads();
#pragma unroll
    for (int r = 0; r < 4; r++) {
        int s = s0 + threadIdx.y * 4 + r;
        float v = tile[threadIdx.x][threadIdx.y * 4 + r];
        __half h = __float2half(v);
        __half l = __float2half(v - __half2float(h));
        size_t o = ((size_t)b * S_ + s) * C_ + c0 + threadIdx.x;
        dh[o] = h;
        dl[o] = l;
    }
}

// ---------------------------------------------------------------------------
// cosine via fp16 hi/lo 3-term mma + per-tile top-2. CTA = (itile, jtile, b).
// Stage: 128 rows x 16 c, row stride 48B (conflict-free ldmatrix), AH|AL|BH|BL.
constexpr int XSTRIDE = 48;
constexpr int STG_A = 128 * XSTRIDE;        // 6144
constexpr int STG_BYTES = 4 * STG_A;        // 24576
constexpr int SMEM_COS = 2 * STG_BYTES;     // 49152

__global__ __launch_bounds__(256) void cos_mma_kernel() {
    extern __shared__ char smem[];
    __shared__ u64 smtop[2][4][32][2];
    const uint32_t sb = smem_to_u32(smem);
    const int tid = threadIdx.x;
    const int lane = tid & 31;
    const int wid = tid >> 5;
    const int wm = wid & 1;
    const int wn = wid >> 1;
    const int it = blockIdx.x, jt = blockIdx.y, b = blockIdx.z;
    const int i0 = it * 128, j0 = jt * 128;

    uint32_t aoff[4], boff[4];
    {
        int arow = wm * 64 + ((lane >> 3) & 1) * 8 + (lane & 7);
        int acol = ((lane >> 4) & 1) * 16;
#pragma unroll
        for (int i = 0; i < 4; i++) aoff[i] = (arow + i * 16) * XSTRIDE + acol;
        int brow = lane & 7;
        int bcol = ((lane >> 3) & 1) * 16;
#pragma unroll
        for (int j = 0; j < 4; j++) boff[j] = (wn * 32 + j * 8 + brow) * XSTRIDE + bcol;
    }

    const __half* srcs[4] = {g_fkh, g_fkl, g_fqh, g_fql};

    auto load_stage = [&](int st, int ks) {
        uint32_t base = sb + st * STG_BYTES;
#pragma unroll
        for (int k = 0; k < 4; k++) {
            int idx = tid + k * 256;
            int arr = idx >> 8;
            int r = (idx >> 1) & 127;
            int half = idx & 1;
            int row = ((arr < 2) ? i0 : j0) + r;
            const __half* s = srcs[arr] + ((size_t)(b * 1024 + row) * 512 + ks * 16 + half * 8);
            CP16(base + arr * STG_A + r * XSTRIDE + half * 16, s);
        }
    };

    float acc[4][4][4];
#pragma unroll
    for (int i = 0; i < 4; i++)
#pragma unroll
        for (int j = 0; j < 4; j++)
#pragma unroll
            for (int r = 0; r < 4; r++) acc[i][j][r] = 0.0f;

    load_stage(0, 0);
    CP_COMMIT();
    CP_WAIT0();
    __syncthreads();

    for (int ks = 0; ks < 32; ks++) {
        const int st = ks & 1;
        if (ks < 31) { load_stage(st ^ 1, ks + 1); CP_COMMIT(); }
        const uint32_t base = sb + st * STG_BYTES;
        uint32_t Ah[4][4], Al[4][4], Bh[4][2], Bl[4][2];
#pragma unroll
        for (int i = 0; i < 4; i++) {
            LDSM_X4(Ah[i][0], Ah[i][1], Ah[i][2], Ah[i][3], base + aoff[i]);
            LDSM_X4(Al[i][0], Al[i][1], Al[i][2], Al[i][3], base + STG_A + aoff[i]);
        }
#pragma unroll
        for (int j = 0; j < 4; j++) {
            LDSM_X2(Bh[j][0], Bh[j][1], base + 2 * STG_A + boff[j]);
            LDSM_X2(Bl[j][0], Bl[j][1], base + 3 * STG_A + boff[j]);
        }
#pragma unroll
        for (int i = 0; i < 4; i++)
#pragma unroll
            for (int j = 0; j < 4; j++) {
                MMA_FP16(acc[i][j], Ah[i], Bh[j]);
                MMA_FP16(acc[i][j], Ah[i], Bl[j]);
                MMA_FP16(acc[i][j], Al[i], Bh[j]);
            }
        if (ks < 31) CP_WAIT0();
        __syncthreads();
    }

    // top-2 over this CTA's 128 i per column j
#pragma unroll
    for (int jf = 0; jf < 4; jf++) {
#pragma unroll
        for (int dj = 0; dj < 2; dj++) {
            u64 k1 = 0, k2 = 0;
#pragma unroll
            for (int i = 0; i < 4; i++) {
                unsigned ig = (unsigned)(i0 + wm * 64 + i * 16 + (lane >> 2));
                u64 key = ((u64)ford(acc[i][jf][dj]) << 32) | (u64)(0xFFFFFFFFu - ig);
                if (key > k1) { k2 = k1; k1 = key; } else if (key > k2) k2 = key;
                u64 key2 = ((u64)ford(acc[i][jf][dj + 2]) << 32) | (u64)(0xFFFFFFFFu - (ig + 8));
                if (key2 > k1) { k2 = k1; k1 = key2; } else if (key2 > k2) k2 = key2;
            }
#pragma unroll
            for (int m = 4; m <= 16; m <<= 1) {
                u64 o1 = __shfl_xor_sync(0xFFFFFFFFu, k1, m);
                u64 o2 = __shfl_xor_sync(0xFFFFFFFFu, k2, m);
                u64 n1 = umax64(k1, o1);
                u64 n2 = umax64(umin64(k1, o1), umax64(k2, o2));
                k1 = n1; k2 = n2;
            }
            if (lane < 4) {
                int j = jf * 8 + 2 * lane + dj;
                smtop[wm][wn][j][0] = k1;
                smtop[wm][wn][j][1] = k2;
            }
        }
    }
    __syncthreads();
    if (tid < 128) {
        int wn2 = tid >> 5, j = tid & 31;
        u64 a1 = smtop[0][wn2][j][0], a2 = smtop[0][wn2][j][1];
        u64 b1 = smtop[1][wn2][j][0], b2 = smtop[1][wn2][j][1];
        u64 k1 = umax64(a1, b1);
        u64 k2 = umax64(umin64(a1, b1), umax64(a2, b2));
        size_t col = (size_t)b * 1024 + j0 + wn2 * 32 + j;
        g_top2[col * 16 + it * 2] = k1;
        g_top2[col * 16 + it * 2 + 1] = k2;
    }
}

// ---------------------------------------------------------------------------
// finalize: provably-exact argmax. If a single candidate sits within the
// margin of the approx max, it is the exact argmax; else rescore in fp32.
__global__ void finalize_kernel(const float* __restrict__ featq) {
    int t = blockIdx.x * 256 + threadIdx.x;  // 8192 columns
    int b = t >> 10, j = t & 1023;
    u64 keys[16];
#pragma unroll
    for (int k = 0; k < 16; k++) keys[k] = g_top2[(size_t)t * 16 + k];
    u64 m1 = keys[0];
#pragma unroll
    for (int k = 1; k < 16; k++) m1 = umax64(m1, keys[k]);
    float vmax = unford((unsigned)(m1 >> 32));
    float thresh = vmax - 6e-3f;
    int cnt = 0;
#pragma unroll
    for (int k = 0; k < 16; k++)
        if (unford((unsigned)(keys[k] >> 32)) >= thresh) cnt++;
    u64 best = m1;
    if (cnt > 1) {
        float bv = -1e30f;
        unsigned bi = 0xFFFFFFFFu;
        for (int k = 0; k < 16; k++) {
            if (unford((unsigned)(keys[k] >> 32)) < thresh) continue;
            unsigned i = 0xFFFFFFFFu - (unsigned)(keys[k] & 0xFFFFFFFFull);
            const float* fk = g_fkn + (size_t)b * C_ * S_ + i;
            const float* fq = featq + (size_t)b * C_ * S_ + j;
            float ex = 0.0f;
#pragma unroll 4
            for (int c = 0; c < C_; c++) ex += fk[(size_t)c * S_] * fq[(size_t)c * S_];
            if (ex > bv || (ex == bv && i < bi)) { bv = ex; bi = i; }
        }
        best = ((u64)ford(bv) << 32) | (u64)(0xFFFFFFFFu - bi);
    }
    g_best[t] = best;
}

// ---------------------------------------------------------------------------
// pos_d + output_d row 0 + target_d (fp32 exact)
__global__ void gather_kernel(float* __restrict__ out) {
    int b = blockIdx.y;
    int z = blockIdx.x * blockDim.x + threadIdx.x;
    u64 key = g_best[b * S_ + z];
    int m = (int)(0xFFFFFFFFu - (unsigned)(key & 0xFFFFFFFFull));
    float pos = 0.0f;
#pragma unroll 4
    for (int d = 0; d < D_; d++) {
        float v = g_dqn[((size_t)b * D_ + d) * S_ + m];
        pos += g_dkn[((size_t)b * D_ + d) * S_ + z] * v;
    }
    out[OD + (size_t)b * (K_ + 1) * S_ + z] = pos * INV_TAU;
    out[TD + (size_t)b * S_ + z] = 0.0f;
}

// fp16 row-major B tiles from gathered d_qn. 65536 threads.
__global__ void btile_kernel() {
    int t = blockIdx.x * blockDim.x + threadIdx.x;
    int b = t >> 13;
    int dgp = (t >> 10) & 7;
    int z = t & 1023;
    int d0 = dgp << 4;
    u64 key = g_best[b * S_ + z];
    int m = (int)(0xFFFFFFFFu - (unsigned)(key & 0xFFFFFFFFull));
    __half h[16];
#pragma unroll
    for (int j = 0; j < 16; j++)
        h[j] = __float2half(g_dqn[((size_t)b * D_ + d0 + j) * S_ + m]);
    size_t idx = ((size_t)((b * 8 + (z >> 7)) * 128 + (z & 127))) * 16 + dgp * 2;
    const uint4* h4 = reinterpret_cast<const uint4*>(h);
    g_bt4[idx] = h4[0];
    g_bt4[idx + 1] = h4[1];
}

// fp16 row-major A tiles from queue_d. 131072 threads.
__global__ void qconv_kernel(const float* __restrict__ queue_d) {
    int t = blockIdx.x * blockDim.x + threadIdx.x;
    int dgp = t >> 14;
    int q = t & 16383;
    int d0 = dgp << 4;
    __half h[16];
#pragma unroll
    for (int j = 0; j < 16; j++)
        h[j] = __float2half(queue_d[(size_t)(d0 + j) * K_ + q]);
    size_t idx = ((size_t)((q >> 7) * 128 + (q & 127))) * 16 + dgp * 2;
    const uint4* h4 = reinterpret_cast<const uint4*>(h);
    g_qt4[idx] = h4[0];
    g_qt4[idx + 1] = h4[1];
}

// ---------------------------------------------------------------------------
// output_g (fp32 exact)
__global__ void outg_kernel(const float* __restrict__ queue_g, float* __restrict__ out) {
    int b = blockIdx.y;
    int t = threadIdx.x;
    int k = blockIdx.x * 128 + t;
    __shared__ float q[128];
    q[t] = g_gqn[b * D_ + t];
    __syncthreads();
    float acc = 0.0f;
#pragma unroll 16
    for (int d = 0; d < D_; d++) acc += q[d] * queue_g[(size_t)d * K_ + k];
    out[OG + (size_t)b * (K_ + 1) + 1 + k] = acc * INV_TAU;
    if (blockIdx.x == 0 && t == 0) {
        float p = 0.0f;
        for (int d = 0; d < D_; d++) p += g_gqn[b * D_ + d] * g_gkn[b * D_ + d];
        out[OG + (size_t)b * (K_ + 1)] = p * INV_TAU;
        out[TG + b] = 0.0f;
    }
}

// ---------------------------------------------------------------------------
// negd via single-pass fp16 mma. CTA = (q-tile 128, b), loops 8 z-tiles.
// 8 warps 2(m) x 4(n), warp tile 64x32. 272B-padded smem rows.
constexpr int TSTRIDE = 272;
constexpr int TILE_BYTES_SM = 128 * TSTRIDE;       // 34816
constexpr int SM_A = 0;
constexpr int SM_B = TILE_BYTES_SM;
constexpr int SMEM_NEGD = 3 * TILE_BYTES_SM;       // 104448 -> 2 CTAs/SM

__device__ __forceinline__ void cp_tile(uint32_t smDst, const uint4* src, int tid) {
#pragma unroll
    for (int k = 0; k < 8; k++) {
        int idx = tid + k * 256;
        int row = idx >> 4, w = idx & 15;
        CP16(smDst + row * TSTRIDE + w * 16, src + idx);
    }
}

__global__ __launch_bounds__(256) void negd_mma_kernel(float* __restrict__ out) {
    extern __shared__ char smem[];
    const uint32_t sb = smem_to_u32(smem);
    const int tid = threadIdx.x;
    const int lane = tid & 31;
    const int wid = tid >> 5;
    const int wm = wid & 1;
    const int wn = wid >> 1;
    const int qt = blockIdx.x;
    const int b = blockIdx.y;
    const int q0 = qt << 7;

    uint32_t aoff[4], boff[4];
    {
        int arow = wm * 64 + ((lane >> 3) & 1) * 8 + (lane & 7);
        int acol = ((lane >> 4) & 1) * 16;
#pragma unroll
        for (int i = 0; i < 4; i++) aoff[i] = (arow + i * 16) * TSTRIDE + acol;
        int brow = lane & 7;
        int bcol = ((lane >> 3) & 1) * 16;
#pragma unroll
        for (int j = 0; j < 4; j++) boff[j] = (wn * 32 + j * 8 + brow) * TSTRIDE + bcol;
    }

    cp_tile(sb + SM_A, g_qt4 + (size_t)qt * 2048, tid);
    cp_tile(sb + SM_B, g_bt4 + (size_t)(b * 8) * 2048, tid);
    CP_COMMIT();
    CP_WAIT0();
    __syncthreads();

    for (int it = 0; it < 8; it++) {
        const int stage = it & 1;
        if (it < 7) {
            cp_tile(sb + SM_B + (stage ^ 1) * TILE_BYTES_SM,
                    g_bt4 + (size_t)(b * 8 + it + 1) * 2048, tid);
            CP_COMMIT();
        }

        float acc[4][4][4];
#pragma unroll
        for (int i = 0; i < 4; i++)
#pragma unroll
            for (int j = 0; j < 4; j++)
#pragma unroll
                for (int r = 0; r < 4; r++) acc[i][j][r] = 0.0f;

        const uint32_t aB = sb + SM_A;
        const uint32_t bB = sb + SM_B + stage * TILE_BYTES_SM;

#pragma unroll
        for (int ks = 0; ks < 8; ks++) {
            uint32_t Af[4][4], Bf[4][2];
#pragma unroll
            for (int i = 0; i < 4; i++)
                LDSM_X4(Af[i][0], Af[i][1], Af[i][2], Af[i][3], aB + aoff[i] + ks * 32);
#pragma unroll
            for (int j = 0; j < 4; j++)
                LDSM_X2(Bf[j][0], Bf[j][1], bB + boff[j] + ks * 32);
#pragma unroll
            for (int i = 0; i < 4; i++)
#pragma unroll
                for (int j = 0; j < 4; j++)
                    MMA_FP16(acc[i][j], Af[i], Bf[j]);
        }

#pragma unroll
        for (int i = 0; i < 4; i++) {
            int q = q0 + wm * 64 + i * 16 + (lane >> 2);
            float* rowp = out + OD + (size_t)(b * (K_ + 1) + 1 + q) * S_;
#pragma unroll
            for (int j = 0; j < 4; j++) {
                int z = it * 128 + wn * 32 + j * 8 + 2 * (lane & 3);
                float2 w0 = {acc[i][j][0] * INV_TAU, acc[i][j][1] * INV_TAU};
                float2 w1 = {acc[i][j][2] * INV_TAU, acc[i][j][3] * INV_TAU};
                *reinterpret_cast<float2*>(rowp + z) = w0;
                *reinterpret_cast<float2*>(rowp + 8 * S_ + z) = w1;
            }
        }

        if (it < 7) CP_WAIT0();
        __syncthreads();
    }
}

// ---------------------------------------------------------------------------
extern "C" void kernel_launch(void* const* d_in, const int* in_sizes, int n_in,
                              void* d_out, int out_size) {
    const float* g_q     = (const float*)d_in[0];
    const float* g_k     = (const float*)d_in[1];
    const float* d_q     = (const float*)d_in[2];
    const float* d_k     = (const float*)d_in[3];
    const float* feat_q  = (const float*)d_in[4];
    const float* feat_k  = (const float*)d_in[5];
    const float* queue_g = (const float*)d_in[6];
    const float* queue_d = (const float*)d_in[7];
    float* out = (float*)d_out;

    cudaFuncSetAttribute(negd_mma_kernel,
                         cudaFuncAttributeMaxDynamicSharedMemorySize, SMEM_NEGD);
    cudaFuncSetAttribute(cos_mma_kernel,
                         cudaFuncAttributeMaxDynamicSharedMemorySize, SMEM_COS);

    // launch index 3 (ncu slot) = cos_mma_kernel
    norm_fk_kernel<<<dim3(S_ / 64, B_), 256>>>(feat_k);                 // 0
    fsplit_kernel<<<dim3(S_ / 32, C_ / 32, 16), dim3(32, 8)>>>(feat_q); // 1
    norm_g_kernel<<<dim3(2, B_), 128>>>(g_q, g_k);                      // 2
    cos_mma_kernel<<<dim3(8, 8, B_), 256, SMEM_COS>>>();                // 3
    finalize_kernel<<<32, 256>>>(feat_q);                               // 4
    norm_dq_kernel<<<dim3(S_ / 64, B_), 256>>>(d_q);                    // 5
    norm_dk_kernel<<<dim3(S_ / 64, B_), 256>>>(d_k);                    // 6
    gather_kernel<<<dim3(S_ / 256, B_), 256>>>(out);                    // 7
    btile_kernel<<<65536 / 256, 256>>>();                               // 8
    qconv_kernel<<<131072 / 256, 256>>>(queue_d);                       // 9
    outg_kernel<<<dim3(K_ / 128, B_), 128>>>(queue_g, out);             // 10
    negd_mma_kernel<<<dim3(128, B_), 256, SMEM_NEGD>>>(out);            // 11
}

// round 6
// speedup vs baseline: 2.2825x; 1.0784x over previous
#include <cuda_runtime.h>
#include <cuda_fp16.h>
#include <cstdint>

typedef unsigned long long u64;

// Problem constants
constexpr int B_ = 8;
constexpr int D_ = 128;
constexpr int S_ = 1024;
constexpr int C_ = 512;
constexpr int K_ = 16384;
constexpr float INV_TAU = 5.0f;

// Output layout (flattened concatenation, float32)
constexpr size_t OG = 0;
constexpr size_t TG = (size_t)B_ * (K_ + 1);
constexpr size_t OD = TG + B_;
constexpr size_t TD = OD + (size_t)B_ * (K_ + 1) * S_;

// Scratch (device globals; no allocation allowed)
__device__ float g_dqt[B_ * S_ * D_];   // normalized d_q, transposed [b][s][d]
__device__ float g_dkt[B_ * S_ * D_];   // normalized d_k, transposed [b][s][d]
__device__ float g_fkinv[B_ * S_];      // 1/||feat_k[:,i]||
__device__ float g_gqn[B_ * D_];
__device__ float g_gkn[B_ * D_];
__device__ u64   g_best[B_ * S_];       // final packed (ordered val, ~idx)
__device__ u64   g_top2[B_ * S_ * 16];  // per (col, itile): top-2 approx keys

// fp16 hi/lo transposed raw features: [b][s][c]
__device__ __half g_fkh[B_ * S_ * C_];
__device__ __half g_fkl[B_ * S_ * C_];
__device__ __half g_fqh[B_ * S_ * C_];
__device__ __half g_fql[B_ * S_ * C_];

// fp16 row-major tiles for negd: [tile][row(128)][d(128)]
__device__ uint4 g_qt4[128 * 2048];     // queue_d
__device__ uint4 g_bt4[64 * 2048];      // gathered d_q (8b x 8 z-tiles)

// ---------- helpers ----------
__device__ __forceinline__ unsigned ford(float f) {
    unsigned u = __float_as_uint(f);
    return (u & 0x80000000u) ? ~u : (u | 0x80000000u);
}
__device__ __forceinline__ float unford(unsigned x) {
    unsigned u = (x & 0x80000000u) ? (x & 0x7FFFFFFFu) : ~x;
    return __uint_as_float(u);
}
__device__ __forceinline__ u64 umax64(u64 a, u64 b) { return a > b ? a : b; }
__device__ __forceinline__ u64 umin64(u64 a, u64 b) { return a < b ? a : b; }

__device__ __forceinline__ uint32_t smem_to_u32(const void* p) {
    uint32_t a;
    asm("{ .reg .u64 t; cvta.to.shared.u64 t, %1; cvt.u32.u64 %0, t; }"
        : "=r"(a) : "l"(p));
    return a;
}
#define LDSM_X4(r0, r1, r2, r3, a) \
    asm volatile("ldmatrix.sync.aligned.m8n8.x4.shared.b16 {%0,%1,%2,%3}, [%4];" \
                 : "=r"(r0), "=r"(r1), "=r"(r2), "=r"(r3) : "r"(a))
#define MMA_FP16(c, a, b) \
    asm volatile("mma.sync.aligned.m16n8k16.row.col.f32.f16.f16.f32 " \
                 "{%0,%1,%2,%3}, {%4,%5,%6,%7}, {%8,%9}, {%0,%1,%2,%3};" \
                 : "+f"((c)[0]), "+f"((c)[1]), "+f"((c)[2]), "+f"((c)[3]) \
                 : "r"((a)[0]), "r"((a)[1]), "r"((a)[2]), "r"((a)[3]), \
                   "r"((b)[0]), "r"((b)[1]))
#define CP16(dst, src) \
    asm volatile("cp.async.cg.shared.global [%0], [%1], 16;" \
                 :: "r"(dst), "l"(src))
#define CP_COMMIT() asm volatile("cp.async.commit_group;")
#define CP_WAIT0()  asm volatile("cp.async.wait_group 0;" ::: "memory")

// ---------------------------------------------------------------------------
__global__ void norm_g_kernel(const float* __restrict__ gq,
                              const float* __restrict__ gk) {
    int b = blockIdx.y;
    const float* src = blockIdx.x ? gk : gq;
    float* dst = blockIdx.x ? g_gkn : g_gqn;
    int t = threadIdx.x;
    float v = src[b * D_ + t];
    __shared__ float sm[128];
    sm[t] = v * v;
    __syncthreads();
    for (int off = 64; off; off >>= 1) {
        if (t < off) sm[t] += sm[t + off];
        __syncthreads();
    }
    float sc = rsqrtf(fmaxf(sm[0], 1e-24f));
    dst[b * D_ + t] = v * sc;
}

// inv norms of feat_k columns (along C). grid (S/64, B), block 256.
__global__ void fknorm_kernel(const float* __restrict__ fk) {
    __shared__ float red[4][64];
    int b = blockIdx.y;
    int sl = threadIdx.x & 63;
    int g = threadIdx.x >> 6;
    int s = blockIdx.x * 64 + sl;
    const float* p = fk + (size_t)b * C_ * S_ + s;
    float ss = 0.0f;
#pragma unroll 8
    for (int c = g * 128; c < g * 128 + 128; c++) {
        float v = p[(size_t)c * S_];
        ss += v * v;
    }
    red[g][sl] = ss;
    __syncthreads();
    if (g == 0) {
        float tot = red[0][sl] + red[1][sl] + red[2][sl] + red[3][sl];
        g_fkinv[b * S_ + s] = rsqrtf(fmaxf(tot, 1e-24f));
    }
}

// Fused column-normalize (along D) + transpose [b][d][s] -> [b][s][d].
// Destination selected at COMPILE TIME in device code (device globals must
// never be passed as host-side kernel arguments). grid (S/32, B), block 256.
template <int WHICH>
__global__ void normt_kernel(const float* __restrict__ src) {
    float* dst = WHICH ? g_dkt : g_dqt;
    __shared__ float sm[32][129];     // [s_local][d]
    __shared__ float red[8][32];
    __shared__ float sinv[32];
    int b = blockIdx.y;
    int s0 = blockIdx.x * 32;
    int tid = threadIdx.x;
#pragma unroll
    for (int k = 0; k < 16; k++) {
        int idx = tid + k * 256;
        int d = idx >> 5, sl = idx & 31;
        sm[sl][d] = src[((size_t)b * D_ + d) * S_ + s0 + sl];
    }
    __syncthreads();
    {
        int sl = tid & 31, pp = tid >> 5;
        float ss = 0.0f;
#pragma unroll
        for (int d = pp * 16; d < pp * 16 + 16; d++) ss += sm[sl][d] * sm[sl][d];
        red[pp][sl] = ss;
    }
    __syncthreads();
    if (tid < 32) {
        float tot = 0.0f;
#pragma unroll
        for (int p = 0; p < 8; p++) tot += red[p][tid];
        sinv[tid] = rsqrtf(fmaxf(tot, 1e-24f));
    }
    __syncthreads();
#pragma unroll
    for (int k = 0; k < 16; k++) {
        int idx = tid + k * 256;
        int sl = idx >> 7, d = idx & 127;
        dst[((size_t)b * S_ + s0 + sl) * D_ + d] = sm[sl][d] * sinv[sl];
    }
}

// ---------------------------------------------------------------------------
// Transpose raw [b][c][s] -> [b][s][c] with fp16 hi/lo split.
// z<8: feat_k; z>=8: feat_q. grid (S/32, C/32, 16), block (32, 8).
__global__ void fsplit_kernel(const float* __restrict__ featq,
                              const float* __restrict__ featk) {
    __shared__ float tile[32][33];
    int z = blockIdx.z;
    bool isk = z < 8;
    int b = isk ? z : z - 8;
    const float* src = isk ? featk : featq;
    __half* dh = isk ? g_fkh : g_fqh;
    __half* dl = isk ? g_fkl : g_fql;
    int s0 = blockIdx.x * 32, c0 = blockIdx.y * 32;
#pragma unroll
    for (int r = 0; r < 4; r++) {
        int c = c0 + threadIdx.y * 4 + r;
        tile[threadIdx.y * 4 + r][threadIdx.x] =
            src[((size_t)b * C_ + c) * S_ + s0 + threadIdx.x];
    }
    __syncthreads();
#pragma unroll
    for (int r = 0; r < 4; r++) {
        int s = s0 + threadIdx.y * 4 + r;
        float v = tile[threadIdx.x][threadIdx.y * 4 + r];
        __half h = __float2half(v);
        __half l = __float2half(v - __half2float(h));
        size_t o = ((size_t)b * S_ + s) * C_ + c0 + threadIdx.x;
        dh[o] = h;
        dl[o] = l;
    }
}

// ---------------------------------------------------------------------------
// cosine via fp16 hi/lo 3-term mma on RAW features; epilogue scales by inv_i.
constexpr int XSTRIDE = 48;
constexpr int STG_A = 128 * XSTRIDE;        // 6144
constexpr int STG_BYTES = 4 * STG_A;        // 24576
constexpr int SMEM_COS = 2 * STG_BYTES;     // 49152

__global__ __launch_bounds__(256) void cos_mma_kernel() {
    extern __shared__ char smem[];
    __shared__ u64 smtop[2][4][32][2];
    __shared__ float sinv[128];
    const uint32_t sb = smem_to_u32(smem);
    const int tid = threadIdx.x;
    const int lane = tid & 31;
    const int wid = tid >> 5;
    const int wm = wid & 1;
    const int wn = wid >> 1;
    const int it = blockIdx.x, jt = blockIdx.y, b = blockIdx.z;
    const int i0 = it * 128, j0 = jt * 128;

    if (tid < 128) sinv[tid] = g_fkinv[b * S_ + i0 + tid];

    uint32_t aoff[4], b4off[2];
    {
        int arow = wm * 64 + ((lane >> 3) & 1) * 8 + (lane & 7);
        int acol = ((lane >> 4) & 1) * 16;
#pragma unroll
        for (int i = 0; i < 4; i++) aoff[i] = (arow + i * 16) * XSTRIDE + acol;
        int jsel = (lane >> 4) & 1;
        int kh = (lane >> 3) & 1;
        int brow = lane & 7;
#pragma unroll
        for (int jp = 0; jp < 2; jp++)
            b4off[jp] = (wn * 32 + (jp * 2 + jsel) * 8 + brow) * XSTRIDE + kh * 16;
    }

    const __half* srcs[4] = {g_fkh, g_fkl, g_fqh, g_fql};

    auto load_stage = [&](int st, int ks) {
        uint32_t base = sb + st * STG_BYTES;
#pragma unroll
        for (int k = 0; k < 4; k++) {
            int idx = tid + k * 256;
            int arr = idx >> 8;
            int r = (idx >> 1) & 127;
            int half = idx & 1;
            int row = ((arr < 2) ? i0 : j0) + r;
            const __half* s = srcs[arr] + ((size_t)(b * 1024 + row) * 512 + ks * 16 + half * 8);
            CP16(base + arr * STG_A + r * XSTRIDE + half * 16, s);
        }
    };

    float acc[4][4][4];
#pragma unroll
    for (int i = 0; i < 4; i++)
#pragma unroll
        for (int j = 0; j < 4; j++)
#pragma unroll
            for (int r = 0; r < 4; r++) acc[i][j][r] = 0.0f;

    load_stage(0, 0);
    CP_COMMIT();
    CP_WAIT0();
    __syncthreads();

    for (int ks = 0; ks < 32; ks++) {
        const int st = ks & 1;
        if (ks < 31) { load_stage(st ^ 1, ks + 1); CP_COMMIT(); }
        const uint32_t base = sb + st * STG_BYTES;
        uint32_t Ah[4][4], Al[4][4], Bh[4][2], Bl[4][2];
#pragma unroll
        for (int i = 0; i < 4; i++) {
            LDSM_X4(Ah[i][0], Ah[i][1], Ah[i][2], Ah[i][3], base + aoff[i]);
            LDSM_X4(Al[i][0], Al[i][1], Al[i][2], Al[i][3], base + STG_A + aoff[i]);
        }
#pragma unroll
        for (int jp = 0; jp < 2; jp++) {
            LDSM_X4(Bh[jp * 2][0], Bh[jp * 2][1], Bh[jp * 2 + 1][0], Bh[jp * 2 + 1][1],
                    base + 2 * STG_A + b4off[jp]);
            LDSM_X4(Bl[jp * 2][0], Bl[jp * 2][1], Bl[jp * 2 + 1][0], Bl[jp * 2 + 1][1],
                    base + 3 * STG_A + b4off[jp]);
        }
#pragma unroll
        for (int i = 0; i < 4; i++)
#pragma unroll
            for (int j = 0; j < 4; j++) {
                MMA_FP16(acc[i][j], Ah[i], Bh[j]);
                MMA_FP16(acc[i][j], Ah[i], Bl[j]);
                MMA_FP16(acc[i][j], Al[i], Bh[j]);
            }
        if (ks < 31) CP_WAIT0();
        __syncthreads();
    }

    float sA[4], sB[4];
#pragma unroll
    for (int i = 0; i < 4; i++) {
        int rl = wm * 64 + i * 16 + (lane >> 2);
        sA[i] = sinv[rl];
        sB[i] = sinv[rl + 8];
    }

    // top-2 over this CTA's 128 i per column j (on scaled values)
#pragma unroll
    for (int jf = 0; jf < 4; jf++) {
#pragma unroll
        for (int dj = 0; dj < 2; dj++) {
            u64 k1 = 0, k2 = 0;
#pragma unroll
            for (int i = 0; i < 4; i++) {
                unsigned ig = (unsigned)(i0 + wm * 64 + i * 16 + (lane >> 2));
                float v1 = acc[i][jf][dj] * sA[i];
                u64 key = ((u64)ford(v1) << 32) | (u64)(0xFFFFFFFFu - ig);
                if (key > k1) { k2 = k1; k1 = key; } else if (key > k2) k2 = key;
                float v2 = acc[i][jf][dj + 2] * sB[i];
                u64 key2 = ((u64)ford(v2) << 32) | (u64)(0xFFFFFFFFu - (ig + 8));
                if (key2 > k1) { k2 = k1; k1 = key2; } else if (key2 > k2) k2 = key2;
            }
#pragma unroll
            for (int m = 4; m <= 16; m <<= 1) {
                u64 o1 = __shfl_xor_sync(0xFFFFFFFFu, k1, m);
                u64 o2 = __shfl_xor_sync(0xFFFFFFFFu, k2, m);
                u64 n1 = umax64(k1, o1);
                u64 n2 = umax64(umin64(k1, o1), umax64(k2, o2));
                k1 = n1; k2 = n2;
            }
            if (lane < 4) {
                int j = jf * 8 + 2 * lane + dj;
                smtop[wm][wn][j][0] = k1;
                smtop[wm][wn][j][1] = k2;
            }
        }
    }
    __syncthreads();
    if (tid < 128) {
        int wn2 = tid >> 5, j = tid & 31;
        u64 a1 = smtop[0][wn2][j][0], a2 = smtop[0][wn2][j][1];
        u64 b1 = smtop[1][wn2][j][0], b2 = smtop[1][wn2][j][1];
        u64 k1 = umax64(a1, b1);
        u64 k2 = umax64(umin64(a1, b1), umax64(a2, b2));
        size_t col = (size_t)b * 1024 + j0 + wn2 * 32 + j;
        g_top2[col * 16 + it * 2] = k1;
        g_top2[col * 16 + it * 2 + 1] = k2;
    }
}

// ---------------------------------------------------------------------------
// finalize: provably-exact argmax (rescue in fp32 when margin ambiguous).
__global__ void finalize_kernel(const float* __restrict__ featq,
                                const float* __restrict__ featk) {
    int t = blockIdx.x * 256 + threadIdx.x;  // 8192 columns
    int b = t >> 10, j = t & 1023;
    u64 keys[16];
#pragma unroll
    for (int k = 0; k < 16; k++) keys[k] = g_top2[(size_t)t * 16 + k];
    u64 m1 = keys[0];
#pragma unroll
    for (int k = 1; k < 16; k++) m1 = umax64(m1, keys[k]);
    float vmax = unford((unsigned)(m1 >> 32));
    float thresh = vmax - 6e-3f;
    int cnt = 0;
#pragma unroll
    for (int k = 0; k < 16; k++)
        if (unford((unsigned)(keys[k] >> 32)) >= thresh) cnt++;
    u64 best = m1;
    if (cnt > 1) {
        float bv = -1e30f;
        unsigned bi = 0xFFFFFFFFu;
        for (int k = 0; k < 16; k++) {
            if (unford((unsigned)(keys[k] >> 32)) < thresh) continue;
            unsigned i = 0xFFFFFFFFu - (unsigned)(keys[k] & 0xFFFFFFFFull);
            const float* fk = featk + (size_t)b * C_ * S_ + i;
            const float* fq = featq + (size_t)b * C_ * S_ + j;
            float ex = 0.0f;
#pragma unroll 4
            for (int c = 0; c < C_; c++) ex += fk[(size_t)c * S_] * fq[(size_t)c * S_];
            ex *= g_fkinv[b * S_ + i];
            if (ex > bv || (ex == bv && i < bi)) { bv = ex; bi = i; }
        }
        best = ((u64)ford(bv) << 32) | (u64)(0xFFFFFFFFu - bi);
    }
    g_best[t] = best;
}

// ---------------------------------------------------------------------------
// pos_d + output_d row 0 + target_d. Warp per z, coalesced rows from dqt/dkt.
__global__ void gatherpos_kernel(float* __restrict__ out) {
    int b = blockIdx.y;
    int z = blockIdx.x * 8 + (threadIdx.x >> 5);
    int lane = threadIdx.x & 31;
    u64 key = g_best[b * S_ + z];
    int m = (int)(0xFFFFFFFFu - (unsigned)(key & 0xFFFFFFFFull));
    const float4* aq = (const float4*)(g_dqt + ((size_t)b * S_ + m) * D_);
    const float4* ak = (const float4*)(g_dkt + ((size_t)b * S_ + z) * D_);
    float4 x = aq[lane], y = ak[lane];
    float d = x.x * y.x + x.y * y.y + x.z * y.z + x.w * y.w;
#pragma unroll
    for (int off = 16; off; off >>= 1) d += __shfl_xor_sync(0xFFFFFFFFu, d, off);
    if (lane == 0) out[OD + (size_t)b * (K_ + 1) * S_ + z] = d * INV_TAU;
    if (lane == 1) out[TD + b * S_ + z] = 0.0f;
}

// fp16 row-major B tiles from gathered dqt rows. Warp per z.
__global__ void btile_kernel() {
    int b = blockIdx.y;
    int z = blockIdx.x * 8 + (threadIdx.x >> 5);
    int lane = threadIdx.x & 31;
    u64 key = g_best[b * S_ + z];
    int m = (int)(0xFFFFFFFFu - (unsigned)(key & 0xFFFFFFFFull));
    float4 v = ((const float4*)(g_dqt + ((size_t)b * S_ + m) * D_))[lane];
    __half h[4] = {__float2half(v.x), __float2half(v.y),
                   __float2half(v.z), __float2half(v.w)};
    uint2* bt2 = (uint2*)g_bt4;
    int zt = z >> 7, row = z & 127;
    uint2 packed;
    memcpy(&packed, h, 8);
    bt2[((size_t)((b * 8 + zt) * 128 + row)) * 32 + lane] = packed;
}

// Coalesced transpose of queue_d -> fp16 row-major tiles. grid 512, block 256.
__global__ void qconv_kernel(const float* __restrict__ queue_d) {
    __shared__ float sm[32][129];   // [q_local][d]
    int q0 = blockIdx.x * 32;
    int tid = threadIdx.x;
#pragma unroll
    for (int k = 0; k < 16; k++) {
        int idx = tid + k * 256;
        int d = idx >> 5, ql = idx & 31;
        sm[ql][d] = queue_d[(size_t)d * K_ + q0 + ql];
    }
    __syncthreads();
    uint2* qt2 = (uint2*)g_qt4;
    int qt = q0 >> 7;
#pragma unroll
    for (int k = 0; k < 4; k++) {
        int idx = tid + k * 256;
        int ql = idx >> 5, dg = idx & 31;
        __half h[4];
#pragma unroll
        for (int e = 0; e < 4; e++) h[e] = __float2half(sm[ql][dg * 4 + e]);
        int row = (q0 + ql) & 127;
        uint2 packed;
        memcpy(&packed, h, 8);
        qt2[((size_t)(qt * 128 + row)) * 32 + dg] = packed;
    }
}

// ---------------------------------------------------------------------------
// output_g (fp32 exact)
__global__ void outg_kernel(const float* __restrict__ queue_g, float* __restrict__ out) {
    int b = blockIdx.y;
    int t = threadIdx.x;
    int k = blockIdx.x * 128 + t;
    __shared__ float q[128];
    q[t] = g_gqn[b * D_ + t];
    __syncthreads();
    float acc = 0.0f;
#pragma unroll 16
    for (int d = 0; d < D_; d++) acc += q[d] * queue_g[(size_t)d * K_ + k];
    out[OG + (size_t)b * (K_ + 1) + 1 + k] = acc * INV_TAU;
    if (blockIdx.x == 0 && t == 0) {
        float p = 0.0f;
        for (int d = 0; d < D_; d++) p += g_gqn[b * D_ + d] * g_gkn[b * D_ + d];
        out[OG + (size_t)b * (K_ + 1)] = p * INV_TAU;
        out[TG + b] = 0.0f;
    }
}

// ---------------------------------------------------------------------------
// negd via single-pass fp16 mma. CTA = (q-tile 128, b), loops 8 z-tiles.
constexpr int TSTRIDE = 272;
constexpr int TILE_BYTES_SM = 128 * TSTRIDE;       // 34816
constexpr int SM_A = 0;
constexpr int SM_B = TILE_BYTES_SM;
constexpr int SMEM_NEGD = 3 * TILE_BYTES_SM;       // 104448 -> 2 CTAs/SM

__device__ __forceinline__ void cp_tile(uint32_t smDst, const uint4* src, int tid) {
#pragma unroll
    for (int k = 0; k < 8; k++) {
        int idx = tid + k * 256;
        int row = idx >> 4, w = idx & 15;
        CP16(smDst + row * TSTRIDE + w * 16, src + idx);
    }
}

__global__ __launch_bounds__(256) void negd_mma_kernel(float* __restrict__ out) {
    extern __shared__ char smem[];
    const uint32_t sb = smem_to_u32(smem);
    const int tid = threadIdx.x;
    const int lane = tid & 31;
    const int wid = tid >> 5;
    const int wm = wid & 1;
    const int wn = wid >> 1;
    const int qt = blockIdx.x;
    const int b = blockIdx.y;
    const int q0 = qt << 7;

    uint32_t aoff[4], b4off[2];
    {
        int arow = wm * 64 + ((lane >> 3) & 1) * 8 + (lane & 7);
        int acol = ((lane >> 4) & 1) * 16;
#pragma unroll
        for (int i = 0; i < 4; i++) aoff[i] = (arow + i * 16) * TSTRIDE + acol;
        int jsel = (lane >> 4) & 1;
        int kh = (lane >> 3) & 1;
        int brow = lane & 7;
#pragma unroll
        for (int jp = 0; jp < 2; jp++)
            b4off[jp] = (wn * 32 + (jp * 2 + jsel) * 8 + brow) * TSTRIDE + kh * 16;
    }

    cp_tile(sb + SM_A, g_qt4 + (size_t)qt * 2048, tid);
    cp_tile(sb + SM_B, g_bt4 + (size_t)(b * 8) * 2048, tid);
    CP_COMMIT();
    CP_WAIT0();
    __syncthreads();

    for (int it = 0; it < 8; it++) {
        const int stage = it & 1;
        if (it < 7) {
            cp_tile(sb + SM_B + (stage ^ 1) * TILE_BYTES_SM,
                    g_bt4 + (size_t)(b * 8 + it + 1) * 2048, tid);
            CP_COMMIT();
        }

        float acc[4][4][4];
#pragma unroll
        for (int i = 0; i < 4; i++)
#pragma unroll
            for (int j = 0; j < 4; j++)
#pragma unroll
                for (int r = 0; r < 4; r++) acc[i][j][r] = 0.0f;

        const uint32_t aB = sb + SM_A;
        const uint32_t bB = sb + SM_B + stage * TILE_BYTES_SM;

#pragma unroll
        for (int ks = 0; ks < 8; ks++) {
            uint32_t Af[4][4], Bf[4][2];
#pragma unroll
            for (int i = 0; i < 4; i++)
                LDSM_X4(Af[i][0], Af[i][1], Af[i][2], Af[i][3], aB + aoff[i] + ks * 32);
#pragma unroll
            for (int jp = 0; jp < 2; jp++)
                LDSM_X4(Bf[jp * 2][0], Bf[jp * 2][1], Bf[jp * 2 + 1][0], Bf[jp * 2 + 1][1],
                        bB + b4off[jp] + ks * 32);
#pragma unroll
            for (int i = 0; i < 4; i++)
#pragma unroll
                for (int j = 0; j < 4; j++)
                    MMA_FP16(acc[i][j], Af[i], Bf[j]);
        }

#pragma unroll
        for (int i = 0; i < 4; i++) {
            int q = q0 + wm * 64 + i * 16 + (lane >> 2);
            float* rowp = out + OD + (size_t)(b * (K_ + 1) + 1 + q) * S_;
#pragma unroll
            for (int j = 0; j < 4; j++) {
                int z = it * 128 + wn * 32 + j * 8 + 2 * (lane & 3);
                float2 w0 = {acc[i][j][0] * INV_TAU, acc[i][j][1] * INV_TAU};
                float2 w1 = {acc[i][j][2] * INV_TAU, acc[i][j][3] * INV_TAU};
                *reinterpret_cast<float2*>(rowp + z) = w0;
                *reinterpret_cast<float2*>(rowp + 8 * S_ + z) = w1;
            }
        }

        if (it < 7) CP_WAIT0();
        __syncthreads();
    }
}

// ---------------------------------------------------------------------------
extern "C" void kernel_launch(void* const* d_in, const int* in_sizes, int n_in,
                              void* d_out, int out_size) {
    const float* g_q     = (const float*)d_in[0];
    const float* g_k     = (const float*)d_in[1];
    const float* d_q     = (const float*)d_in[2];
    const float* d_k     = (const float*)d_in[3];
    const float* feat_q  = (const float*)d_in[4];
    const float* feat_k  = (const float*)d_in[5];
    const float* queue_g = (const float*)d_in[6];
    const float* queue_d = (const float*)d_in[7];
    float* out = (float*)d_out;

    cudaFuncSetAttribute(negd_mma_kernel,
                         cudaFuncAttributeMaxDynamicSharedMemorySize, SMEM_NEGD);
    cudaFuncSetAttribute(cos_mma_kernel,
                         cudaFuncAttributeMaxDynamicSharedMemorySize, SMEM_COS);

    fknorm_kernel<<<dim3(S_ / 64, B_), 256>>>(feat_k);                        // 0
    fsplit_kernel<<<dim3(S_ / 32, C_ / 32, 16), dim3(32, 8)>>>(feat_q, feat_k); // 1
    norm_g_kernel<<<dim3(2, B_), 128>>>(g_q, g_k);                            // 2
    cos_mma_kernel<<<dim3(8, 8, B_), 256, SMEM_COS>>>();                      // 3 (ncu slot)
    finalize_kernel<<<32, 256>>>(feat_q, feat_k);                             // 4
    normt_kernel<0><<<dim3(S_ / 32, B_), 256>>>(d_q);                         // 5
    normt_kernel<1><<<dim3(S_ / 32, B_), 256>>>(d_k);                         // 6
    gatherpos_kernel<<<dim3(S_ / 8, B_), 256>>>(out);                         // 7
    btile_kernel<<<dim3(S_ / 8, B_), 256>>>();                                // 8
    qconv_kernel<<<K_ / 32, 256>>>(queue_d);                                  // 9
    outg_kernel<<<dim3(K_ / 128, B_), 128>>>(queue_g, out);                   // 10
    negd_mma_kernel<<<dim3(128, B_), 256, SMEM_NEGD>>>(out);                  // 11
}

// round 7
// speedup vs baseline: 2.4702x; 1.0822x over previous
#include <cuda_runtime.h>
#include <cuda_fp16.h>
#include <cstdint>

typedef unsigned long long u64;

// Problem constants
constexpr int B_ = 8;
constexpr int D_ = 128;
constexpr int S_ = 1024;
constexpr int C_ = 512;
constexpr int K_ = 16384;
constexpr float INV_TAU = 5.0f;

// Output layout (flattened concatenation, float32)
constexpr size_t OG = 0;
constexpr size_t TG = (size_t)B_ * (K_ + 1);
constexpr size_t OD = TG + B_;
constexpr size_t TD = OD + (size_t)B_ * (K_ + 1) * S_;

// Scratch (device globals; no allocation allowed)
__device__ float g_dqt[B_ * S_ * D_];   // normalized d_q, transposed [b][s][d]
__device__ float g_dkt[B_ * S_ * D_];   // normalized d_k, transposed [b][s][d]
__device__ float g_fkinv[B_ * S_];      // 1/||feat_k[:,i]||
__device__ float g_gqn[B_ * D_];
__device__ float g_gkn[B_ * D_];
__device__ u64   g_best[B_ * S_];       // final packed (ordered val, ~idx)
__device__ u64   g_top4[B_ * S_ * 32];  // per (col, itile): top-4 approx keys

// fp16 transposed raw features: [b][s][c]
__device__ __half g_fkh[B_ * S_ * C_];
__device__ __half g_fqh[B_ * S_ * C_];

// fp16 row-major tiles for negd: [tile][row(128)][d(128)]
__device__ uint4 g_qt4[128 * 2048];     // queue_d
__device__ uint4 g_bt4[64 * 2048];      // gathered d_q (8b x 8 z-tiles)

// ---------- helpers ----------
__device__ __forceinline__ unsigned ford(float f) {
    unsigned u = __float_as_uint(f);
    return (u & 0x80000000u) ? ~u : (u | 0x80000000u);
}
__device__ __forceinline__ float unford(unsigned x) {
    unsigned u = (x & 0x80000000u) ? (x & 0x7FFFFFFFu) : ~x;
    return __uint_as_float(u);
}
__device__ __forceinline__ u64 umax64(u64 a, u64 b) { return a > b ? a : b; }

// sorted-descending top-4 insert
__device__ __forceinline__ void ins4(u64* t, u64 k) {
    if (k > t[0])      { t[3] = t[2]; t[2] = t[1]; t[1] = t[0]; t[0] = k; }
    else if (k > t[1]) { t[3] = t[2]; t[2] = t[1]; t[1] = k; }
    else if (k > t[2]) { t[3] = t[2]; t[2] = k; }
    else if (k > t[3]) { t[3] = k; }
}

__device__ __forceinline__ uint32_t smem_to_u32(const void* p) {
    uint32_t a;
    asm("{ .reg .u64 t; cvta.to.shared.u64 t, %1; cvt.u32.u64 %0, t; }"
        : "=r"(a) : "l"(p));
    return a;
}
#define LDSM_X4(r0, r1, r2, r3, a) \
    asm volatile("ldmatrix.sync.aligned.m8n8.x4.shared.b16 {%0,%1,%2,%3}, [%4];" \
                 : "=r"(r0), "=r"(r1), "=r"(r2), "=r"(r3) : "r"(a))
#define MMA_FP16(c, a, b) \
    asm volatile("mma.sync.aligned.m16n8k16.row.col.f32.f16.f16.f32 " \
                 "{%0,%1,%2,%3}, {%4,%5,%6,%7}, {%8,%9}, {%0,%1,%2,%3};" \
                 : "+f"((c)[0]), "+f"((c)[1]), "+f"((c)[2]), "+f"((c)[3]) \
                 : "r"((a)[0]), "r"((a)[1]), "r"((a)[2]), "r"((a)[3]), \
                   "r"((b)[0]), "r"((b)[1]))
#define CP16(dst, src) \
    asm volatile("cp.async.cg.shared.global [%0], [%1], 16;" \
                 :: "r"(dst), "l"(src))
#define CP_COMMIT() asm volatile("cp.async.commit_group;")
#define CP_WAIT0()  asm volatile("cp.async.wait_group 0;" ::: "memory")

// ---------------------------------------------------------------------------
__global__ void norm_g_kernel(const float* __restrict__ gq,
                              const float* __restrict__ gk) {
    int b = blockIdx.y;
    const float* src = blockIdx.x ? gk : gq;
    float* dst = blockIdx.x ? g_gkn : g_gqn;
    int t = threadIdx.x;
    float v = src[b * D_ + t];
    __shared__ float sm[128];
    sm[t] = v * v;
    __syncthreads();
    for (int off = 64; off; off >>= 1) {
        if (t < off) sm[t] += sm[t + off];
        __syncthreads();
    }
    float sc = rsqrtf(fmaxf(sm[0], 1e-24f));
    dst[b * D_ + t] = v * sc;
}

// inv norms of feat_k columns (along C). grid (S/64, B), block 256.
__global__ void fknorm_kernel(const float* __restrict__ fk) {
    __shared__ float red[4][64];
    int b = blockIdx.y;
    int sl = threadIdx.x & 63;
    int g = threadIdx.x >> 6;
    int s = blockIdx.x * 64 + sl;
    const float* p = fk + (size_t)b * C_ * S_ + s;
    float ss = 0.0f;
#pragma unroll 8
    for (int c = g * 128; c < g * 128 + 128; c++) {
        float v = p[(size_t)c * S_];
        ss += v * v;
    }
    red[g][sl] = ss;
    __syncthreads();
    if (g == 0) {
        float tot = red[0][sl] + red[1][sl] + red[2][sl] + red[3][sl];
        g_fkinv[b * S_ + s] = rsqrtf(fmaxf(tot, 1e-24f));
    }
}

// Fused column-normalize (along D) + transpose [b][d][s] -> [b][s][d].
// Destination selected at compile time in device code. grid (S/32, B), block 256.
template <int WHICH>
__global__ void normt_kernel(const float* __restrict__ src) {
    float* dst = WHICH ? g_dkt : g_dqt;
    __shared__ float sm[32][129];
    __shared__ float red[8][32];
    __shared__ float sinv[32];
    int b = blockIdx.y;
    int s0 = blockIdx.x * 32;
    int tid = threadIdx.x;
#pragma unroll
    for (int k = 0; k < 16; k++) {
        int idx = tid + k * 256;
        int d = idx >> 5, sl = idx & 31;
        sm[sl][d] = src[((size_t)b * D_ + d) * S_ + s0 + sl];
    }
    __syncthreads();
    {
        int sl = tid & 31, pp = tid >> 5;
        float ss = 0.0f;
#pragma unroll
        for (int d = pp * 16; d < pp * 16 + 16; d++) ss += sm[sl][d] * sm[sl][d];
        red[pp][sl] = ss;
    }
    __syncthreads();
    if (tid < 32) {
        float tot = 0.0f;
#pragma unroll
        for (int p = 0; p < 8; p++) tot += red[p][tid];
        sinv[tid] = rsqrtf(fmaxf(tot, 1e-24f));
    }
    __syncthreads();
#pragma unroll
    for (int k = 0; k < 16; k++) {
        int idx = tid + k * 256;
        int sl = idx >> 7, d = idx & 127;
        dst[((size_t)b * S_ + s0 + sl) * D_ + d] = sm[sl][d] * sinv[sl];
    }
}

// ---------------------------------------------------------------------------
// Transpose raw [b][c][s] -> [b][s][c], fp16 (hi only).
// z<8: feat_k; z>=8: feat_q. grid (S/32, C/32, 16), block (32, 8).
__global__ void fsplit_kernel(const float* __restrict__ featq,
                              const float* __restrict__ featk) {
    __shared__ float tile[32][33];
    int z = blockIdx.z;
    bool isk = z < 8;
    int b = isk ? z : z - 8;
    const float* src = isk ? featk : featq;
    __half* dh = isk ? g_fkh : g_fqh;
    int s0 = blockIdx.x * 32, c0 = blockIdx.y * 32;
#pragma unroll
    for (int r = 0; r < 4; r++) {
        int c = c0 + threadIdx.y * 4 + r;
        tile[threadIdx.y * 4 + r][threadIdx.x] =
            src[((size_t)b * C_ + c) * S_ + s0 + threadIdx.x];
    }
    __syncthreads();
#pragma unroll
    for (int r = 0; r < 4; r++) {
        int s = s0 + threadIdx.y * 4 + r;
        float v = tile[threadIdx.x][threadIdx.y * 4 + r];
        dh[((size_t)b * S_ + s) * C_ + c0 + threadIdx.x] = __float2half(v);
    }
}

// ---------------------------------------------------------------------------
// cosine via single-pass fp16 mma on RAW features; epilogue scales by inv_i
// and keeps top-4 per 128-i tile. k=32 per stage, double-buffered.
constexpr int XSTRIDE = 80;                 // 64B data + 16B pad
constexpr int STG_ARR = 128 * XSTRIDE;      // 10240
constexpr int STG_BYTES = 2 * STG_ARR;      // A + B = 20480
constexpr int SMEM_COS = 2 * STG_BYTES;     // 40960

__global__ __launch_bounds__(256) void cos_mma_kernel() {
    extern __shared__ char smem[];
    __shared__ u64 smtop[2][4][32][4];
    __shared__ float sinv[128];
    const uint32_t sb = smem_to_u32(smem);
    const int tid = threadIdx.x;
    const int lane = tid & 31;
    const int wid = tid >> 5;
    const int wm = wid & 1;
    const int wn = wid >> 1;
    const int it = blockIdx.x, jt = blockIdx.y, b = blockIdx.z;
    const int i0 = it * 128, j0 = jt * 128;

    if (tid < 128) sinv[tid] = g_fkinv[b * S_ + i0 + tid];

    uint32_t aoff[4], b4off[2];
    {
        int arow = wm * 64 + ((lane >> 3) & 1) * 8 + (lane & 7);
        int acol = ((lane >> 4) & 1) * 16;
#pragma unroll
        for (int i = 0; i < 4; i++) aoff[i] = (arow + i * 16) * XSTRIDE + acol;
        int jsel = (lane >> 4) & 1;
        int kh = (lane >> 3) & 1;
        int brow = lane & 7;
#pragma unroll
        for (int jp = 0; jp < 2; jp++)
            b4off[jp] = (wn * 32 + (jp * 2 + jsel) * 8 + brow) * XSTRIDE + kh * 16;
    }

    // stage loader: 2 arrays (A=fk rows i0.., B=fq rows j0..), 64B per row
    auto load_stage = [&](int st, int kc) {
        uint32_t base = sb + st * STG_BYTES;
#pragma unroll
        for (int k = 0; k < 4; k++) {
            int idx = tid + k * 256;
            int arr = idx >> 9;             // 0 = A(fk), 1 = B(fq)
            int rem = idx & 511;
            int r = rem >> 2;
            int quad = rem & 3;             // 16B chunk within 64B
            int row = (arr ? j0 : i0) + r;
            const __half* s = (arr ? g_fqh : g_fkh) +
                              ((size_t)(b * 1024 + row) * 512 + kc * 32 + quad * 8);
            CP16(base + arr * STG_ARR + r * XSTRIDE + quad * 16, s);
        }
    };

    float acc[4][4][4];
#pragma unroll
    for (int i = 0; i < 4; i++)
#pragma unroll
        for (int j = 0; j < 4; j++)
#pragma unroll
            for (int r = 0; r < 4; r++) acc[i][j][r] = 0.0f;

    load_stage(0, 0);
    CP_COMMIT();
    CP_WAIT0();
    __syncthreads();

    for (int kc = 0; kc < 16; kc++) {
        const int st = kc & 1;
        if (kc < 15) { load_stage(st ^ 1, kc + 1); CP_COMMIT(); }
        const uint32_t base = sb + st * STG_BYTES;
#pragma unroll
        for (int kh = 0; kh < 2; kh++) {
            uint32_t Af[4][4], Bf[4][2];
#pragma unroll
            for (int i = 0; i < 4; i++)
                LDSM_X4(Af[i][0], Af[i][1], Af[i][2], Af[i][3],
                        base + aoff[i] + kh * 32);
#pragma unroll
            for (int jp = 0; jp < 2; jp++)
                LDSM_X4(Bf[jp * 2][0], Bf[jp * 2][1], Bf[jp * 2 + 1][0], Bf[jp * 2 + 1][1],
                        base + STG_ARR + b4off[jp] + kh * 32);
#pragma unroll
            for (int i = 0; i < 4; i++)
#pragma unroll
                for (int j = 0; j < 4; j++)
                    MMA_FP16(acc[i][j], Af[i], Bf[j]);
        }
        if (kc < 15) CP_WAIT0();
        __syncthreads();
    }

    float sA[4], sB[4];
#pragma unroll
    for (int i = 0; i < 4; i++) {
        int rl = wm * 64 + i * 16 + (lane >> 2);
        sA[i] = sinv[rl];
        sB[i] = sinv[rl + 8];
    }

    // top-4 over this CTA's 128 i per column j (scaled values)
#pragma unroll
    for (int jf = 0; jf < 4; jf++) {
#pragma unroll
        for (int dj = 0; dj < 2; dj++) {
            u64 t[4] = {0, 0, 0, 0};
#pragma unroll
            for (int i = 0; i < 4; i++) {
                unsigned ig = (unsigned)(i0 + wm * 64 + i * 16 + (lane >> 2));
                ins4(t, ((u64)ford(acc[i][jf][dj] * sA[i]) << 32) |
                        (u64)(0xFFFFFFFFu - ig));
                ins4(t, ((u64)ford(acc[i][jf][dj + 2] * sB[i]) << 32) |
                        (u64)(0xFFFFFFFFu - (ig + 8)));
            }
#pragma unroll
            for (int m = 4; m <= 16; m <<= 1) {
                u64 o0 = __shfl_xor_sync(0xFFFFFFFFu, t[0], m);
                u64 o1 = __shfl_xor_sync(0xFFFFFFFFu, t[1], m);
                u64 o2 = __shfl_xor_sync(0xFFFFFFFFu, t[2], m);
                u64 o3 = __shfl_xor_sync(0xFFFFFFFFu, t[3], m);
                ins4(t, o0); ins4(t, o1); ins4(t, o2); ins4(t, o3);
            }
            if (lane < 4) {
                int j = jf * 8 + 2 * lane + dj;
#pragma unroll
                for (int e = 0; e < 4; e++) smtop[wm][wn][j][e] = t[e];
            }
        }
    }
    __syncthreads();
    if (tid < 128) {
        int wn2 = tid >> 5, j = tid & 31;
        u64 t[4];
#pragma unroll
        for (int e = 0; e < 4; e++) t[e] = smtop[0][wn2][j][e];
#pragma unroll
        for (int e = 0; e < 4; e++) ins4(t, smtop[1][wn2][j][e]);
        size_t col = (size_t)b * 1024 + j0 + wn2 * 32 + j;
#pragma unroll
        for (int e = 0; e < 4; e++) g_top4[col * 32 + it * 4 + e] = t[e];
    }
}

// ---------------------------------------------------------------------------
// finalize: exact argmax. Rescore in fp32 when margin ambiguous.
__global__ void finalize_kernel(const float* __restrict__ featq,
                                const float* __restrict__ featk) {
    int t = blockIdx.x * 256 + threadIdx.x;  // 8192 columns
    int b = t >> 10, j = t & 1023;
    const u64* keys = g_top4 + (size_t)t * 32;
    u64 m1 = 0;
#pragma unroll 8
    for (int k = 0; k < 32; k++) m1 = umax64(m1, keys[k]);
    float vmax = unford((unsigned)(m1 >> 32));
    float thresh = vmax - 1.2e-2f;
    int cnt = 0;
#pragma unroll 8
    for (int k = 0; k < 32; k++)
        if (unford((unsigned)(keys[k] >> 32)) >= thresh) cnt++;
    u64 best = m1;
    if (cnt > 1) {
        float bv = -1e30f;
        unsigned bi = 0xFFFFFFFFu;
        for (int k = 0; k < 32; k++) {
            if (unford((unsigned)(keys[k] >> 32)) < thresh) continue;
            unsigned i = 0xFFFFFFFFu - (unsigned)(keys[k] & 0xFFFFFFFFull);
            const float* fk = featk + (size_t)b * C_ * S_ + i;
            const float* fq = featq + (size_t)b * C_ * S_ + j;
            float ex = 0.0f;
#pragma unroll 4
            for (int c = 0; c < C_; c++) ex += fk[(size_t)c * S_] * fq[(size_t)c * S_];
            ex *= g_fkinv[b * S_ + i];
            if (ex > bv || (ex == bv && i < bi)) { bv = ex; bi = i; }
        }
        best = ((u64)ford(bv) << 32) | (u64)(0xFFFFFFFFu - bi);
    }
    g_best[t] = best;
}

// ---------------------------------------------------------------------------
// pos_d + output_d row 0 + target_d. Warp per z, coalesced rows from dqt/dkt.
__global__ void gatherpos_kernel(float* __restrict__ out) {
    int b = blockIdx.y;
    int z = blockIdx.x * 8 + (threadIdx.x >> 5);
    int lane = threadIdx.x & 31;
    u64 key = g_best[b * S_ + z];
    int m = (int)(0xFFFFFFFFu - (unsigned)(key & 0xFFFFFFFFull));
    const float4* aq = (const float4*)(g_dqt + ((size_t)b * S_ + m) * D_);
    const float4* ak = (const float4*)(g_dkt + ((size_t)b * S_ + z) * D_);
    float4 x = aq[lane], y = ak[lane];
    float d = x.x * y.x + x.y * y.y + x.z * y.z + x.w * y.w;
#pragma unroll
    for (int off = 16; off; off >>= 1) d += __shfl_xor_sync(0xFFFFFFFFu, d, off);
    if (lane == 0) out[OD + (size_t)b * (K_ + 1) * S_ + z] = d * INV_TAU;
    if (lane == 1) out[TD + b * S_ + z] = 0.0f;
}

// fp16 row-major B tiles from gathered dqt rows. Warp per z.
__global__ void btile_kernel() {
    int b = blockIdx.y;
    int z = blockIdx.x * 8 + (threadIdx.x >> 5);
    int lane = threadIdx.x & 31;
    u64 key = g_best[b * S_ + z];
    int m = (int)(0xFFFFFFFFu - (unsigned)(key & 0xFFFFFFFFull));
    float4 v = ((const float4*)(g_dqt + ((size_t)b * S_ + m) * D_))[lane];
    __half h[4] = {__float2half(v.x), __float2half(v.y),
                   __float2half(v.z), __float2half(v.w)};
    uint2* bt2 = (uint2*)g_bt4;
    int zt = z >> 7, row = z & 127;
    uint2 packed;
    memcpy(&packed, h, 8);
    bt2[((size_t)((b * 8 + zt) * 128 + row)) * 32 + lane] = packed;
}

// Coalesced transpose of queue_d -> fp16 row-major tiles. grid 512, block 256.
__global__ void qconv_kernel(const float* __restrict__ queue_d) {
    __shared__ float sm[32][129];
    int q0 = blockIdx.x * 32;
    int tid = threadIdx.x;
#pragma unroll
    for (int k = 0; k < 16; k++) {
        int idx = tid + k * 256;
        int d = idx >> 5, ql = idx & 31;
        sm[ql][d] = queue_d[(size_t)d * K_ + q0 + ql];
    }
    __syncthreads();
    uint2* qt2 = (uint2*)g_qt4;
    int qt = q0 >> 7;
#pragma unroll
    for (int k = 0; k < 4; k++) {
        int idx = tid + k * 256;
        int ql = idx >> 5, dg = idx & 31;
        __half h[4];
#pragma unroll
        for (int e = 0; e < 4; e++) h[e] = __float2half(sm[ql][dg * 4 + e]);
        int row = (q0 + ql) & 127;
        uint2 packed;
        memcpy(&packed, h, 8);
        qt2[((size_t)(qt * 128 + row)) * 32 + dg] = packed;
    }
}

// ---------------------------------------------------------------------------
// output_g (fp32 exact)
__global__ void outg_kernel(const float* __restrict__ queue_g, float* __restrict__ out) {
    int b = blockIdx.y;
    int t = threadIdx.x;
    int k = blockIdx.x * 128 + t;
    __shared__ float q[128];
    q[t] = g_gqn[b * D_ + t];
    __syncthreads();
    float acc = 0.0f;
#pragma unroll 16
    for (int d = 0; d < D_; d++) acc += q[d] * queue_g[(size_t)d * K_ + k];
    out[OG + (size_t)b * (K_ + 1) + 1 + k] = acc * INV_TAU;
    if (blockIdx.x == 0 && t == 0) {
        float p = 0.0f;
        for (int d = 0; d < D_; d++) p += g_gqn[b * D_ + d] * g_gkn[b * D_ + d];
        out[OG + (size_t)b * (K_ + 1)] = p * INV_TAU;
        out[TG + b] = 0.0f;
    }
}

// ---------------------------------------------------------------------------
// negd via single-pass fp16 mma. CTA = (q-tile 128, b), loops 8 z-tiles.
constexpr int TSTRIDE = 272;
constexpr int TILE_BYTES_SM = 128 * TSTRIDE;       // 34816
constexpr int SM_A = 0;
constexpr int SM_B = TILE_BYTES_SM;
constexpr int SMEM_NEGD = 3 * TILE_BYTES_SM;       // 104448 -> 2 CTAs/SM

__device__ __forceinline__ void cp_tile(uint32_t smDst, const uint4* src, int tid) {
#pragma unroll
    for (int k = 0; k < 8; k++) {
        int idx = tid + k * 256;
        int row = idx >> 4, w = idx & 15;
        CP16(smDst + row * TSTRIDE + w * 16, src + idx);
    }
}

__global__ __launch_bounds__(256) void negd_mma_kernel(float* __restrict__ out) {
    extern __shared__ char smem[];
    const uint32_t sb = smem_to_u32(smem);
    const int tid = threadIdx.x;
    const int lane = tid & 31;
    const int wid = tid >> 5;
    const int wm = wid & 1;
    const int wn = wid >> 1;
    const int qt = blockIdx.x;
    const int b = blockIdx.y;
    const int q0 = qt << 7;

    uint32_t aoff[4], b4off[2];
    {
        int arow = wm * 64 + ((lane >> 3) & 1) * 8 + (lane & 7);
        int acol = ((lane >> 4) & 1) * 16;
#pragma unroll
        for (int i = 0; i < 4; i++) aoff[i] = (arow + i * 16) * TSTRIDE + acol;
        int jsel = (lane >> 4) & 1;
        int kh = (lane >> 3) & 1;
        int brow = lane & 7;
#pragma unroll
        for (int jp = 0; jp < 2; jp++)
            b4off[jp] = (wn * 32 + (jp * 2 + jsel) * 8 + brow) * TSTRIDE + kh * 16;
    }

    cp_tile(sb + SM_A, g_qt4 + (size_t)qt * 2048, tid);
    cp_tile(sb + SM_B, g_bt4 + (size_t)(b * 8) * 2048, tid);
    CP_COMMIT();
    CP_WAIT0();
    __syncthreads();

    for (int it = 0; it < 8; it++) {
        const int stage = it & 1;
        if (it < 7) {
            cp_tile(sb + SM_B + (stage ^ 1) * TILE_BYTES_SM,
                    g_bt4 + (size_t)(b * 8 + it + 1) * 2048, tid);
            CP_COMMIT();
        }

        float acc[4][4][4];
#pragma unroll
        for (int i = 0; i < 4; i++)
#pragma unroll
            for (int j = 0; j < 4; j++)
#pragma unroll
                for (int r = 0; r < 4; r++) acc[i][j][r] = 0.0f;

        const uint32_t aB = sb + SM_A;
        const uint32_t bB = sb + SM_B + stage * TILE_BYTES_SM;

#pragma unroll
        for (int ks = 0; ks < 8; ks++) {
            uint32_t Af[4][4], Bf[4][2];
#pragma unroll
            for (int i = 0; i < 4; i++)
                LDSM_X4(Af[i][0], Af[i][1], Af[i][2], Af[i][3], aB + aoff[i] + ks * 32);
#pragma unroll
            for (int jp = 0; jp < 2; jp++)
                LDSM_X4(Bf[jp * 2][0], Bf[jp * 2][1], Bf[jp * 2 + 1][0], Bf[jp * 2 + 1][1],
                        bB + b4off[jp] + ks * 32);
#pragma unroll
            for (int i = 0; i < 4; i++)
#pragma unroll
                for (int j = 0; j < 4; j++)
                    MMA_FP16(acc[i][j], Af[i], Bf[j]);
        }

#pragma unroll
        for (int i = 0; i < 4; i++) {
            int q = q0 + wm * 64 + i * 16 + (lane >> 2);
            float* rowp = out + OD + (size_t)(b * (K_ + 1) + 1 + q) * S_;
#pragma unroll
            for (int j = 0; j < 4; j++) {
                int z = it * 128 + wn * 32 + j * 8 + 2 * (lane & 3);
                float2 w0 = {acc[i][j][0] * INV_TAU, acc[i][j][1] * INV_TAU};
                float2 w1 = {acc[i][j][2] * INV_TAU, acc[i][j][3] * INV_TAU};
                *reinterpret_cast<float2*>(rowp + z) = w0;
                *reinterpret_cast<float2*>(rowp + 8 * S_ + z) = w1;
            }
        }

        if (it < 7) CP_WAIT0();
        __syncthreads();
    }
}

// ---------------------------------------------------------------------------
extern "C" void kernel_launch(void* const* d_in, const int* in_sizes, int n_in,
                              void* d_out, int out_size) {
    const float* g_q     = (const float*)d_in[0];
    const float* g_k     = (const float*)d_in[1];
    const float* d_q     = (const float*)d_in[2];
    const float* d_k     = (const float*)d_in[3];
    const float* feat_q  = (const float*)d_in[4];
    const float* feat_k  = (const float*)d_in[5];
    const float* queue_g = (const float*)d_in[6];
    const float* queue_d = (const float*)d_in[7];
    float* out = (float*)d_out;

    cudaFuncSetAttribute(negd_mma_kernel,
                         cudaFuncAttributeMaxDynamicSharedMemorySize, SMEM_NEGD);
    cudaFuncSetAttribute(cos_mma_kernel,
                         cudaFuncAttributeMaxDynamicSharedMemorySize, SMEM_COS);

    fknorm_kernel<<<dim3(S_ / 64, B_), 256>>>(feat_k);                          // 0
    fsplit_kernel<<<dim3(S_ / 32, C_ / 32, 16), dim3(32, 8)>>>(feat_q, feat_k); // 1
    norm_g_kernel<<<dim3(2, B_), 128>>>(g_q, g_k);                              // 2
    cos_mma_kernel<<<dim3(8, 8, B_), 256, SMEM_COS>>>();                        // 3 (ncu slot)
    finalize_kernel<<<32, 256>>>(feat_q, feat_k);                               // 4
    normt_kernel<0><<<dim3(S_ / 32, B_), 256>>>(d_q);                           // 5
    normt_kernel<1><<<dim3(S_ / 32, B_), 256>>>(d_k);                           // 6
    gatherpos_kernel<<<dim3(S_ / 8, B_), 256>>>(out);                           // 7
    btile_kernel<<<dim3(S_ / 8, B_), 256>>>();                                  // 8
    qconv_kernel<<<K_ / 32, 256>>>(queue_d);                                    // 9
    outg_kernel<<<dim3(K_ / 128, B_), 128>>>(queue_g, out);                     // 10
    negd_mma_kernel<<<dim3(128, B_), 256, SMEM_NEGD>>>(out);                    // 11
}

// round 8
// speedup vs baseline: 2.9349x; 1.1881x over previous
#include <cuda_runtime.h>
#include <cuda_fp16.h>
#include <cstdint>

typedef unsigned long long u64;

// Problem constants
constexpr int B_ = 8;
constexpr int D_ = 128;
constexpr int S_ = 1024;
constexpr int C_ = 512;
constexpr int K_ = 16384;
constexpr float INV_TAU = 5.0f;
constexpr float MARGIN = 3e-3f;

// Output layout (flattened concatenation, float32)
constexpr size_t OG = 0;
constexpr size_t TG = (size_t)B_ * (K_ + 1);
constexpr size_t OD = TG + B_;
constexpr size_t TD = OD + (size_t)B_ * (K_ + 1) * S_;

// Scratch (device globals; no allocation allowed)
__device__ float g_dqt[B_ * S_ * D_];   // normalized d_q, transposed [b][s][d]
__device__ float g_dkt[B_ * S_ * D_];   // normalized d_k, transposed [b][s][d]
__device__ float g_fkinv[B_ * S_];      // 1/||feat_k[:,i]||
__device__ float g_gqn[B_ * D_];
__device__ float g_gkn[B_ * D_];
__device__ u64   g_best[B_ * S_];       // final packed (ordered val, ~idx)
__device__ u64   g_top4[B_ * S_ * 32];  // per (col, itile): top-4 approx keys

// fp16 transposed raw features: [b][s][c]
__device__ __half g_fkh[B_ * S_ * C_];
__device__ __half g_fqh[B_ * S_ * C_];

// fp16 row-major tiles for negd: [tile][row(128)][d(128)]
__device__ uint4 g_qt4[128 * 2048];     // queue_d
__device__ uint4 g_bt4[64 * 2048];      // gathered d_q (8b x 8 z-tiles)

// ---------- helpers ----------
__device__ __forceinline__ unsigned ford(float f) {
    unsigned u = __float_as_uint(f);
    return (u & 0x80000000u) ? ~u : (u | 0x80000000u);
}
__device__ __forceinline__ float unford(unsigned x) {
    unsigned u = (x & 0x80000000u) ? (x & 0x7FFFFFFFu) : ~x;
    return __uint_as_float(u);
}
__device__ __forceinline__ u64 umax64(u64 a, u64 b) { return a > b ? a : b; }

// sorted-descending top-4 insert
__device__ __forceinline__ void ins4(u64* t, u64 k) {
    if (k > t[0])      { t[3] = t[2]; t[2] = t[1]; t[1] = t[0]; t[0] = k; }
    else if (k > t[1]) { t[3] = t[2]; t[2] = t[1]; t[1] = k; }
    else if (k > t[2]) { t[3] = t[2]; t[2] = k; }
    else if (k > t[3]) { t[3] = k; }
}

__device__ __forceinline__ uint32_t smem_to_u32(const void* p) {
    uint32_t a;
    asm("{ .reg .u64 t; cvta.to.shared.u64 t, %1; cvt.u32.u64 %0, t; }"
        : "=r"(a) : "l"(p));
    return a;
}
#define LDSM_X4(r0, r1, r2, r3, a) \
    asm volatile("ldmatrix.sync.aligned.m8n8.x4.shared.b16 {%0,%1,%2,%3}, [%4];" \
                 : "=r"(r0), "=r"(r1), "=r"(r2), "=r"(r3) : "r"(a))
#define MMA_FP16(c, a, b) \
    asm volatile("mma.sync.aligned.m16n8k16.row.col.f32.f16.f16.f32 " \
                 "{%0,%1,%2,%3}, {%4,%5,%6,%7}, {%8,%9}, {%0,%1,%2,%3};" \
                 : "+f"((c)[0]), "+f"((c)[1]), "+f"((c)[2]), "+f"((c)[3]) \
                 : "r"((a)[0]), "r"((a)[1]), "r"((a)[2]), "r"((a)[3]), \
                   "r"((b)[0]), "r"((b)[1]))
#define CP16(dst, src) \
    asm volatile("cp.async.cg.shared.global [%0], [%1], 16;" \
                 :: "r"(dst), "l"(src))
#define CP_COMMIT() asm volatile("cp.async.commit_group;")
#define CP_WAIT0()  asm volatile("cp.async.wait_group 0;" ::: "memory")

// ---------------------------------------------------------------------------
__global__ void norm_g_kernel(const float* __restrict__ gq,
                              const float* __restrict__ gk) {
    int b = blockIdx.y;
    const float* src = blockIdx.x ? gk : gq;
    float* dst = blockIdx.x ? g_gkn : g_gqn;
    int t = threadIdx.x;
    float v = src[b * D_ + t];
    __shared__ float sm[128];
    sm[t] = v * v;
    __syncthreads();
    for (int off = 64; off; off >>= 1) {
        if (t < off) sm[t] += sm[t + off];
        __syncthreads();
    }
    float sc = rsqrtf(fmaxf(sm[0], 1e-24f));
    dst[b * D_ + t] = v * sc;
}

// inv norms of feat_k columns (along C). grid (S/64, B), block 256.
__global__ void fknorm_kernel(const float* __restrict__ fk) {
    __shared__ float red[4][64];
    int b = blockIdx.y;
    int sl = threadIdx.x & 63;
    int g = threadIdx.x >> 6;
    int s = blockIdx.x * 64 + sl;
    const float* p = fk + (size_t)b * C_ * S_ + s;
    float ss = 0.0f;
#pragma unroll 8
    for (int c = g * 128; c < g * 128 + 128; c++) {
        float v = p[(size_t)c * S_];
        ss += v * v;
    }
    red[g][sl] = ss;
    __syncthreads();
    if (g == 0) {
        float tot = red[0][sl] + red[1][sl] + red[2][sl] + red[3][sl];
        g_fkinv[b * S_ + s] = rsqrtf(fmaxf(tot, 1e-24f));
    }
}

// Fused column-normalize (along D) + transpose [b][d][s] -> [b][s][d].
// blockIdx.z selects d_q / d_k (device-side global selection).
// grid (S/32, B, 2), block 256.
__global__ void normt_kernel(const float* __restrict__ dq,
                             const float* __restrict__ dk) {
    const float* src = blockIdx.z ? dk : dq;
    float* dst = blockIdx.z ? g_dkt : g_dqt;
    __shared__ float sm[32][129];
    __shared__ float red[8][32];
    __shared__ float sinv[32];
    int b = blockIdx.y;
    int s0 = blockIdx.x * 32;
    int tid = threadIdx.x;
#pragma unroll
    for (int k = 0; k < 16; k++) {
        int idx = tid + k * 256;
        int d = idx >> 5, sl = idx & 31;
        sm[sl][d] = src[((size_t)b * D_ + d) * S_ + s0 + sl];
    }
    __syncthreads();
    {
        int sl = tid & 31, pp = tid >> 5;
        float ss = 0.0f;
#pragma unroll
        for (int d = pp * 16; d < pp * 16 + 16; d++) ss += sm[sl][d] * sm[sl][d];
        red[pp][sl] = ss;
    }
    __syncthreads();
    if (tid < 32) {
        float tot = 0.0f;
#pragma unroll
        for (int p = 0; p < 8; p++) tot += red[p][tid];
        sinv[tid] = rsqrtf(fmaxf(tot, 1e-24f));
    }
    __syncthreads();
#pragma unroll
    for (int k = 0; k < 16; k++) {
        int idx = tid + k * 256;
        int sl = idx >> 7, d = idx & 127;
        dst[((size_t)b * S_ + s0 + sl) * D_ + d] = sm[sl][d] * sinv[sl];
    }
}

// ---------------------------------------------------------------------------
// Transpose raw [b][c][s] -> [b][s][c], fp16.
// z<8: feat_k; z>=8: feat_q. grid (S/32, C/32, 16), block (32, 8).
__global__ void fsplit_kernel(const float* __restrict__ featq,
                              const float* __restrict__ featk) {
    __shared__ float tile[32][33];
    int z = blockIdx.z;
    bool isk = z < 8;
    int b = isk ? z : z - 8;
    const float* src = isk ? featk : featq;
    __half* dh = isk ? g_fkh : g_fqh;
    int s0 = blockIdx.x * 32, c0 = blockIdx.y * 32;
#pragma unroll
    for (int r = 0; r < 4; r++) {
        int c = c0 + threadIdx.y * 4 + r;
        tile[threadIdx.y * 4 + r][threadIdx.x] =
            src[((size_t)b * C_ + c) * S_ + s0 + threadIdx.x];
    }
    __syncthreads();
#pragma unroll
    for (int r = 0; r < 4; r++) {
        int s = s0 + threadIdx.y * 4 + r;
        float v = tile[threadIdx.x][threadIdx.y * 4 + r];
        dh[((size_t)b * S_ + s) * C_ + c0 + threadIdx.x] = __float2half(v);
    }
}

// ---------------------------------------------------------------------------
// cosine via single-pass fp16 mma on RAW features; epilogue scales by inv_i
// and keeps top-4 per 128-i tile. k=32 per stage, double-buffered.
constexpr int XSTRIDE = 80;                 // 64B data + 16B pad
constexpr int STG_ARR = 128 * XSTRIDE;      // 10240
constexpr int STG_BYTES = 2 * STG_ARR;      // A + B = 20480
constexpr int SMEM_COS = 2 * STG_BYTES;     // 40960

__global__ __launch_bounds__(256) void cos_mma_kernel() {
    extern __shared__ char smem[];
    __shared__ u64 smtop[2][4][32][4];
    __shared__ float sinv[128];
    const uint32_t sb = smem_to_u32(smem);
    const int tid = threadIdx.x;
    const int lane = tid & 31;
    const int wid = tid >> 5;
    const int wm = wid & 1;
    const int wn = wid >> 1;
    const int it = blockIdx.x, jt = blockIdx.y, b = blockIdx.z;
    const int i0 = it * 128, j0 = jt * 128;

    if (tid < 128) sinv[tid] = g_fkinv[b * S_ + i0 + tid];

    uint32_t aoff[4], b4off[2];
    {
        int arow = wm * 64 + ((lane >> 3) & 1) * 8 + (lane & 7);
        int acol = ((lane >> 4) & 1) * 16;
#pragma unroll
        for (int i = 0; i < 4; i++) aoff[i] = (arow + i * 16) * XSTRIDE + acol;
        int jsel = (lane >> 4) & 1;
        int kh = (lane >> 3) & 1;
        int brow = lane & 7;
#pragma unroll
        for (int jp = 0; jp < 2; jp++)
            b4off[jp] = (wn * 32 + (jp * 2 + jsel) * 8 + brow) * XSTRIDE + kh * 16;
    }

    auto load_stage = [&](int st, int kc) {
        uint32_t base = sb + st * STG_BYTES;
#pragma unroll
        for (int k = 0; k < 4; k++) {
            int idx = tid + k * 256;
            int arr = idx >> 9;             // 0 = A(fk), 1 = B(fq)
            int rem = idx & 511;
            int r = rem >> 2;
            int quad = rem & 3;
            int row = (arr ? j0 : i0) + r;
            const __half* s = (arr ? g_fqh : g_fkh) +
                              ((size_t)(b * 1024 + row) * 512 + kc * 32 + quad * 8);
            CP16(base + arr * STG_ARR + r * XSTRIDE + quad * 16, s);
        }
    };

    float acc[4][4][4];
#pragma unroll
    for (int i = 0; i < 4; i++)
#pragma unroll
        for (int j = 0; j < 4; j++)
#pragma unroll
            for (int r = 0; r < 4; r++) acc[i][j][r] = 0.0f;

    load_stage(0, 0);
    CP_COMMIT();
    CP_WAIT0();
    __syncthreads();

    for (int kc = 0; kc < 16; kc++) {
        const int st = kc & 1;
        if (kc < 15) { load_stage(st ^ 1, kc + 1); CP_COMMIT(); }
        const uint32_t base = sb + st * STG_BYTES;
#pragma unroll
        for (int kh = 0; kh < 2; kh++) {
            uint32_t Af[4][4], Bf[4][2];
#pragma unroll
            for (int i = 0; i < 4; i++)
                LDSM_X4(Af[i][0], Af[i][1], Af[i][2], Af[i][3],
                        base + aoff[i] + kh * 32);
#pragma unroll
            for (int jp = 0; jp < 2; jp++)
                LDSM_X4(Bf[jp * 2][0], Bf[jp * 2][1], Bf[jp * 2 + 1][0], Bf[jp * 2 + 1][1],
                        base + STG_ARR + b4off[jp] + kh * 32);
#pragma unroll
            for (int i = 0; i < 4; i++)
#pragma unroll
                for (int j = 0; j < 4; j++)
                    MMA_FP16(acc[i][j], Af[i], Bf[j]);
        }
        if (kc < 15) CP_WAIT0();
        __syncthreads();
    }

    float sA[4], sB[4];
#pragma unroll
    for (int i = 0; i < 4; i++) {
        int rl = wm * 64 + i * 16 + (lane >> 2);
        sA[i] = sinv[rl];
        sB[i] = sinv[rl + 8];
    }

    // top-4 over this CTA's 128 i per column j (scaled values)
#pragma unroll
    for (int jf = 0; jf < 4; jf++) {
#pragma unroll
        for (int dj = 0; dj < 2; dj++) {
            u64 t[4] = {0, 0, 0, 0};
#pragma unroll
            for (int i = 0; i < 4; i++) {
                unsigned ig = (unsigned)(i0 + wm * 64 + i * 16 + (lane >> 2));
                ins4(t, ((u64)ford(acc[i][jf][dj] * sA[i]) << 32) |
                        (u64)(0xFFFFFFFFu - ig));
                ins4(t, ((u64)ford(acc[i][jf][dj + 2] * sB[i]) << 32) |
                        (u64)(0xFFFFFFFFu - (ig + 8)));
            }
#pragma unroll
            for (int m = 4; m <= 16; m <<= 1) {
                u64 o0 = __shfl_xor_sync(0xFFFFFFFFu, t[0], m);
                u64 o1 = __shfl_xor_sync(0xFFFFFFFFu, t[1], m);
                u64 o2 = __shfl_xor_sync(0xFFFFFFFFu, t[2], m);
                u64 o3 = __shfl_xor_sync(0xFFFFFFFFu, t[3], m);
                ins4(t, o0); ins4(t, o1); ins4(t, o2); ins4(t, o3);
            }
            if (lane < 4) {
                int j = jf * 8 + 2 * lane + dj;
#pragma unroll
                for (int e = 0; e < 4; e++) smtop[wm][wn][j][e] = t[e];
            }
        }
    }
    __syncthreads();
    if (tid < 128) {
        int wn2 = tid >> 5, j = tid & 31;
        u64 t[4];
#pragma unroll
        for (int e = 0; e < 4; e++) t[e] = smtop[0][wn2][j][e];
#pragma unroll
        for (int e = 0; e < 4; e++) ins4(t, smtop[1][wn2][j][e]);
        size_t col = (size_t)b * 1024 + j0 + wn2 * 32 + j;
#pragma unroll
        for (int e = 0; e < 4; e++) g_top4[col * 32 + it * 4 + e] = t[e];
    }
}

// ---------------------------------------------------------------------------
// finalize: warp per column. Warp-max + ballot margin test; cooperative fp32
// rescore only for ambiguous columns. grid 1024 x block 256 (8 warps).
__global__ void finalize_kernel(const float* __restrict__ featq,
                                const float* __restrict__ featk) {
    int col = blockIdx.x * 8 + (threadIdx.x >> 5);
    int lane = threadIdx.x & 31;
    int b = col >> 10, j = col & 1023;
    u64 key = g_top4[(size_t)col * 32 + lane];
    u64 m = key;
#pragma unroll
    for (int off = 16; off; off >>= 1)
        m = umax64(m, __shfl_xor_sync(0xFFFFFFFFu, m, off));
    float vmax = unford((unsigned)(m >> 32));
    bool pass = unford((unsigned)(key >> 32)) >= vmax - MARGIN;
    unsigned mask = __ballot_sync(0xFFFFFFFFu, pass);
    u64 best = m;
    if (__popc(mask) > 1) {
        float bv = -1e30f;
        unsigned bi = 0xFFFFFFFFu;
        unsigned rem = mask;
        while (rem) {
            int c = __ffs(rem) - 1;
            rem &= rem - 1;
            unsigned i = 0xFFFFFFFFu -
                         (unsigned)(__shfl_sync(0xFFFFFFFFu, key, c) & 0xFFFFFFFFull);
            const float* fk = featk + (size_t)b * C_ * S_ + i;
            const float* fq = featq + (size_t)b * C_ * S_ + j;
            float ex = 0.0f;
#pragma unroll 4
            for (int c0 = lane; c0 < C_; c0 += 32)
                ex += fk[(size_t)c0 * S_] * fq[(size_t)c0 * S_];
#pragma unroll
            for (int off = 16; off; off >>= 1)
                ex += __shfl_xor_sync(0xFFFFFFFFu, ex, off);
            ex *= g_fkinv[b * S_ + i];
            if (ex > bv || (ex == bv && i < bi)) { bv = ex; bi = i; }
        }
        best = ((u64)ford(bv) << 32) | (u64)(0xFFFFFFFFu - bi);
    }
    if (lane == 0) g_best[col] = best;
}

// ---------------------------------------------------------------------------
// Fused: gather d_qn row at match idx -> pos_d dot + fp16 B-tile write +
// output_d row 0 + target_d. Warp per z.
__global__ void gatherbtile_kernel(float* __restrict__ out) {
    int b = blockIdx.y;
    int z = blockIdx.x * 8 + (threadIdx.x >> 5);
    int lane = threadIdx.x & 31;
    u64 key = g_best[b * S_ + z];
    int m = (int)(0xFFFFFFFFu - (unsigned)(key & 0xFFFFFFFFull));
    float4 x = ((const float4*)(g_dqt + ((size_t)b * S_ + m) * D_))[lane];
    float4 y = ((const float4*)(g_dkt + ((size_t)b * S_ + z) * D_))[lane];
    float d = x.x * y.x + x.y * y.y + x.z * y.z + x.w * y.w;
#pragma unroll
    for (int off = 16; off; off >>= 1) d += __shfl_xor_sync(0xFFFFFFFFu, d, off);
    __half h[4] = {__float2half(x.x), __float2half(x.y),
                   __float2half(x.z), __float2half(x.w)};
    uint2 packed;
    memcpy(&packed, h, 8);
    ((uint2*)g_bt4)[((size_t)((b * 8 + (z >> 7)) * 128 + (z & 127))) * 32 + lane] =
        packed;
    if (lane == 0) out[OD + (size_t)b * (K_ + 1) * S_ + z] = d * INV_TAU;
    if (lane == 1) out[TD + b * S_ + z] = 0.0f;
}

// Coalesced transpose of queue_d -> fp16 row-major tiles. grid 512, block 256.
__global__ void qconv_kernel(const float* __restrict__ queue_d) {
    __shared__ float sm[32][129];
    int q0 = blockIdx.x * 32;
    int tid = threadIdx.x;
#pragma unroll
    for (int k = 0; k < 16; k++) {
        int idx = tid + k * 256;
        int d = idx >> 5, ql = idx & 31;
        sm[ql][d] = queue_d[(size_t)d * K_ + q0 + ql];
    }
    __syncthreads();
    uint2* qt2 = (uint2*)g_qt4;
    int qt = q0 >> 7;
#pragma unroll
    for (int k = 0; k < 4; k++) {
        int idx = tid + k * 256;
        int ql = idx >> 5, dg = idx & 31;
        __half h[4];
#pragma unroll
        for (int e = 0; e < 4; e++) h[e] = __float2half(sm[ql][dg * 4 + e]);
        int row = (q0 + ql) & 127;
        uint2 packed;
        memcpy(&packed, h, 8);
        qt2[((size_t)(qt * 128 + row)) * 32 + dg] = packed;
    }
}

// ---------------------------------------------------------------------------
// output_g (fp32 exact)
__global__ void outg_kernel(const float* __restrict__ queue_g, float* __restrict__ out) {
    int b = blockIdx.y;
    int t = threadIdx.x;
    int k = blockIdx.x * 128 + t;
    __shared__ float q[128];
    q[t] = g_gqn[b * D_ + t];
    __syncthreads();
    float acc = 0.0f;
#pragma unroll 16
    for (int d = 0; d < D_; d++) acc += q[d] * queue_g[(size_t)d * K_ + k];
    out[OG + (size_t)b * (K_ + 1) + 1 + k] = acc * INV_TAU;
    if (blockIdx.x == 0 && t == 0) {
        float p = 0.0f;
        for (int d = 0; d < D_; d++) p += g_gqn[b * D_ + d] * g_gkn[b * D_ + d];
        out[OG + (size_t)b * (K_ + 1)] = p * INV_TAU;
        out[TG + b] = 0.0f;
    }
}

// ---------------------------------------------------------------------------
// negd via single-pass fp16 mma. CTA = (q-tile 128, b), loops 8 z-tiles.
constexpr int TSTRIDE = 272;
constexpr int TILE_BYTES_SM = 128 * TSTRIDE;       // 34816
constexpr int SM_A = 0;
constexpr int SM_B = TILE_BYTES_SM;
constexpr int SMEM_NEGD = 3 * TILE_BYTES_SM;       // 104448 -> 2 CTAs/SM

__device__ __forceinline__ void cp_tile(uint32_t smDst, const uint4* src, int tid) {
#pragma unroll
    for (int k = 0; k < 8; k++) {
        int idx = tid + k * 256;
        int row = idx >> 4, w = idx & 15;
        CP16(smDst + row * TSTRIDE + w * 16, src + idx);
    }
}

__global__ __launch_bounds__(256) void negd_mma_kernel(float* __restrict__ out) {
    extern __shared__ char smem[];
    const uint32_t sb = smem_to_u32(smem);
    const int tid = threadIdx.x;
    const int lane = tid & 31;
    const int wid = tid >> 5;
    const int wm = wid & 1;
    const int wn = wid >> 1;
    const int qt = blockIdx.x;
    const int b = blockIdx.y;
    const int q0 = qt << 7;

    uint32_t aoff[4], b4off[2];
    {
        int arow = wm * 64 + ((lane >> 3) & 1) * 8 + (lane & 7);
        int acol = ((lane >> 4) & 1) * 16;
#pragma unroll
        for (int i = 0; i < 4; i++) aoff[i] = (arow + i * 16) * TSTRIDE + acol;
        int jsel = (lane >> 4) & 1;
        int kh = (lane >> 3) & 1;
        int brow = lane & 7;
#pragma unroll
        for (int jp = 0; jp < 2; jp++)
            b4off[jp] = (wn * 32 + (jp * 2 + jsel) * 8 + brow) * TSTRIDE + kh * 16;
    }

    cp_tile(sb + SM_A, g_qt4 + (size_t)qt * 2048, tid);
    cp_tile(sb + SM_B, g_bt4 + (size_t)(b * 8) * 2048, tid);
    CP_COMMIT();
    CP_WAIT0();
    __syncthreads();

    for (int it = 0; it < 8; it++) {
        const int stage = it & 1;
        if (it < 7) {
            cp_tile(sb + SM_B + (stage ^ 1) * TILE_BYTES_SM,
                    g_bt4 + (size_t)(b * 8 + it + 1) * 2048, tid);
            CP_COMMIT();
        }

        float acc[4][4][4];
#pragma unroll
        for (int i = 0; i < 4; i++)
#pragma unroll
            for (int j = 0; j < 4; j++)
#pragma unroll
                for (int r = 0; r < 4; r++) acc[i][j][r] = 0.0f;

        const uint32_t aB = sb + SM_A;
        const uint32_t bB = sb + SM_B + stage * TILE_BYTES_SM;

#pragma unroll
        for (int ks = 0; ks < 8; ks++) {
            uint32_t Af[4][4], Bf[4][2];
#pragma unroll
            for (int i = 0; i < 4; i++)
                LDSM_X4(Af[i][0], Af[i][1], Af[i][2], Af[i][3], aB + aoff[i] + ks * 32);
#pragma unroll
            for (int jp = 0; jp < 2; jp++)
                LDSM_X4(Bf[jp * 2][0], Bf[jp * 2][1], Bf[jp * 2 + 1][0], Bf[jp * 2 + 1][1],
                        bB + b4off[jp] + ks * 32);
#pragma unroll
            for (int i = 0; i < 4; i++)
#pragma unroll
                for (int j = 0; j < 4; j++)
                    MMA_FP16(acc[i][j], Af[i], Bf[j]);
        }

#pragma unroll
        for (int i = 0; i < 4; i++) {
            int q = q0 + wm * 64 + i * 16 + (lane >> 2);
            float* rowp = out + OD + (size_t)(b * (K_ + 1) + 1 + q) * S_;
#pragma unroll
            for (int j = 0; j < 4; j++) {
                int z = it * 128 + wn * 32 + j * 8 + 2 * (lane & 3);
                float2 w0 = {acc[i][j][0] * INV_TAU, acc[i][j][1] * INV_TAU};
                float2 w1 = {acc[i][j][2] * INV_TAU, acc[i][j][3] * INV_TAU};
                *reinterpret_cast<float2*>(rowp + z) = w0;
                *reinterpret_cast<float2*>(rowp + 8 * S_ + z) = w1;
            }
        }

        if (it < 7) CP_WAIT0();
        __syncthreads();
    }
}

// ---------------------------------------------------------------------------
extern "C" void kernel_launch(void* const* d_in, const int* in_sizes, int n_in,
                              void* d_out, int out_size) {
    const float* g_q     = (const float*)d_in[0];
    const float* g_k     = (const float*)d_in[1];
    const float* d_q     = (const float*)d_in[2];
    const float* d_k     = (const float*)d_in[3];
    const float* feat_q  = (const float*)d_in[4];
    const float* feat_k  = (const float*)d_in[5];
    const float* queue_g = (const float*)d_in[6];
    const float* queue_d = (const float*)d_in[7];
    float* out = (float*)d_out;

    cudaFuncSetAttribute(negd_mma_kernel,
                         cudaFuncAttributeMaxDynamicSharedMemorySize, SMEM_NEGD);
    cudaFuncSetAttribute(cos_mma_kernel,
                         cudaFuncAttributeMaxDynamicSharedMemorySize, SMEM_COS);

    fknorm_kernel<<<dim3(S_ / 64, B_), 256>>>(feat_k);                          // 0
    fsplit_kernel<<<dim3(S_ / 32, C_ / 32, 16), dim3(32, 8)>>>(feat_q, feat_k); // 1
    norm_g_kernel<<<dim3(2, B_), 128>>>(g_q, g_k);                              // 2
    cos_mma_kernel<<<dim3(8, 8, B_), 256, SMEM_COS>>>();                        // 3 (ncu slot)
    normt_kernel<<<dim3(S_ / 32, B_, 2), 256>>>(d_q, d_k);                      // 4
    finalize_kernel<<<1024, 256>>>(feat_q, feat_k);                             // 5
    gatherbtile_kernel<<<dim3(S_ / 8, B_), 256>>>(out);                         // 6
    qconv_kernel<<<K_ / 32, 256>>>(queue_d);                                    // 7
    outg_kernel<<<dim3(K_ / 128, B_), 128>>>(queue_g, out);                     // 8
    negd_mma_kernel<<<dim3(128, B_), 256, SMEM_NEGD>>>(out);                    // 9
}

// round 10
// speedup vs baseline: 4.4361x; 1.5115x over previous
#include <cuda_runtime.h>
#include <cuda_fp16.h>
#include <cstdint>

typedef unsigned long long u64;

// Problem constants
constexpr int B_ = 8;
constexpr int D_ = 128;
constexpr int S_ = 1024;
constexpr int C_ = 512;
constexpr int K_ = 16384;
constexpr float INV_TAU = 5.0f;
constexpr float MARGIN = 3e-3f;

// Output layout (flattened concatenation, float32)
constexpr size_t OG = 0;
constexpr size_t TG = (size_t)B_ * (K_ + 1);
constexpr size_t OD = TG + B_;
constexpr size_t TD = OD + (size_t)B_ * (K_ + 1) * S_;

// Scratch (device globals; no allocation allowed)
__device__ float g_dqt[B_ * S_ * D_];   // normalized d_q, transposed [b][s][d]
__device__ float g_dkt[B_ * S_ * D_];   // normalized d_k, transposed [b][s][d]
__device__ float g_fkinv[B_ * S_];      // 1/||feat_k[:,i]||
__device__ float g_gqn[B_ * D_];
__device__ float g_gkn[B_ * D_];
__device__ u64   g_top4[B_ * S_ * 32];  // per (col, itile): top-4 approx keys

// fp16 transposed raw features: [b][s][c]
__device__ __half g_fkh[B_ * S_ * C_];
__device__ __half g_fqh[B_ * S_ * C_];

// fp16 row-major tiles for negd: [tile][row(128)][d(128)]
__device__ uint4 g_qt4[128 * 2048];     // queue_d
__device__ uint4 g_bt4[64 * 2048];      // gathered d_q (8b x 8 z-tiles)

// ---------- helpers ----------
__device__ __forceinline__ unsigned ford(float f) {
    unsigned u = __float_as_uint(f);
    return (u & 0x80000000u) ? ~u : (u | 0x80000000u);
}
__device__ __forceinline__ float unford(unsigned x) {
    unsigned u = (x & 0x80000000u) ? (x & 0x7FFFFFFFu) : ~x;
    return __uint_as_float(u);
}
__device__ __forceinline__ u64 umax64(u64 a, u64 b) { return a > b ? a : b; }

// sorted-descending top-4 insert
__device__ __forceinline__ void ins4(u64* t, u64 k) {
    if (k > t[0])      { t[3] = t[2]; t[2] = t[1]; t[1] = t[0]; t[0] = k; }
    else if (k > t[1]) { t[3] = t[2]; t[2] = t[1]; t[1] = k; }
    else if (k > t[2]) { t[3] = t[2]; t[2] = k; }
    else if (k > t[3]) { t[3] = k; }
}

__device__ __forceinline__ uint32_t smem_to_u32(const void* p) {
    uint32_t a;
    asm("{ .reg .u64 t; cvta.to.shared.u64 t, %1; cvt.u32.u64 %0, t; }"
        : "=r"(a) : "l"(p));
    return a;
}
#define LDSM_X4(r0, r1, r2, r3, a) \
    asm volatile("ldmatrix.sync.aligned.m8n8.x4.shared.b16 {%0,%1,%2,%3}, [%4];" \
                 : "=r"(r0), "=r"(r1), "=r"(r2), "=r"(r3) : "r"(a))
#define MMA_FP16(c, a, b) \
    asm volatile("mma.sync.aligned.m16n8k16.row.col.f32.f16.f16.f32 " \
                 "{%0,%1,%2,%3}, {%4,%5,%6,%7}, {%8,%9}, {%0,%1,%2,%3};" \
                 : "+f"((c)[0]), "+f"((c)[1]), "+f"((c)[2]), "+f"((c)[3]) \
                 : "r"((a)[0]), "r"((a)[1]), "r"((a)[2]), "r"((a)[3]), \
                   "r"((b)[0]), "r"((b)[1]))
#define CP16(dst, src) \
    asm volatile("cp.async.cg.shared.global [%0], [%1], 16;" \
                 :: "r"(dst), "l"(src))
#define CP_COMMIT() asm volatile("cp.async.commit_group;")
#define CP_WAIT0()  asm volatile("cp.async.wait_group 0;" ::: "memory")

// ---------------------------------------------------------------------------
// prep_kernel: fuses 4 independent preprocessing jobs as block ranges.
//  [0, 512)     normt: normalize(d_q/d_k along D) + transpose -> g_dqt/g_dkt
//  [512, 1024)  qconv: queue_d -> fp16 row-major tiles
//  [1024, 1152) fknorm: inverse norms of feat_k columns
//  [1152, 1168) norm_g: normalize g_q / g_k rows
__global__ __launch_bounds__(256) void prep_kernel(
    const float* __restrict__ dq, const float* __restrict__ dk,
    const float* __restrict__ queue_d, const float* __restrict__ fk,
    const float* __restrict__ gq, const float* __restrict__ gk) {
    __shared__ float buf[4416];
    const int bx = blockIdx.x;
    const int tid = threadIdx.x;

    if (bx < 512) {
        // ---- normt ----
        const int which = bx >> 8;           // 0: d_q, 1: d_k
        const int rr = bx & 255;
        const int b = rr >> 5;
        const int s0 = (rr & 31) * 32;
        const float* src = which ? dk : dq;
        float* dst = which ? g_dkt : g_dqt;
        float (*sm)[129] = reinterpret_cast<float (*)[129]>(buf);          // 32x129
        float (*red)[32] = reinterpret_cast<float (*)[32]>(buf + 4128);    // 8x32
        float* sinv = buf + 4384;                                          // 32
#pragma unroll
        for (int k = 0; k < 16; k++) {
            int idx = tid + k * 256;
            int d = idx >> 5, sl = idx & 31;
            sm[sl][d] = src[((size_t)b * D_ + d) * S_ + s0 + sl];
        }
        __syncthreads();
        {
            int sl = tid & 31, pp = tid >> 5;
            float ss = 0.0f;
#pragma unroll
            for (int d = pp * 16; d < pp * 16 + 16; d++) ss += sm[sl][d] * sm[sl][d];
            red[pp][sl] = ss;
        }
        __syncthreads();
        if (tid < 32) {
            float tot = 0.0f;
#pragma unroll
            for (int p = 0; p < 8; p++) tot += red[p][tid];
            sinv[tid] = rsqrtf(fmaxf(tot, 1e-24f));
        }
        __syncthreads();
#pragma unroll
        for (int k = 0; k < 16; k++) {
            int idx = tid + k * 256;
            int sl = idx >> 7, d = idx & 127;
            dst[((size_t)b * S_ + s0 + sl) * D_ + d] = sm[sl][d] * sinv[sl];
        }
    } else if (bx < 1024) {
        // ---- qconv ----
        const int q0 = (bx - 512) * 32;
        float (*sm)[129] = reinterpret_cast<float (*)[129]>(buf);
#pragma unroll
        for (int k = 0; k < 16; k++) {
            int idx = tid + k * 256;
            int d = idx >> 5, ql = idx & 31;
            sm[ql][d] = queue_d[(size_t)d * K_ + q0 + ql];
        }
        __syncthreads();
        uint2* qt2 = (uint2*)g_qt4;
        const int qt = q0 >> 7;
#pragma unroll
        for (int k = 0; k < 4; k++) {
            int idx = tid + k * 256;
            int ql = idx >> 5, dg = idx & 31;
            __half h[4];
#pragma unroll
            for (int e = 0; e < 4; e++) h[e] = __float2half(sm[ql][dg * 4 + e]);
            int row = (q0 + ql) & 127;
            uint2 packed;
            memcpy(&packed, h, 8);
            qt2[((size_t)(qt * 128 + row)) * 32 + dg] = packed;
        }
    } else if (bx < 1152) {
        // ---- fknorm ----
        const int r = bx - 1024;
        const int b = r >> 4;
        const int s = (r & 15) * 64 + (tid & 63);
        const int g = tid >> 6;
        float (*red)[64] = reinterpret_cast<float (*)[64]>(buf);           // 4x64
        const float* p = fk + (size_t)b * C_ * S_ + s;
        float ss = 0.0f;
#pragma unroll 8
        for (int c = g * 128; c < g * 128 + 128; c++) {
            float v = p[(size_t)c * S_];
            ss += v * v;
        }
        red[g][tid & 63] = ss;
        __syncthreads();
        if (g == 0) {
            float tot = red[0][tid] + red[1][tid] + red[2][tid] + red[3][tid];
            g_fkinv[b * S_ + s] = rsqrtf(fmaxf(tot, 1e-24f));
        }
    } else {
        // ---- norm_g (2 vectors x 8 batches over 16 blocks) ----
        const int r = bx - 1152;
        const int xsel = r & 1;
        const int b = r >> 1;
        const float* src = xsel ? gk : gq;
        float* dst = xsel ? g_gkn : g_gqn;
        float v = 0.0f;
        if (tid < 128) {
            v = src[b * D_ + tid];
            buf[tid] = v * v;
        }
        __syncthreads();
        for (int off = 64; off; off >>= 1) {
            if (tid < off) buf[tid] += buf[tid + off];
            __syncthreads();
        }
        if (tid < 128) dst[b * D_ + tid] = v * rsqrtf(fmaxf(buf[0], 1e-24f));
    }
}

// ---------------------------------------------------------------------------
// Transpose raw [b][c][s] -> [b][s][c], fp16.
// z<8: feat_k; z>=8: feat_q. grid (S/32, C/32, 16), block (32, 8).
__global__ void fsplit_kernel(const float* __restrict__ featq,
                              const float* __restrict__ featk) {
    __shared__ float tile[32][33];
    int z = blockIdx.z;
    bool isk = z < 8;
    int b = isk ? z : z - 8;
    const float* src = isk ? featk : featq;
    __half* dh = isk ? g_fkh : g_fqh;
    int s0 = blockIdx.x * 32, c0 = blockIdx.y * 32;
#pragma unroll
    for (int r = 0; r < 4; r++) {
        int c = c0 + threadIdx.y * 4 + r;
        tile[threadIdx.y * 4 + r][threadIdx.x] =
            src[((size_t)b * C_ + c) * S_ + s0 + threadIdx.x];
    }
    __syncthreads();
#pragma unroll
    for (int r = 0; r < 4; r++) {
        int s = s0 + threadIdx.y * 4 + r;
        float v = tile[threadIdx.x][threadIdx.y * 4 + r];
        dh[((size_t)b * S_ + s) * C_ + c0 + threadIdx.x] = __float2half(v);
    }
}

// ---------------------------------------------------------------------------
// cosine via single-pass fp16 mma on RAW features; epilogue scales by inv_i
// and keeps top-4 per 128-i tile. k=32 per stage, double-buffered.
constexpr int XSTRIDE = 80;                 // 64B data + 16B pad
constexpr int STG_ARR = 128 * XSTRIDE;      // 10240
constexpr int STG_BYTES = 2 * STG_ARR;      // A + B = 20480
constexpr int SMEM_COS = 2 * STG_BYTES;     // 40960

__global__ __launch_bounds__(256) void cos_mma_kernel() {
    extern __shared__ char smem[];
    __shared__ u64 smtop[2][4][32][4];
    __shared__ float sinv[128];
    const uint32_t sb = smem_to_u32(smem);
    const int tid = threadIdx.x;
    const int lane = tid & 31;
    const int wid = tid >> 5;
    const int wm = wid & 1;
    const int wn = wid >> 1;
    const int it = blockIdx.x, jt = blockIdx.y, b = blockIdx.z;
    const int i0 = it * 128, j0 = jt * 128;

    if (tid < 128) sinv[tid] = g_fkinv[b * S_ + i0 + tid];

    uint32_t aoff[4], b4off[2];
    {
        int arow = wm * 64 + ((lane >> 3) & 1) * 8 + (lane & 7);
        int acol = ((lane >> 4) & 1) * 16;
#pragma unroll
        for (int i = 0; i < 4; i++) aoff[i] = (arow + i * 16) * XSTRIDE + acol;
        int jsel = (lane >> 4) & 1;
        int kh = (lane >> 3) & 1;
        int brow = lane & 7;
#pragma unroll
        for (int jp = 0; jp < 2; jp++)
            b4off[jp] = (wn * 32 + (jp * 2 + jsel) * 8 + brow) * XSTRIDE + kh * 16;
    }

    auto load_stage = [&](int st, int kc) {
        uint32_t base = sb + st * STG_BYTES;
#pragma unroll
        for (int k = 0; k < 4; k++) {
            int idx = tid + k * 256;
            int arr = idx >> 9;             // 0 = A(fk), 1 = B(fq)
            int rem = idx & 511;
            int r = rem >> 2;
            int quad = rem & 3;
            int row = (arr ? j0 : i0) + r;
            const __half* s = (arr ? g_fqh : g_fkh) +
                              ((size_t)(b * 1024 + row) * 512 + kc * 32 + quad * 8);
            CP16(base + arr * STG_ARR + r * XSTRIDE + quad * 16, s);
        }
    };

    float acc[4][4][4];
#pragma unroll
    for (int i = 0; i < 4; i++)
#pragma unroll
        for (int j = 0; j < 4; j++)
#pragma unroll
            for (int r = 0; r < 4; r++) acc[i][j][r] = 0.0f;

    load_stage(0, 0);
    CP_COMMIT();
    CP_WAIT0();
    __syncthreads();

    for (int kc = 0; kc < 16; kc++) {
        const int st = kc & 1;
        if (kc < 15) { load_stage(st ^ 1, kc + 1); CP_COMMIT(); }
        const uint32_t base = sb + st * STG_BYTES;
#pragma unroll
        for (int kh = 0; kh < 2; kh++) {
            uint32_t Af[4][4], Bf[4][2];
#pragma unroll
            for (int i = 0; i < 4; i++)
                LDSM_X4(Af[i][0], Af[i][1], Af[i][2], Af[i][3],
                        base + aoff[i] + kh * 32);
#pragma unroll
            for (int jp = 0; jp < 2; jp++)
                LDSM_X4(Bf[jp * 2][0], Bf[jp * 2][1], Bf[jp * 2 + 1][0], Bf[jp * 2 + 1][1],
                        base + STG_ARR + b4off[jp] + kh * 32);
#pragma unroll
            for (int i = 0; i < 4; i++)
#pragma unroll
                for (int j = 0; j < 4; j++)
                    MMA_FP16(acc[i][j], Af[i], Bf[j]);
        }
        if (kc < 15) CP_WAIT0();
        __syncthreads();
    }

    float sA[4], sB[4];
#pragma unroll
    for (int i = 0; i < 4; i++) {
        int rl = wm * 64 + i * 16 + (lane >> 2);
        sA[i] = sinv[rl];
        sB[i] = sinv[rl + 8];
    }

    // top-4 over this CTA's 128 i per column j (scaled values)
#pragma unroll
    for (int jf = 0; jf < 4; jf++) {
#pragma unroll
        for (int dj = 0; dj < 2; dj++) {
            u64 t[4] = {0, 0, 0, 0};
#pragma unroll
            for (int i = 0; i < 4; i++) {
                unsigned ig = (unsigned)(i0 + wm * 64 + i * 16 + (lane >> 2));
                ins4(t, ((u64)ford(acc[i][jf][dj] * sA[i]) << 32) |
                        (u64)(0xFFFFFFFFu - ig));
                ins4(t, ((u64)ford(acc[i][jf][dj + 2] * sB[i]) << 32) |
                        (u64)(0xFFFFFFFFu - (ig + 8)));
            }
#pragma unroll
            for (int m = 4; m <= 16; m <<= 1) {
                u64 o0 = __shfl_xor_sync(0xFFFFFFFFu, t[0], m);
                u64 o1 = __shfl_xor_sync(0xFFFFFFFFu, t[1], m);
                u64 o2 = __shfl_xor_sync(0xFFFFFFFFu, t[2], m);
                u64 o3 = __shfl_xor_sync(0xFFFFFFFFu, t[3], m);
                ins4(t, o0); ins4(t, o1); ins4(t, o2); ins4(t, o3);
            }
            if (lane < 4) {
                int j = jf * 8 + 2 * lane + dj;
#pragma unroll
                for (int e = 0; e < 4; e++) smtop[wm][wn][j][e] = t[e];
            }
        }
    }
    __syncthreads();
    if (tid < 128) {
        int wn2 = tid >> 5, j = tid & 31;
        u64 t[4];
#pragma unroll
        for (int e = 0; e < 4; e++) t[e] = smtop[0][wn2][j][e];
#pragma unroll
        for (int e = 0; e < 4; e++) ins4(t, smtop[1][wn2][j][e]);
        size_t col = (size_t)b * 1024 + j0 + wn2 * 32 + j;
#pragma unroll
        for (int e = 0; e < 4; e++) g_top4[col * 32 + it * 4 + e] = t[e];
    }
}

// ---------------------------------------------------------------------------
// fingather: warp per column. Computes exact argmax (ballot margin test +
// cooperative fp32 rescore when ambiguous), then directly gathers the matched
// d_qn row: pos_d dot, fp16 B-tile write, output_d row 0, target_d.
// grid 1024 x block 256 (8 warps).
__global__ void fingather_kernel(const float* __restrict__ featq,
                                 const float* __restrict__ featk,
                                 float* __restrict__ out) {
    int col = blockIdx.x * 8 + (threadIdx.x >> 5);
    int lane = threadIdx.x & 31;
    int b = col >> 10, z = col & 1023;
    u64 key = g_top4[(size_t)col * 32 + lane];
    u64 m = key;
#pragma unroll
    for (int off = 16; off; off >>= 1)
        m = umax64(m, __shfl_xor_sync(0xFFFFFFFFu, m, off));
    float vmax = unford((unsigned)(m >> 32));
    bool pass = unford((unsigned)(key >> 32)) >= vmax - MARGIN;
    unsigned mask = __ballot_sync(0xFFFFFFFFu, pass);
    u64 best = m;
    if (__popc(mask) > 1) {
        float bv = -1e30f;
        unsigned bi = 0xFFFFFFFFu;
        unsigned rem = mask;
        while (rem) {
            int c = __ffs(rem) - 1;
            rem &= rem - 1;
            unsigned i = 0xFFFFFFFFu -
                         (unsigned)(__shfl_sync(0xFFFFFFFFu, key, c) & 0xFFFFFFFFull);
            const float* fkp = featk + (size_t)b * C_ * S_ + i;
            const float* fqp = featq + (size_t)b * C_ * S_ + z;
            float ex = 0.0f;
#pragma unroll 4
            for (int c0 = lane; c0 < C_; c0 += 32)
                ex += fkp[(size_t)c0 * S_] * fqp[(size_t)c0 * S_];
#pragma unroll
            for (int off = 16; off; off >>= 1)
                ex += __shfl_xor_sync(0xFFFFFFFFu, ex, off);
            ex *= g_fkinv[b * S_ + i];
            if (ex > bv || (ex == bv && i < bi)) { bv = ex; bi = i; }
        }
        best = ((u64)ford(bv) << 32) | (u64)(0xFFFFFFFFu - bi);
    }
    // best is warp-uniform: gather immediately
    int midx = (int)(0xFFFFFFFFu - (unsigned)(best & 0xFFFFFFFFull));
    float4 x = ((const float4*)(g_dqt + ((size_t)b * S_ + midx) * D_))[lane];
    float4 y = ((const float4*)(g_dkt + ((size_t)b * S_ + z) * D_))[lane];
    float d = x.x * y.x + x.y * y.y + x.z * y.z + x.w * y.w;
#pragma unroll
    for (int off = 16; off; off >>= 1) d += __shfl_xor_sync(0xFFFFFFFFu, d, off);
    __half h[4] = {__float2half(x.x), __float2half(x.y),
                   __float2half(x.z), __float2half(x.w)};
    uint2 packed;
    memcpy(&packed, h, 8);
    ((uint2*)g_bt4)[((size_t)((b * 8 + (z >> 7)) * 128 + (z & 127))) * 32 + lane] =
        packed;
    if (lane == 0) out[OD + (size_t)b * (K_ + 1) * S_ + z] = d * INV_TAU;
    if (lane == 1) out[TD + b * S_ + z] = 0.0f;
}

// ---------------------------------------------------------------------------
// output_g (fp32 exact)
__global__ void outg_kernel(const float* __restrict__ queue_g, float* __restrict__ out) {
    int b = blockIdx.y;
    int t = threadIdx.x;
    int k = blockIdx.x * 128 + t;
    __shared__ float q[128];
    q[t] = g_gqn[b * D_ + t];
    __syncthreads();
    float acc = 0.0f;
#pragma unroll 16
    for (int d = 0; d < D_; d++) acc += q[d] * queue_g[(size_t)d * K_ + k];
    out[OG + (size_t)b * (K_ + 1) + 1 + k] = acc * INV_TAU;
    if (blockIdx.x == 0 && t == 0) {
        float p = 0.0f;
        for (int d = 0; d < D_; d++) p += g_gqn[b * D_ + d] * g_gkn[b * D_ + d];
        out[OG + (size_t)b * (K_ + 1)] = p * INV_TAU;
        out[TG + b] = 0.0f;
    }
}

// ---------------------------------------------------------------------------
// negd via single-pass fp16 mma. CTA = (q-tile 128, b), loops 8 z-tiles.
constexpr int TSTRIDE = 272;
constexpr int TILE_BYTES_SM = 128 * TSTRIDE;       // 34816
constexpr int SM_A = 0;
constexpr int SM_B = TILE_BYTES_SM;
constexpr int SMEM_NEGD = 3 * TILE_BYTES_SM;       // 104448 -> 2 CTAs/SM

__device__ __forceinline__ void cp_tile(uint32_t smDst, const uint4* src, int tid) {
#pragma unroll
    for (int k = 0; k < 8; k++) {
        int idx = tid + k * 256;
        int row = idx >> 4, w = idx & 15;
        CP16(smDst + row * TSTRIDE + w * 16, src + idx);
    }
}

__global__ __launch_bounds__(256) void negd_mma_kernel(float* __restrict__ out) {
    extern __shared__ char smem[];
    const uint32_t sb = smem_to_u32(smem);
    const int tid = threadIdx.x;
    const int lane = tid & 31;
    const int wid = tid >> 5;
    const int wm = wid & 1;
    const int wn = wid >> 1;
    const int qt = blockIdx.x;
    const int b = blockIdx.y;
    const int q0 = qt << 7;

    uint32_t aoff[4], b4off[2];
    {
        int arow = wm * 64 + ((lane >> 3) & 1) * 8 + (lane & 7);
        int acol = ((lane >> 4) & 1) * 16;
#pragma unroll
        for (int i = 0; i < 4; i++) aoff[i] = (arow + i * 16) * TSTRIDE + acol;
        int jsel = (lane >> 4) & 1;
        int kh = (lane >> 3) & 1;
        int brow = lane & 7;
#pragma unroll
        for (int jp = 0; jp < 2; jp++)
            b4off[jp] = (wn * 32 + (jp * 2 + jsel) * 8 + brow) * TSTRIDE + kh * 16;
    }

    cp_tile(sb + SM_A, g_qt4 + (size_t)qt * 2048, tid);
    cp_tile(sb + SM_B, g_bt4 + (size_t)(b * 8) * 2048, tid);
    CP_COMMIT();
    CP_WAIT0();
    __syncthreads();

    for (int it = 0; it < 8; it++) {
        const int stage = it & 1;
        if (it < 7) {
            cp_tile(sb + SM_B + (stage ^ 1) * TILE_BYTES_SM,
                    g_bt4 + (size_t)(b * 8 + it + 1) * 2048, tid);
            CP_COMMIT();
        }

        float acc[4][4][4];
#pragma unroll
        for (int i = 0; i < 4; i++)
#pragma unroll
            for (int j = 0; j < 4; j++)
#pragma unroll
                for (int r = 0; r < 4; r++) acc[i][j][r] = 0.0f;

        const uint32_t aB = sb + SM_A;
        const uint32_t bB = sb + SM_B + stage * TILE_BYTES_SM;

#pragma unroll
        for (int ks = 0; ks < 8; ks++) {
            uint32_t Af[4][4], Bf[4][2];
#pragma unroll
            for (int i = 0; i < 4; i++)
                LDSM_X4(Af[i][0], Af[i][1], Af[i][2], Af[i][3], aB + aoff[i] + ks * 32);
#pragma unroll
            for (int jp = 0; jp < 2; jp++)
                LDSM_X4(Bf[jp * 2][0], Bf[jp * 2][1], Bf[jp * 2 + 1][0], Bf[jp * 2 + 1][1],
                        bB + b4off[jp] + ks * 32);
#pragma unroll
            for (int i = 0; i < 4; i++)
#pragma unroll
                for (int j = 0; j < 4; j++)
                    MMA_FP16(acc[i][j], Af[i], Bf[j]);
        }

#pragma unroll
        for (int i = 0; i < 4; i++) {
            int q = q0 + wm * 64 + i * 16 + (lane >> 2);
            float* rowp = out + OD + (size_t)(b * (K_ + 1) + 1 + q) * S_;
#pragma unroll
            for (int j = 0; j < 4; j++) {
                int z = it * 128 + wn * 32 + j * 8 + 2 * (lane & 3);
                float2 w0 = {acc[i][j][0] * INV_TAU, acc[i][j][1] * INV_TAU};
                float2 w1 = {acc[i][j][2] * INV_TAU, acc[i][j][3] * INV_TAU};
                *reinterpret_cast<float2*>(rowp + z) = w0;
                *reinterpret_cast<float2*>(rowp + 8 * S_ + z) = w1;
            }
        }

        if (it < 7) CP_WAIT0();
        __syncthreads();
    }
}

// ---------------------------------------------------------------------------
extern "C" void kernel_launch(void* const* d_in, const int* in_sizes, int n_in,
                              void* d_out, int out_size) {
    const float* g_q     = (const float*)d_in[0];
    const float* g_k     = (const float*)d_in[1];
    const float* d_q     = (const float*)d_in[2];
    const float* d_k     = (const float*)d_in[3];
    const float* feat_q  = (const float*)d_in[4];
    const float* feat_k  = (const float*)d_in[5];
    const float* queue_g = (const float*)d_in[6];
    const float* queue_d = (const float*)d_in[7];
    float* out = (float*)d_out;

    cudaFuncSetAttribute(negd_mma_kernel,
                         cudaFuncAttributeMaxDynamicSharedMemorySize, SMEM_NEGD);
    cudaFuncSetAttribute(cos_mma_kernel,
                         cudaFuncAttributeMaxDynamicSharedMemorySize, SMEM_COS);

    prep_kernel<<<1168, 256>>>(d_q, d_k, queue_d, feat_k, g_q, g_k);            // 0
    fsplit_kernel<<<dim3(S_ / 32, C_ / 32, 16), dim3(32, 8)>>>(feat_q, feat_k); // 1
    outg_kernel<<<dim3(K_ / 128, B_), 128>>>(queue_g, out);                     // 2
    cos_mma_kernel<<<dim3(8, 8, B_), 256, SMEM_COS>>>();                        // 3 (ncu slot)
    fingather_kernel<<<1024, 256>>>(feat_q, feat_k, out);                       // 4
    negd_mma_kernel<<<dim3(128, B_), 256, SMEM_NEGD>>>(out);                    // 5
}

// round 11
// speedup vs baseline: 4.8968x; 1.1039x over previous
#include <cuda_runtime.h>
#include <cuda_fp16.h>
#include <cstdint>

typedef unsigned long long u64;
typedef unsigned u32;

// Problem constants
constexpr int B_ = 8;
constexpr int D_ = 128;
constexpr int S_ = 1024;
constexpr int C_ = 512;
constexpr int K_ = 16384;
constexpr float INV_TAU = 5.0f;
constexpr float MARGIN = 3e-3f;

// Output layout (flattened concatenation, float32)
constexpr size_t OG = 0;
constexpr size_t TG = (size_t)B_ * (K_ + 1);
constexpr size_t OD = TG + B_;
constexpr size_t TD = OD + (size_t)B_ * (K_ + 1) * S_;

// Scratch (device globals; no allocation allowed)
__device__ float g_dqt[B_ * S_ * D_];   // normalized d_q, transposed [b][s][d]
__device__ float g_dkt[B_ * S_ * D_];   // normalized d_k, transposed [b][s][d]
__device__ float g_fkinv[B_ * S_];      // 1/||feat_k[:,i]||
__device__ u32   g_top4[B_ * S_ * 32];  // per (col, itile): top-4 packed keys

// fp16 transposed raw features: [b][s][c]
__device__ __half g_fkh[B_ * S_ * C_];
__device__ __half g_fqh[B_ * S_ * C_];

// fp16 row-major tiles for negd: [tile][row(128)][d(128)]
__device__ uint4 g_qt4[128 * 2048];     // queue_d
__device__ uint4 g_bt4[64 * 2048];      // gathered d_q (8b x 8 z-tiles of 128)

// ---------- helpers ----------
__device__ __forceinline__ unsigned ford(float f) {
    unsigned u = __float_as_uint(f);
    return (u & 0x80000000u) ? ~u : (u | 0x80000000u);
}
__device__ __forceinline__ float unford(unsigned x) {
    unsigned u = (x & 0x80000000u) ? (x & 0x7FFFFFFFu) : ~x;
    return __uint_as_float(u);
}

// packed key: [22b truncated ford(value)][10b (1023 - index)]
__device__ __forceinline__ u32 mkkey(float v, unsigned ig) {
    return (ford(v) & 0xFFFFFC00u) | (1023u - ig);
}
__device__ __forceinline__ float keyval(u32 k) { return unford(k & 0xFFFFFC00u); }
__device__ __forceinline__ int keyidx(u32 k) { return 1023 - (int)(k & 1023u); }

// sorted-descending top-4 insert (u32)
__device__ __forceinline__ void ins4(u32* t, u32 k) {
    if (k > t[0])      { t[3] = t[2]; t[2] = t[1]; t[1] = t[0]; t[0] = k; }
    else if (k > t[1]) { t[3] = t[2]; t[2] = t[1]; t[1] = k; }
    else if (k > t[2]) { t[3] = t[2]; t[2] = k; }
    else if (k > t[3]) { t[3] = k; }
}

__device__ __forceinline__ uint32_t smem_to_u32(const void* p) {
    uint32_t a;
    asm("{ .reg .u64 t; cvta.to.shared.u64 t, %1; cvt.u32.u64 %0, t; }"
        : "=r"(a) : "l"(p));
    return a;
}
#define LDSM_X4(r0, r1, r2, r3, a) \
    asm volatile("ldmatrix.sync.aligned.m8n8.x4.shared.b16 {%0,%1,%2,%3}, [%4];" \
                 : "=r"(r0), "=r"(r1), "=r"(r2), "=r"(r3) : "r"(a))
#define MMA_FP16(c, a, b) \
    asm volatile("mma.sync.aligned.m16n8k16.row.col.f32.f16.f16.f32 " \
                 "{%0,%1,%2,%3}, {%4,%5,%6,%7}, {%8,%9}, {%0,%1,%2,%3};" \
                 : "+f"((c)[0]), "+f"((c)[1]), "+f"((c)[2]), "+f"((c)[3]) \
                 : "r"((a)[0]), "r"((a)[1]), "r"((a)[2]), "r"((a)[3]), \
                   "r"((b)[0]), "r"((b)[1]))
#define CP16(dst, src) \
    asm volatile("cp.async.cg.shared.global [%0], [%1], 16;" \
                 :: "r"(dst), "l"(src))
#define CP_COMMIT() asm volatile("cp.async.commit_group;")
#define CP_WAIT0()  asm volatile("cp.async.wait_group 0;" ::: "memory")

// ---------------------------------------------------------------------------
// mega_kernel: all independent preprocessing + output_g as block ranges.
//  [0, 512)      normt: normalize(d_q/d_k along D) + transpose
//  [512, 1024)   qconv: queue_d -> fp16 row-major tiles
//  [1024, 1152)  fknorm: inverse norms of feat_k columns
//  [1152, 9344)  fsplit: feat_k/feat_q -> [b][s][c] fp16
//  [9344, 9856)  outg: output_g (self-computes g-norms)
__global__ __launch_bounds__(256) void mega_kernel(
    const float* __restrict__ dq, const float* __restrict__ dk,
    const float* __restrict__ queue_d, const float* __restrict__ featk,
    const float* __restrict__ featq,
    const float* __restrict__ gq, const float* __restrict__ gk,
    const float* __restrict__ queue_g, float* __restrict__ out) {
    __shared__ float buf[4416];
    const int bx = blockIdx.x;
    const int tid = threadIdx.x;

    if (bx < 512) {
        // ---- normt ----
        const int which = bx >> 8;
        const int rr = bx & 255;
        const int b = rr >> 5;
        const int s0 = (rr & 31) * 32;
        const float* src = which ? dk : dq;
        float* dst = which ? g_dkt : g_dqt;
        float (*sm)[129] = reinterpret_cast<float (*)[129]>(buf);
        float (*red)[32] = reinterpret_cast<float (*)[32]>(buf + 4128);
        float* sinv = buf + 4384;
#pragma unroll
        for (int k = 0; k < 16; k++) {
            int idx = tid + k * 256;
            int d = idx >> 5, sl = idx & 31;
            sm[sl][d] = src[((size_t)b * D_ + d) * S_ + s0 + sl];
        }
        __syncthreads();
        {
            int sl = tid & 31, pp = tid >> 5;
            float ss = 0.0f;
#pragma unroll
            for (int d = pp * 16; d < pp * 16 + 16; d++) ss += sm[sl][d] * sm[sl][d];
            red[pp][sl] = ss;
        }
        __syncthreads();
        if (tid < 32) {
            float tot = 0.0f;
#pragma unroll
            for (int p = 0; p < 8; p++) tot += red[p][tid];
            sinv[tid] = rsqrtf(fmaxf(tot, 1e-24f));
        }
        __syncthreads();
#pragma unroll
        for (int k = 0; k < 16; k++) {
            int idx = tid + k * 256;
            int sl = idx >> 7, d = idx & 127;
            dst[((size_t)b * S_ + s0 + sl) * D_ + d] = sm[sl][d] * sinv[sl];
        }
    } else if (bx < 1024) {
        // ---- qconv ----
        const int q0 = (bx - 512) * 32;
        float (*sm)[129] = reinterpret_cast<float (*)[129]>(buf);
#pragma unroll
        for (int k = 0; k < 16; k++) {
            int idx = tid + k * 256;
            int d = idx >> 5, ql = idx & 31;
            sm[ql][d] = queue_d[(size_t)d * K_ + q0 + ql];
        }
        __syncthreads();
        uint2* qt2 = (uint2*)g_qt4;
        const int qt = q0 >> 7;
#pragma unroll
        for (int k = 0; k < 4; k++) {
            int idx = tid + k * 256;
            int ql = idx >> 5, dg = idx & 31;
            __half h[4];
#pragma unroll
            for (int e = 0; e < 4; e++) h[e] = __float2half(sm[ql][dg * 4 + e]);
            int row = (q0 + ql) & 127;
            uint2 packed;
            memcpy(&packed, h, 8);
            qt2[((size_t)(qt * 128 + row)) * 32 + dg] = packed;
        }
    } else if (bx < 1152) {
        // ---- fknorm ----
        const int r = bx - 1024;
        const int b = r >> 4;
        const int s = (r & 15) * 64 + (tid & 63);
        const int g = tid >> 6;
        float (*red)[64] = reinterpret_cast<float (*)[64]>(buf);
        const float* p = featk + (size_t)b * C_ * S_ + s;
        float ss = 0.0f;
#pragma unroll 8
        for (int c = g * 128; c < g * 128 + 128; c++) {
            float v = p[(size_t)c * S_];
            ss += v * v;
        }
        red[g][tid & 63] = ss;
        __syncthreads();
        if (g == 0) {
            float tot = red[0][tid] + red[1][tid] + red[2][tid] + red[3][tid];
            g_fkinv[b * S_ + s] = rsqrtf(fmaxf(tot, 1e-24f));
        }
    } else if (bx < 9344) {
        // ---- fsplit: transpose [b][c][s] -> [b][s][c], fp16 ----
        const int r = bx - 1152;
        const int z = r / 512;               // 0..15
        const int rem = r & 511;
        const int s0 = (rem & 31) * 32;
        const int c0 = (rem >> 5) * 32;
        const bool isk = z < 8;
        const int b = isk ? z : z - 8;
        const float* src = isk ? featk : featq;
        __half* dh = isk ? g_fkh : g_fqh;
        float (*tile)[33] = reinterpret_cast<float (*)[33]>(buf);
        const int tx = tid & 31, ty = tid >> 5;
#pragma unroll
        for (int rr = 0; rr < 4; rr++) {
            int c = c0 + ty * 4 + rr;
            tile[ty * 4 + rr][tx] = src[((size_t)b * C_ + c) * S_ + s0 + tx];
        }
        __syncthreads();
#pragma unroll
        for (int rr = 0; rr < 4; rr++) {
            int s = s0 + ty * 4 + rr;
            dh[((size_t)b * S_ + s) * C_ + c0 + tx] =
                __float2half(tile[tx][ty * 4 + rr]);
        }
    } else {
        // ---- outg: 512 blocks; each 256 k's; self-computes g norms ----
        const int r = bx - 9344;
        const int b = r >> 6;
        const int k = (r & 63) * 256 + tid;
        // normalize g_q[b]
        float v = 0.0f;
        if (tid < 128) v = gq[b * D_ + tid];
        buf[tid] = v * v;
        if (tid >= 128) buf[tid] = 0.0f;
        __syncthreads();
        for (int off = 128; off; off >>= 1) {
            if (tid < off) buf[tid] += buf[tid + off];
            __syncthreads();
        }
        float qsc = rsqrtf(fmaxf(buf[0], 1e-24f));
        __syncthreads();
        if (tid < 128) buf[256 + tid] = v * qsc;   // g_qn in buf[256..384)
        __syncthreads();
        float acc = 0.0f;
#pragma unroll 16
        for (int d = 0; d < D_; d++) acc += buf[256 + d] * queue_g[(size_t)d * K_ + k];
        out[OG + (size_t)b * (K_ + 1) + 1 + k] = acc * INV_TAU;
        if ((r & 63) == 0) {
            // pos_g needs g_kn too
            float w = 0.0f;
            if (tid < 128) w = gk[b * D_ + tid];
            buf[tid] = w * w;
            if (tid >= 128) buf[tid] = 0.0f;
            __syncthreads();
            for (int off = 128; off; off >>= 1) {
                if (tid < off) buf[tid] += buf[tid + off];
                __syncthreads();
            }
            float ksc = rsqrtf(fmaxf(buf[0], 1e-24f));
            __syncthreads();
            buf[tid] = (tid < 128) ? buf[256 + tid] * w * ksc : 0.0f;
            __syncthreads();
            for (int off = 128; off; off >>= 1) {
                if (tid < off) buf[tid] += buf[tid + off];
                __syncthreads();
            }
            if (tid == 0) {
                out[OG + (size_t)b * (K_ + 1)] = buf[0] * INV_TAU;
                out[TG + b] = 0.0f;
            }
        }
    }
}

// ---------------------------------------------------------------------------
// cosine: CTA = 128i x 64j, 8 warps (2 wm x 4 wn), warp tile 64x16.
// Single-pass fp16 mma on raw features; epilogue scales by inv_i and keeps
// top-4 per (column, 128-i tile) as packed u32 keys. 3 CTAs/SM.
constexpr int XSTRIDE = 80;                 // 64B data + 16B pad
constexpr int STG_A_SZ = 128 * XSTRIDE;     // 10240
constexpr int STG_B_SZ = 64 * XSTRIDE;      // 5120
constexpr int STG_BYTES = STG_A_SZ + STG_B_SZ;  // 15360
constexpr int SMEM_COS = 2 * STG_BYTES;     // 30720

__global__ __launch_bounds__(256, 3) void cos_mma_kernel() {
    extern __shared__ char smem[];
    __shared__ u32 smtop[2][4][16][4];
    __shared__ float sinv[128];
    const uint32_t sb = smem_to_u32(smem);
    const int tid = threadIdx.x;
    const int lane = tid & 31;
    const int wid = tid >> 5;
    const int wm = wid & 1;        // 64 i-rows
    const int wn = wid >> 1;       // 16 j-cols
    const int it = blockIdx.x, jt = blockIdx.y, b = blockIdx.z;
    const int i0 = it * 128, j0 = jt * 64;

    if (tid < 128) sinv[tid] = g_fkinv[b * S_ + i0 + tid];

    uint32_t aoff[4], boff;
    {
        int arow = wm * 64 + ((lane >> 3) & 1) * 8 + (lane & 7);
        int acol = ((lane >> 4) & 1) * 16;
#pragma unroll
        for (int i = 0; i < 4; i++) aoff[i] = (arow + i * 16) * XSTRIDE + acol;
        int jsel = (lane >> 4) & 1;
        int kh = (lane >> 3) & 1;
        int brow = lane & 7;
        boff = (wn * 16 + jsel * 8 + brow) * XSTRIDE + kh * 16;
    }

    auto load_stage = [&](int st, int kc) {
        uint32_t base = sb + st * STG_BYTES;
#pragma unroll
        for (int k = 0; k < 3; k++) {
            int idx = tid + k * 256;         // 0..767
            bool isA = idx < 512;
            int rem = isA ? idx : idx - 512;
            int r = rem >> 2;
            int quad = rem & 3;
            int row = isA ? (i0 + r) : (j0 + r);
            const __half* s = (isA ? g_fkh : g_fqh) +
                              ((size_t)(b * 1024 + row) * 512 + kc * 32 + quad * 8);
            uint32_t d = base + (isA ? 0 : STG_A_SZ) + r * XSTRIDE + quad * 16;
            CP16(d, s);
        }
    };

    float acc[4][2][4];
#pragma unroll
    for (int i = 0; i < 4; i++)
#pragma unroll
        for (int j = 0; j < 2; j++)
#pragma unroll
            for (int r = 0; r < 4; r++) acc[i][j][r] = 0.0f;

    load_stage(0, 0);
    CP_COMMIT();
    CP_WAIT0();
    __syncthreads();

    for (int kc = 0; kc < 16; kc++) {
        const int st = kc & 1;
        if (kc < 15) { load_stage(st ^ 1, kc + 1); CP_COMMIT(); }
        const uint32_t base = sb + st * STG_BYTES;
#pragma unroll
        for (int kh = 0; kh < 2; kh++) {
            uint32_t Af[4][4], Bf[2][2];
#pragma unroll
            for (int i = 0; i < 4; i++)
                LDSM_X4(Af[i][0], Af[i][1], Af[i][2], Af[i][3],
                        base + aoff[i] + kh * 32);
            LDSM_X4(Bf[0][0], Bf[0][1], Bf[1][0], Bf[1][1],
                    base + STG_A_SZ + boff + kh * 32);
#pragma unroll
            for (int i = 0; i < 4; i++)
#pragma unroll
                for (int j = 0; j < 2; j++)
                    MMA_FP16(acc[i][j], Af[i], Bf[j]);
        }
        if (kc < 15) CP_WAIT0();
        __syncthreads();
    }

    float sA[4], sB[4];
#pragma unroll
    for (int i = 0; i < 4; i++) {
        int rl = wm * 64 + i * 16 + (lane >> 2);
        sA[i] = sinv[rl];
        sB[i] = sinv[rl + 8];
    }

    // top-4 over this CTA's 128 i per column (16 cols per warp)
#pragma unroll
    for (int jf = 0; jf < 2; jf++) {
#pragma unroll
        for (int dj = 0; dj < 2; dj++) {
            u32 t[4] = {0, 0, 0, 0};
#pragma unroll
            for (int i = 0; i < 4; i++) {
                unsigned ig = (unsigned)(i0 + wm * 64 + i * 16 + (lane >> 2));
                ins4(t, mkkey(acc[i][jf][dj] * sA[i], ig));
                ins4(t, mkkey(acc[i][jf][dj + 2] * sB[i], ig + 8));
            }
#pragma unroll
            for (int m = 4; m <= 16; m <<= 1) {
                u32 o0 = __shfl_xor_sync(0xFFFFFFFFu, t[0], m);
                u32 o1 = __shfl_xor_sync(0xFFFFFFFFu, t[1], m);
                u32 o2 = __shfl_xor_sync(0xFFFFFFFFu, t[2], m);
                u32 o3 = __shfl_xor_sync(0xFFFFFFFFu, t[3], m);
                ins4(t, o0); ins4(t, o1); ins4(t, o2); ins4(t, o3);
            }
            if (lane < 4) {
                int j = jf * 8 + 2 * lane + dj;
#pragma unroll
                for (int e = 0; e < 4; e++) smtop[wm][wn][j][e] = t[e];
            }
        }
    }
    __syncthreads();
    if (tid < 64) {
        int wn2 = tid >> 4, j = tid & 15;
        u32 t[4];
#pragma unroll
        for (int e = 0; e < 4; e++) t[e] = smtop[0][wn2][j][e];
#pragma unroll
        for (int e = 0; e < 4; e++) ins4(t, smtop[1][wn2][j][e]);
        size_t col = (size_t)b * 1024 + j0 + wn2 * 16 + j;
#pragma unroll
        for (int e = 0; e < 4; e++) g_top4[col * 32 + it * 4 + e] = t[e];
    }
}

// ---------------------------------------------------------------------------
// fingather: warp per column. Exact argmax (ballot margin + cooperative fp32
// rescore), then gather matched row: pos_d, B-tile, output_d row0, target_d.
__global__ void fingather_kernel(const float* __restrict__ featq,
                                 const float* __restrict__ featk,
                                 float* __restrict__ out) {
    int col = blockIdx.x * 8 + (threadIdx.x >> 5);
    int lane = threadIdx.x & 31;
    int b = col >> 10, z = col & 1023;
    u32 key = g_top4[(size_t)col * 32 + lane];
    u32 m = key;
#pragma unroll
    for (int off = 16; off; off >>= 1)
        m = max(m, __shfl_xor_sync(0xFFFFFFFFu, m, off));
    float vmax = keyval(m);
    bool pass = keyval(key) >= vmax - MARGIN;
    unsigned mask = __ballot_sync(0xFFFFFFFFu, pass);
    u32 best = m;
    if (__popc(mask) > 1) {
        float bv = -1e30f;
        int bi = 0x7FFFFFFF;
        unsigned rem = mask;
        while (rem) {
            int c = __ffs(rem) - 1;
            rem &= rem - 1;
            int i = keyidx(__shfl_sync(0xFFFFFFFFu, key, c));
            const float* fkp = featk + (size_t)b * C_ * S_ + i;
            const float* fqp = featq + (size_t)b * C_ * S_ + z;
            float ex = 0.0f;
#pragma unroll 4
            for (int c0 = lane; c0 < C_; c0 += 32)
                ex += fkp[(size_t)c0 * S_] * fqp[(size_t)c0 * S_];
#pragma unroll
            for (int off = 16; off; off >>= 1)
                ex += __shfl_xor_sync(0xFFFFFFFFu, ex, off);
            ex *= g_fkinv[b * S_ + i];
            if (ex > bv || (ex == bv && i < bi)) { bv = ex; bi = i; }
        }
        best = mkkey(bv, (unsigned)bi);
    }
    int midx = keyidx(best);
    float4 x = ((const float4*)(g_dqt + ((size_t)b * S_ + midx) * D_))[lane];
    float4 y = ((const float4*)(g_dkt + ((size_t)b * S_ + z) * D_))[lane];
    float d = x.x * y.x + x.y * y.y + x.z * y.z + x.w * y.w;
#pragma unroll
    for (int off = 16; off; off >>= 1) d += __shfl_xor_sync(0xFFFFFFFFu, d, off);
    __half h[4] = {__float2half(x.x), __float2half(x.y),
                   __float2half(x.z), __float2half(x.w)};
    uint2 packed;
    memcpy(&packed, h, 8);
    ((uint2*)g_bt4)[((size_t)((b * 8 + (z >> 7)) * 128 + (z & 127))) * 32 + lane] =
        packed;
    if (lane == 0) out[OD + (size_t)b * (K_ + 1) * S_ + z] = d * INV_TAU;
    if (lane == 1) out[TD + b * S_ + z] = 0.0f;
}

// ---------------------------------------------------------------------------
// negd: CTA = 128q x 64z, 8 warps (4 wm x 2 wn), warp tile 32x32. Loops 16
// z-tiles of 64, double-buffered B. 3 CTAs/SM.
constexpr int TSTRIDE = 272;
constexpr int A_BYTES_SM = 128 * TSTRIDE;          // 34816
constexpr int BSTG_BYTES = 64 * TSTRIDE;           // 17408
constexpr int SM_A = 0;
constexpr int SM_B = A_BYTES_SM;
constexpr int SMEM_NEGD = A_BYTES_SM + 2 * BSTG_BYTES;  // 69632

__device__ __forceinline__ void cp_tile_a(uint32_t smDst, const uint4* src, int tid) {
#pragma unroll
    for (int k = 0; k < 8; k++) {
        int idx = tid + k * 256;
        int row = idx >> 4, w = idx & 15;
        CP16(smDst + row * TSTRIDE + w * 16, src + idx);
    }
}
__device__ __forceinline__ void cp_tile_b(uint32_t smDst, const uint4* src, int tid) {
#pragma unroll
    for (int k = 0; k < 4; k++) {
        int idx = tid + k * 256;
        int row = idx >> 4, w = idx & 15;
        CP16(smDst + row * TSTRIDE + w * 16, src + idx);
    }
}
// source pointer for 64-row z-tile zt (0..15) of batch b
__device__ __forceinline__ const uint4* btile_src(int b, int zt) {
    return g_bt4 + (size_t)(b * 8 + (zt >> 1)) * 2048 + (zt & 1) * 1024;
}

__global__ __launch_bounds__(256, 3) void negd_mma_kernel(float* __restrict__ out) {
    extern __shared__ char smem[];
    const uint32_t sb = smem_to_u32(smem);
    const int tid = threadIdx.x;
    const int lane = tid & 31;
    const int wid = tid >> 5;
    const int wm = wid & 3;        // 32 q-rows
    const int wn = wid >> 2;       // 32 z-cols
    const int qt = blockIdx.x;
    const int b = blockIdx.y;
    const int q0 = qt << 7;

    uint32_t aoff[2], b4off[2];
    {
        int arow = wm * 32 + ((lane >> 3) & 1) * 8 + (lane & 7);
        int acol = ((lane >> 4) & 1) * 16;
#pragma unroll
        for (int i = 0; i < 2; i++) aoff[i] = (arow + i * 16) * TSTRIDE + acol;
        int jsel = (lane >> 4) & 1;
        int kh = (lane >> 3) & 1;
        int brow = lane & 7;
#pragma unroll
        for (int jp = 0; jp < 2; jp++)
            b4off[jp] = (wn * 32 + (jp * 2 + jsel) * 8 + brow) * TSTRIDE + kh * 16;
    }

    cp_tile_a(sb + SM_A, g_qt4 + (size_t)qt * 2048, tid);
    cp_tile_b(sb + SM_B, btile_src(b, 0), tid);
    CP_COMMIT();
    CP_WAIT0();
    __syncthreads();

    for (int zt = 0; zt < 16; zt++) {
        const int stage = zt & 1;
        if (zt < 15) {
            cp_tile_b(sb + SM_B + (stage ^ 1) * BSTG_BYTES, btile_src(b, zt + 1), tid);
            CP_COMMIT();
        }

        float acc[2][4][4];
#pragma unroll
        for (int i = 0; i < 2; i++)
#pragma unroll
            for (int j = 0; j < 4; j++)
#pragma unroll
                for (int r = 0; r < 4; r++) acc[i][j][r] = 0.0f;

        const uint32_t aB = sb + SM_A;
        const uint32_t bB = sb + SM_B + stage * BSTG_BYTES;

#pragma unroll
        for (int ks = 0; ks < 8; ks++) {
            uint32_t Af[2][4], Bf[4][2];
#pragma unroll
            for (int i = 0; i < 2; i++)
                LDSM_X4(Af[i][0], Af[i][1], Af[i][2], Af[i][3], aB + aoff[i] + ks * 32);
#pragma unroll
            for (int jp = 0; jp < 2; jp++)
                LDSM_X4(Bf[jp * 2][0], Bf[jp * 2][1], Bf[jp * 2 + 1][0], Bf[jp * 2 + 1][1],
                        bB + b4off[jp] + ks * 32);
#pragma unroll
            for (int i = 0; i < 2; i++)
#pragma unroll
                for (int j = 0; j < 4; j++)
                    MMA_FP16(acc[i][j], Af[i], Bf[j]);
        }

#pragma unroll
        for (int i = 0; i < 2; i++) {
            int q = q0 + wm * 32 + i * 16 + (lane >> 2);
            float* rowp = out + OD + (size_t)(b * (K_ + 1) + 1 + q) * S_;
#pragma unroll
            for (int j = 0; j < 4; j++) {
                int z = zt * 64 + wn * 32 + j * 8 + 2 * (lane & 3);
                float2 w0 = {acc[i][j][0] * INV_TAU, acc[i][j][1] * INV_TAU};
                float2 w1 = {acc[i][j][2] * INV_TAU, acc[i][j][3] * INV_TAU};
                *reinterpret_cast<float2*>(rowp + z) = w0;
                *reinterpret_cast<float2*>(rowp + 8 * S_ + z) = w1;
            }
        }

        if (zt < 15) CP_WAIT0();
        __syncthreads();
    }
}

// ---------------------------------------------------------------------------
extern "C" void kernel_launch(void* const* d_in, const int* in_sizes, int n_in,
                              void* d_out, int out_size) {
    const float* g_q     = (const float*)d_in[0];
    const float* g_k     = (const float*)d_in[1];
    const float* d_q     = (const float*)d_in[2];
    const float* d_k     = (const float*)d_in[3];
    const float* feat_q  = (const float*)d_in[4];
    const float* feat_k  = (const float*)d_in[5];
    const float* queue_g = (const float*)d_in[6];
    const float* queue_d = (const float*)d_in[7];
    float* out = (float*)d_out;

    cudaFuncSetAttribute(negd_mma_kernel,
                         cudaFuncAttributeMaxDynamicSharedMemorySize, SMEM_NEGD);
    cudaFuncSetAttribute(cos_mma_kernel,
                         cudaFuncAttributeMaxDynamicSharedMemorySize, SMEM_COS);

    mega_kernel<<<9856, 256>>>(d_q, d_k, queue_d, feat_k, feat_q,
                               g_q, g_k, queue_g, out);                 // 0
    cos_mma_kernel<<<dim3(8, 16, B_), 256, SMEM_COS>>>();               // 1
    fingather_kernel<<<1024, 256>>>(feat_q, feat_k, out);               // 2
    negd_mma_kernel<<<dim3(128, B_), 256, SMEM_NEGD>>>(out);            // 3
}

// round 12
// speedup vs baseline: 5.2565x; 1.0735x over previous
#include <cuda_runtime.h>
#include <cuda_fp16.h>
#include <cstdint>

typedef unsigned long long u64;
typedef unsigned u32;

// Problem constants
constexpr int B_ = 8;
constexpr int D_ = 128;
constexpr int S_ = 1024;
constexpr int C_ = 512;
constexpr int K_ = 16384;
constexpr float INV_TAU = 5.0f;
constexpr float MARGIN = 3e-3f;

// Output layout (flattened concatenation, float32)
constexpr size_t OG = 0;
constexpr size_t TG = (size_t)B_ * (K_ + 1);
constexpr size_t OD = TG + B_;
constexpr size_t TD = OD + (size_t)B_ * (K_ + 1) * S_;

// Scratch (device globals; no allocation allowed)
__device__ float g_dqt[B_ * S_ * D_];   // normalized d_q, transposed [b][s][d]
__device__ float g_dkt[B_ * S_ * D_];   // normalized d_k, transposed [b][s][d]
__device__ float g_fkinv[B_ * S_];      // 1/||feat_k[:,i]||
__device__ u32   g_top4[B_ * S_ * 32];  // per (col, itile): top-4 packed keys

// fp16 transposed raw features: [b][s][c]
__device__ __half g_fkh[B_ * S_ * C_];
__device__ __half g_fqh[B_ * S_ * C_];

// fp16 row-major tiles for negd: [tile][row(128)][d(128)]
__device__ uint4 g_qt4[128 * 2048];     // queue_d
__device__ uint4 g_bt4[64 * 2048];      // gathered d_q (8b x 8 z-tiles of 128)

// ---------- helpers ----------
__device__ __forceinline__ unsigned ford(float f) {
    unsigned u = __float_as_uint(f);
    return (u & 0x80000000u) ? ~u : (u | 0x80000000u);
}
__device__ __forceinline__ float unford(unsigned x) {
    unsigned u = (x & 0x80000000u) ? (x & 0x7FFFFFFFu) : ~x;
    return __uint_as_float(u);
}

// packed key: [22b truncated ford(value)][10b (1023 - index)]
__device__ __forceinline__ u32 mkkey(float v, unsigned ig) {
    return (ford(v) & 0xFFFFFC00u) | (1023u - ig);
}
__device__ __forceinline__ float keyval(u32 k) { return unford(k & 0xFFFFFC00u); }
__device__ __forceinline__ int keyidx(u32 k) { return 1023 - (int)(k & 1023u); }

// sorted-descending top-4 insert (u32)
__device__ __forceinline__ void ins4(u32* t, u32 k) {
    if (k > t[0])      { t[3] = t[2]; t[2] = t[1]; t[1] = t[0]; t[0] = k; }
    else if (k > t[1]) { t[3] = t[2]; t[2] = t[1]; t[1] = k; }
    else if (k > t[2]) { t[3] = t[2]; t[2] = k; }
    else if (k > t[3]) { t[3] = k; }
}

__device__ __forceinline__ uint32_t smem_to_u32(const void* p) {
    uint32_t a;
    asm("{ .reg .u64 t; cvta.to.shared.u64 t, %1; cvt.u32.u64 %0, t; }"
        : "=r"(a) : "l"(p));
    return a;
}
#define LDSM_X4(r0, r1, r2, r3, a) \
    asm volatile("ldmatrix.sync.aligned.m8n8.x4.shared.b16 {%0,%1,%2,%3}, [%4];" \
                 : "=r"(r0), "=r"(r1), "=r"(r2), "=r"(r3) : "r"(a))
#define MMA_FP16(c, a, b) \
    asm volatile("mma.sync.aligned.m16n8k16.row.col.f32.f16.f16.f32 " \
                 "{%0,%1,%2,%3}, {%4,%5,%6,%7}, {%8,%9}, {%0,%1,%2,%3};" \
                 : "+f"((c)[0]), "+f"((c)[1]), "+f"((c)[2]), "+f"((c)[3]) \
                 : "r"((a)[0]), "r"((a)[1]), "r"((a)[2]), "r"((a)[3]), \
                   "r"((b)[0]), "r"((b)[1]))
#define CP16(dst, src) \
    asm volatile("cp.async.cg.shared.global [%0], [%1], 16;" \
                 :: "r"(dst), "l"(src))
#define CP_COMMIT() asm volatile("cp.async.commit_group;")
#define CP_WAIT0()  asm volatile("cp.async.wait_group 0;" ::: "memory")

// ---------------------------------------------------------------------------
// mega_kernel: all independent preprocessing + output_g as block ranges.
//  [0, 512)      normt: normalize(d_q/d_k along D) + transpose
//  [512, 1024)   qconv: queue_d -> fp16 row-major tiles
//  [1024, 1152)  fknorm: inverse norms of feat_k columns
//  [1152, 9344)  fsplit: feat_k/feat_q -> [b][s][c] fp16
//  [9344, 9856)  outg: output_g (self-computes g-norms)
__global__ __launch_bounds__(256) void mega_kernel(
    const float* __restrict__ dq, const float* __restrict__ dk,
    const float* __restrict__ queue_d, const float* __restrict__ featk,
    const float* __restrict__ featq,
    const float* __restrict__ gq, const float* __restrict__ gk,
    const float* __restrict__ queue_g, float* __restrict__ out) {
    __shared__ float buf[4416];
    const int bx = blockIdx.x;
    const int tid = threadIdx.x;

    if (bx < 512) {
        // ---- normt ----
        const int which = bx >> 8;
        const int rr = bx & 255;
        const int b = rr >> 5;
        const int s0 = (rr & 31) * 32;
        const float* src = which ? dk : dq;
        float* dst = which ? g_dkt : g_dqt;
        float (*sm)[129] = reinterpret_cast<float (*)[129]>(buf);
        float (*red)[32] = reinterpret_cast<float (*)[32]>(buf + 4128);
        float* sinv = buf + 4384;
#pragma unroll
        for (int k = 0; k < 16; k++) {
            int idx = tid + k * 256;
            int d = idx >> 5, sl = idx & 31;
            sm[sl][d] = src[((size_t)b * D_ + d) * S_ + s0 + sl];
        }
        __syncthreads();
        {
            int sl = tid & 31, pp = tid >> 5;
            float ss = 0.0f;
#pragma unroll
            for (int d = pp * 16; d < pp * 16 + 16; d++) ss += sm[sl][d] * sm[sl][d];
            red[pp][sl] = ss;
        }
        __syncthreads();
        if (tid < 32) {
            float tot = 0.0f;
#pragma unroll
            for (int p = 0; p < 8; p++) tot += red[p][tid];
            sinv[tid] = rsqrtf(fmaxf(tot, 1e-24f));
        }
        __syncthreads();
#pragma unroll
        for (int k = 0; k < 16; k++) {
            int idx = tid + k * 256;
            int sl = idx >> 7, d = idx & 127;
            dst[((size_t)b * S_ + s0 + sl) * D_ + d] = sm[sl][d] * sinv[sl];
        }
    } else if (bx < 1024) {
        // ---- qconv ----
        const int q0 = (bx - 512) * 32;
        float (*sm)[129] = reinterpret_cast<float (*)[129]>(buf);
#pragma unroll
        for (int k = 0; k < 16; k++) {
            int idx = tid + k * 256;
            int d = idx >> 5, ql = idx & 31;
            sm[ql][d] = queue_d[(size_t)d * K_ + q0 + ql];
        }
        __syncthreads();
        uint2* qt2 = (uint2*)g_qt4;
        const int qt = q0 >> 7;
#pragma unroll
        for (int k = 0; k < 4; k++) {
            int idx = tid + k * 256;
            int ql = idx >> 5, dg = idx & 31;
            __half h[4];
#pragma unroll
            for (int e = 0; e < 4; e++) h[e] = __float2half(sm[ql][dg * 4 + e]);
            int row = (q0 + ql) & 127;
            uint2 packed;
            memcpy(&packed, h, 8);
            qt2[((size_t)(qt * 128 + row)) * 32 + dg] = packed;
        }
    } else if (bx < 1152) {
        // ---- fknorm ----
        const int r = bx - 1024;
        const int b = r >> 4;
        const int s = (r & 15) * 64 + (tid & 63);
        const int g = tid >> 6;
        float (*red)[64] = reinterpret_cast<float (*)[64]>(buf);
        const float* p = featk + (size_t)b * C_ * S_ + s;
        float ss = 0.0f;
#pragma unroll 8
        for (int c = g * 128; c < g * 128 + 128; c++) {
            float v = p[(size_t)c * S_];
            ss += v * v;
        }
        red[g][tid & 63] = ss;
        __syncthreads();
        if (g == 0) {
            float tot = red[0][tid] + red[1][tid] + red[2][tid] + red[3][tid];
            g_fkinv[b * S_ + s] = rsqrtf(fmaxf(tot, 1e-24f));
        }
    } else if (bx < 9344) {
        // ---- fsplit: transpose [b][c][s] -> [b][s][c], fp16 ----
        const int r = bx - 1152;
        const int z = r / 512;               // 0..15
        const int rem = r & 511;
        const int s0 = (rem & 31) * 32;
        const int c0 = (rem >> 5) * 32;
        const bool isk = z < 8;
        const int b = isk ? z : z - 8;
        const float* src = isk ? featk : featq;
        __half* dh = isk ? g_fkh : g_fqh;
        float (*tile)[33] = reinterpret_cast<float (*)[33]>(buf);
        const int tx = tid & 31, ty = tid >> 5;
#pragma unroll
        for (int rr = 0; rr < 4; rr++) {
            int c = c0 + ty * 4 + rr;
            tile[ty * 4 + rr][tx] = src[((size_t)b * C_ + c) * S_ + s0 + tx];
        }
        __syncthreads();
#pragma unroll
        for (int rr = 0; rr < 4; rr++) {
            int s = s0 + ty * 4 + rr;
            dh[((size_t)b * S_ + s) * C_ + c0 + tx] =
                __float2half(tile[tx][ty * 4 + rr]);
        }
    } else {
        // ---- outg: 512 blocks; each 256 k's; self-computes g norms ----
        const int r = bx - 9344;
        const int b = r >> 6;
        const int k = (r & 63) * 256 + tid;
        float v = 0.0f;
        if (tid < 128) v = gq[b * D_ + tid];
        buf[tid] = v * v;
        if (tid >= 128) buf[tid] = 0.0f;
        __syncthreads();
        for (int off = 128; off; off >>= 1) {
            if (tid < off) buf[tid] += buf[tid + off];
            __syncthreads();
        }
        float qsc = rsqrtf(fmaxf(buf[0], 1e-24f));
        __syncthreads();
        if (tid < 128) buf[256 + tid] = v * qsc;
        __syncthreads();
        float acc = 0.0f;
#pragma unroll 16
        for (int d = 0; d < D_; d++) acc += buf[256 + d] * queue_g[(size_t)d * K_ + k];
        out[OG + (size_t)b * (K_ + 1) + 1 + k] = acc * INV_TAU;
        if ((r & 63) == 0) {
            float w = 0.0f;
            if (tid < 128) w = gk[b * D_ + tid];
            buf[tid] = w * w;
            if (tid >= 128) buf[tid] = 0.0f;
            __syncthreads();
            for (int off = 128; off; off >>= 1) {
                if (tid < off) buf[tid] += buf[tid + off];
                __syncthreads();
            }
            float ksc = rsqrtf(fmaxf(buf[0], 1e-24f));
            __syncthreads();
            buf[tid] = (tid < 128) ? buf[256 + tid] * w * ksc : 0.0f;
            __syncthreads();
            for (int off = 128; off; off >>= 1) {
                if (tid < off) buf[tid] += buf[tid + off];
                __syncthreads();
            }
            if (tid == 0) {
                out[OG + (size_t)b * (K_ + 1)] = buf[0] * INV_TAU;
                out[TG + b] = 0.0f;
            }
        }
    }
}

// ---------------------------------------------------------------------------
// cosine: CTA = 128i x 64j, 8 warps (2 wm x 4 wn), warp tile 64x16.
constexpr int XSTRIDE = 80;                 // 64B data + 16B pad
constexpr int STG_A_SZ = 128 * XSTRIDE;     // 10240
constexpr int STG_B_SZ = 64 * XSTRIDE;      // 5120
constexpr int STG_BYTES = STG_A_SZ + STG_B_SZ;  // 15360
constexpr int SMEM_COS = 2 * STG_BYTES;     // 30720

__global__ __launch_bounds__(256, 3) void cos_mma_kernel() {
    extern __shared__ char smem[];
    __shared__ u32 smtop[2][4][16][4];
    __shared__ float sinv[128];
    const uint32_t sb = smem_to_u32(smem);
    const int tid = threadIdx.x;
    const int lane = tid & 31;
    const int wid = tid >> 5;
    const int wm = wid & 1;
    const int wn = wid >> 1;
    const int it = blockIdx.x, jt = blockIdx.y, b = blockIdx.z;
    const int i0 = it * 128, j0 = jt * 64;

    if (tid < 128) sinv[tid] = g_fkinv[b * S_ + i0 + tid];

    uint32_t aoff[4], boff;
    {
        int arow = wm * 64 + ((lane >> 3) & 1) * 8 + (lane & 7);
        int acol = ((lane >> 4) & 1) * 16;
#pragma unroll
        for (int i = 0; i < 4; i++) aoff[i] = (arow + i * 16) * XSTRIDE + acol;
        int jsel = (lane >> 4) & 1;
        int kh = (lane >> 3) & 1;
        int brow = lane & 7;
        boff = (wn * 16 + jsel * 8 + brow) * XSTRIDE + kh * 16;
    }

    auto load_stage = [&](int st, int kc) {
        uint32_t base = sb + st * STG_BYTES;
#pragma unroll
        for (int k = 0; k < 3; k++) {
            int idx = tid + k * 256;
            bool isA = idx < 512;
            int rem = isA ? idx : idx - 512;
            int r = rem >> 2;
            int quad = rem & 3;
            int row = isA ? (i0 + r) : (j0 + r);
            const __half* s = (isA ? g_fkh : g_fqh) +
                              ((size_t)(b * 1024 + row) * 512 + kc * 32 + quad * 8);
            uint32_t d = base + (isA ? 0 : STG_A_SZ) + r * XSTRIDE + quad * 16;
            CP16(d, s);
        }
    };

    float acc[4][2][4];
#pragma unroll
    for (int i = 0; i < 4; i++)
#pragma unroll
        for (int j = 0; j < 2; j++)
#pragma unroll
            for (int r = 0; r < 4; r++) acc[i][j][r] = 0.0f;

    load_stage(0, 0);
    CP_COMMIT();
    CP_WAIT0();
    __syncthreads();

    for (int kc = 0; kc < 16; kc++) {
        const int st = kc & 1;
        if (kc < 15) { load_stage(st ^ 1, kc + 1); CP_COMMIT(); }
        const uint32_t base = sb + st * STG_BYTES;
#pragma unroll
        for (int kh = 0; kh < 2; kh++) {
            uint32_t Af[4][4], Bf[2][2];
#pragma unroll
            for (int i = 0; i < 4; i++)
                LDSM_X4(Af[i][0], Af[i][1], Af[i][2], Af[i][3],
                        base + aoff[i] + kh * 32);
            LDSM_X4(Bf[0][0], Bf[0][1], Bf[1][0], Bf[1][1],
                    base + STG_A_SZ + boff + kh * 32);
#pragma unroll
            for (int i = 0; i < 4; i++)
#pragma unroll
                for (int j = 0; j < 2; j++)
                    MMA_FP16(acc[i][j], Af[i], Bf[j]);
        }
        if (kc < 15) CP_WAIT0();
        __syncthreads();
    }

    float sA[4], sB[4];
#pragma unroll
    for (int i = 0; i < 4; i++) {
        int rl = wm * 64 + i * 16 + (lane >> 2);
        sA[i] = sinv[rl];
        sB[i] = sinv[rl + 8];
    }

#pragma unroll
    for (int jf = 0; jf < 2; jf++) {
#pragma unroll
        for (int dj = 0; dj < 2; dj++) {
            u32 t[4] = {0, 0, 0, 0};
#pragma unroll
            for (int i = 0; i < 4; i++) {
                unsigned ig = (unsigned)(i0 + wm * 64 + i * 16 + (lane >> 2));
                ins4(t, mkkey(acc[i][jf][dj] * sA[i], ig));
                ins4(t, mkkey(acc[i][jf][dj + 2] * sB[i], ig + 8));
            }
#pragma unroll
            for (int m = 4; m <= 16; m <<= 1) {
                u32 o0 = __shfl_xor_sync(0xFFFFFFFFu, t[0], m);
                u32 o1 = __shfl_xor_sync(0xFFFFFFFFu, t[1], m);
                u32 o2 = __shfl_xor_sync(0xFFFFFFFFu, t[2], m);
                u32 o3 = __shfl_xor_sync(0xFFFFFFFFu, t[3], m);
                ins4(t, o0); ins4(t, o1); ins4(t, o2); ins4(t, o3);
            }
            if (lane < 4) {
                int j = jf * 8 + 2 * lane + dj;
#pragma unroll
                for (int e = 0; e < 4; e++) smtop[wm][wn][j][e] = t[e];
            }
        }
    }
    __syncthreads();
    if (tid < 64) {
        int wn2 = tid >> 4, j = tid & 15;
        u32 t[4];
#pragma unroll
        for (int e = 0; e < 4; e++) t[e] = smtop[0][wn2][j][e];
#pragma unroll
        for (int e = 0; e < 4; e++) ins4(t, smtop[1][wn2][j][e]);
        size_t col = (size_t)b * 1024 + j0 + wn2 * 16 + j;
#pragma unroll
        for (int e = 0; e < 4; e++) g_top4[col * 32 + it * 4 + e] = t[e];
    }
}

// ---------------------------------------------------------------------------
// fingather: warp per column. Exact argmax then gather matched row.
__global__ void fingather_kernel(const float* __restrict__ featq,
                                 const float* __restrict__ featk,
                                 float* __restrict__ out) {
    int col = blockIdx.x * 8 + (threadIdx.x >> 5);
    int lane = threadIdx.x & 31;
    int b = col >> 10, z = col & 1023;
    u32 key = g_top4[(size_t)col * 32 + lane];
    u32 m = key;
#pragma unroll
    for (int off = 16; off; off >>= 1)
        m = max(m, __shfl_xor_sync(0xFFFFFFFFu, m, off));
    float vmax = keyval(m);
    bool pass = keyval(key) >= vmax - MARGIN;
    unsigned mask = __ballot_sync(0xFFFFFFFFu, pass);
    u32 best = m;
    if (__popc(mask) > 1) {
        float bv = -1e30f;
        int bi = 0x7FFFFFFF;
        unsigned rem = mask;
        while (rem) {
            int c = __ffs(rem) - 1;
            rem &= rem - 1;
            int i = keyidx(__shfl_sync(0xFFFFFFFFu, key, c));
            const float* fkp = featk + (size_t)b * C_ * S_ + i;
            const float* fqp = featq + (size_t)b * C_ * S_ + z;
            float ex = 0.0f;
#pragma unroll 4
            for (int c0 = lane; c0 < C_; c0 += 32)
                ex += fkp[(size_t)c0 * S_] * fqp[(size_t)c0 * S_];
#pragma unroll
            for (int off = 16; off; off >>= 1)
                ex += __shfl_xor_sync(0xFFFFFFFFu, ex, off);
            ex *= g_fkinv[b * S_ + i];
            if (ex > bv || (ex == bv && i < bi)) { bv = ex; bi = i; }
        }
        best = mkkey(bv, (unsigned)bi);
    }
    int midx = keyidx(best);
    float4 x = ((const float4*)(g_dqt + ((size_t)b * S_ + midx) * D_))[lane];
    float4 y = ((const float4*)(g_dkt + ((size_t)b * S_ + z) * D_))[lane];
    float d = x.x * y.x + x.y * y.y + x.z * y.z + x.w * y.w;
#pragma unroll
    for (int off = 16; off; off >>= 1) d += __shfl_xor_sync(0xFFFFFFFFu, d, off);
    __half h[4] = {__float2half(x.x), __float2half(x.y),
                   __float2half(x.z), __float2half(x.w)};
    uint2 packed;
    memcpy(&packed, h, 8);
    ((uint2*)g_bt4)[((size_t)((b * 8 + (z >> 7)) * 128 + (z & 127))) * 32 + lane] =
        packed;
    if (lane == 0) out[OD + (size_t)b * (K_ + 1) * S_ + z] = d * INV_TAU;
    if (lane == 1) out[TD + b * S_ + z] = 0.0f;
}

// ---------------------------------------------------------------------------
// negd: CTA = 128q x 128z, 4 warps (2 wm x 2 wn), warp tile 64x64. Loops 8
// z-tiles of 128, double-buffered B. 2 CTAs/SM. Big warp tile halves LDSM
// traffic per output (L1tex was the binding pipe at 81.6%).
constexpr int TSTRIDE = 272;
constexpr int TILE_SM = 128 * TSTRIDE;             // 34816
constexpr int SM_A = 0;
constexpr int SM_B = TILE_SM;
constexpr int SMEM_NEGD = 3 * TILE_SM;             // 104448 -> 2 CTAs/SM

__device__ __forceinline__ void cp_tile128(uint32_t smDst, const uint4* src, int tid) {
#pragma unroll
    for (int k = 0; k < 16; k++) {
        int idx = tid + k * 128;
        int row = idx >> 4, w = idx & 15;
        CP16(smDst + row * TSTRIDE + w * 16, src + idx);
    }
}

__global__ __launch_bounds__(128, 2) void negd_mma_kernel(float* __restrict__ out) {
    extern __shared__ char smem[];
    const uint32_t sb = smem_to_u32(smem);
    const int tid = threadIdx.x;
    const int lane = tid & 31;
    const int wid = tid >> 5;
    const int wm = wid & 1;        // 64 q-rows
    const int wn = wid >> 1;       // 64 z-cols
    const int qt = blockIdx.x;
    const int b = blockIdx.y;
    const int q0 = qt << 7;

    uint32_t aoff[4], b4off[4];
    {
        int arow = wm * 64 + ((lane >> 3) & 1) * 8 + (lane & 7);
        int acol = ((lane >> 4) & 1) * 16;
#pragma unroll
        for (int i = 0; i < 4; i++) aoff[i] = (arow + i * 16) * TSTRIDE + acol;
        int jsel = (lane >> 4) & 1;
        int kh = (lane >> 3) & 1;
        int brow = lane & 7;
#pragma unroll
        for (int jp = 0; jp < 4; jp++)
            b4off[jp] = (wn * 64 + (jp * 2 + jsel) * 8 + brow) * TSTRIDE + kh * 16;
    }

    cp_tile128(sb + SM_A, g_qt4 + (size_t)qt * 2048, tid);
    cp_tile128(sb + SM_B, g_bt4 + (size_t)(b * 8) * 2048, tid);
    CP_COMMIT();
    CP_WAIT0();
    __syncthreads();

    for (int zt = 0; zt < 8; zt++) {
        const int stage = zt & 1;
        if (zt < 7) {
            cp_tile128(sb + SM_B + (stage ^ 1) * TILE_SM,
                       g_bt4 + (size_t)(b * 8 + zt + 1) * 2048, tid);
            CP_COMMIT();
        }

        float acc[4][8][4];
#pragma unroll
        for (int i = 0; i < 4; i++)
#pragma unroll
            for (int j = 0; j < 8; j++)
#pragma unroll
                for (int r = 0; r < 4; r++) acc[i][j][r] = 0.0f;

        const uint32_t aB = sb + SM_A;
        const uint32_t bB = sb + SM_B + stage * TILE_SM;

#pragma unroll
        for (int ks = 0; ks < 8; ks++) {
            uint32_t Af[4][4], Bf[8][2];
#pragma unroll
            for (int i = 0; i < 4; i++)
                LDSM_X4(Af[i][0], Af[i][1], Af[i][2], Af[i][3], aB + aoff[i] + ks * 32);
#pragma unroll
            for (int jp = 0; jp < 4; jp++)
                LDSM_X4(Bf[jp * 2][0], Bf[jp * 2][1], Bf[jp * 2 + 1][0], Bf[jp * 2 + 1][1],
                        bB + b4off[jp] + ks * 32);
#pragma unroll
            for (int i = 0; i < 4; i++)
#pragma unroll
                for (int j = 0; j < 8; j++)
                    MMA_FP16(acc[i][j], Af[i], Bf[j]);
        }

#pragma unroll
        for (int i = 0; i < 4; i++) {
            int q = q0 + wm * 64 + i * 16 + (lane >> 2);
            float* rowp = out + OD + (size_t)(b * (K_ + 1) + 1 + q) * S_;
#pragma unroll
            for (int j = 0; j < 8; j++) {
                int z = zt * 128 + wn * 64 + j * 8 + 2 * (lane & 3);
                float2 w0 = {acc[i][j][0] * INV_TAU, acc[i][j][1] * INV_TAU};
                float2 w1 = {acc[i][j][2] * INV_TAU, acc[i][j][3] * INV_TAU};
                *reinterpret_cast<float2*>(rowp + z) = w0;
                *reinterpret_cast<float2*>(rowp + 8 * S_ + z) = w1;
            }
        }

        if (zt < 7) CP_WAIT0();
        __syncthreads();
    }
}

// ---------------------------------------------------------------------------
extern "C" void kernel_launch(void* const* d_in, const int* in_sizes, int n_in,
                              void* d_out, int out_size) {
    const float* g_q     = (const float*)d_in[0];
    const float* g_k     = (const float*)d_in[1];
    const float* d_q     = (const float*)d_in[2];
    const float* d_k     = (const float*)d_in[3];
    const float* feat_q  = (const float*)d_in[4];
    const float* feat_k  = (const float*)d_in[5];
    const float* queue_g = (const float*)d_in[6];
    const float* queue_d = (const float*)d_in[7];
    float* out = (float*)d_out;

    cudaFuncSetAttribute(negd_mma_kernel,
                         cudaFuncAttributeMaxDynamicSharedMemorySize, SMEM_NEGD);
    cudaFuncSetAttribute(cos_mma_kernel,
                         cudaFuncAttributeMaxDynamicSharedMemorySize, SMEM_COS);

    mega_kernel<<<9856, 256>>>(d_q, d_k, queue_d, feat_k, feat_q,
                               g_q, g_k, queue_g, out);                 // 0
    cos_mma_kernel<<<dim3(8, 16, B_), 256, SMEM_COS>>>();               // 1
    fingather_kernel<<<1024, 256>>>(feat_q, feat_k, out);               // 2
    negd_mma_kernel<<<dim3(128, B_), 128, SMEM_NEGD>>>(out);            // 3
}